// round 5
// baseline (speedup 1.0000x reference)
#include <cuda_runtime.h>
#include <math.h>

#define N_TOK 8192
#define EMB   1024
#define DFF   4096
#define TSEQ  2048

// scratch (device globals; allocation is forbidden)
__device__ float g_h  [N_TOK * EMB];
__device__ float g_q  [N_TOK * EMB];
__device__ float g_k  [N_TOK * EMB];
__device__ float g_v  [N_TOK * EMB];
__device__ float g_ctx[N_TOK * EMB];
__device__ float g_x1 [N_TOK * EMB];
__device__ float g_ff [N_TOK * DFF];
__device__ float g_rowsum[N_TOK];
__device__ float g_rowsq [N_TOK];
__device__ float g_var[2];

union F4U { float4 f4; unsigned long long u2[2]; float f[4]; };
union PDU { unsigned long long u; float f[2]; };

__device__ __forceinline__ unsigned long long dup_f32(float v) {
    unsigned long long r;
    asm("mov.b64 %0, {%1, %1};" : "=l"(r) : "f"(v));
    return r;
}
__device__ __forceinline__ void fma2(unsigned long long& acc,
                                     unsigned long long a, unsigned long long b) {
    asm("fma.rn.f32x2 %0, %1, %2, %0;" : "+l"(acc) : "l"(a), "l"(b));
}
__device__ __forceinline__ void mul2(unsigned long long& acc, unsigned long long a) {
    asm("mul.rn.f32x2 %0, %0, %1;" : "+l"(acc) : "l"(a));
}

// ---------- per-row sum & sumsq ----------
__global__ void rowstats_kernel(const float* __restrict__ x,
                                float* __restrict__ rowsum,
                                float* __restrict__ rowsq) {
    int row = blockIdx.x, tid = threadIdx.x;
    float4 v = *(const float4*)(x + (size_t)row * EMB + tid * 4);
    float s = v.x + v.y + v.z + v.w;
    float q = v.x * v.x + v.y * v.y + v.z * v.z + v.w * v.w;
#pragma unroll
    for (int o = 16; o > 0; o >>= 1) {
        s += __shfl_down_sync(0xffffffffu, s, o);
        q += __shfl_down_sync(0xffffffffu, q, o);
    }
    __shared__ float ss[8], qs[8];
    int w = tid >> 5, lane = tid & 31;
    if (lane == 0) { ss[w] = s; qs[w] = q; }
    __syncthreads();
    if (tid == 0) {
        float S = 0.f, Q = 0.f;
#pragma unroll
        for (int i = 0; i < 8; i++) { S += ss[i]; Q += qs[i]; }
        rowsum[row] = S; rowsq[row] = Q;
    }
}

// whole-tensor variance (correction=0), deterministic
__global__ void finalize_var_kernel(const float* __restrict__ rowsum,
                                    const float* __restrict__ rowsq,
                                    float* __restrict__ varout) {
    int tid = threadIdx.x;
    double s = 0.0, q = 0.0;
    for (int i = tid; i < N_TOK; i += 256) { s += (double)rowsum[i]; q += (double)rowsq[i]; }
#pragma unroll
    for (int o = 16; o > 0; o >>= 1) {
        s += __shfl_down_sync(0xffffffffu, s, o);
        q += __shfl_down_sync(0xffffffffu, q, o);
    }
    __shared__ double sd[8], qd[8];
    int w = tid >> 5, lane = tid & 31;
    if (lane == 0) { sd[w] = s; qd[w] = q; }
    __syncthreads();
    if (tid == 0) {
        double S = 0.0, Q = 0.0;
        for (int i = 0; i < 8; i++) { S += sd[i]; Q += qd[i]; }
        double M = (double)N_TOK * (double)EMB;
        double mean = S / M;
        varout[0] = (float)(Q / M - mean * mean);
    }
}

// h = ((x - row_mean)/var + eps) * scale + shift   (reference's exact quirk)
__global__ void ln_apply_kernel(const float* __restrict__ x,
                                const float* __restrict__ rowsum,
                                const float* __restrict__ varp,
                                const float* __restrict__ scale,
                                const float* __restrict__ shift,
                                float* __restrict__ out) {
    size_t off = ((size_t)blockIdx.x * blockDim.x + threadIdx.x) * 4;
    int row = (int)(off >> 10), col = (int)(off & 1023);
    float invv = 1.0f / varp[0];
    float mean = rowsum[row] * (1.0f / 1024.0f);
    float4 v  = *(const float4*)(x + off);
    float4 sc = *(const float4*)(scale + col);
    float4 sh = *(const float4*)(shift + col);
    float4 o;
    o.x = ((v.x - mean) * invv + 1e-5f) * sc.x + sh.x;
    o.y = ((v.y - mean) * invv + 1e-5f) * sc.y + sh.y;
    o.z = ((v.z - mean) * invv + 1e-5f) * sc.z + sh.z;
    o.w = ((v.w - mean) * invv + 1e-5f) * sc.w + sh.w;
    *(float4*)(out + off) = o;
}

// ---------- SGEMM: C[M,N] = A[M,K]*B[N,K]^T (+bias)(+res)(+gelu) ----------
#define BM 128
#define BN 128
#define BK 16
#define ASTRIDE 260
#define BSTRIDE 132
enum { MODE_BIAS = 0, MODE_BIAS_RES = 1, MODE_BIAS_GELU = 2 };

template <int MODE>
__global__ __launch_bounds__(256, 2)
void sgemm_nt_kernel(const float* __restrict__ A, const float* __restrict__ B,
                     const float* __restrict__ bias, const float* __restrict__ res,
                     float* __restrict__ C, int M, int N, int K) {
    __shared__ __align__(16) float Asd[BK * ASTRIDE];   // A duplicated: [k][2m]=[k][2m+1]
    __shared__ __align__(16) float Bs [BK * BSTRIDE];
    const int tid  = threadIdx.x;
    const int tm   = tid >> 4;
    const int tn   = tid & 15;
    const int lrow = tid >> 2;
    const int lc4  = tid & 3;
    const float* Ap = A + ((size_t)(blockIdx.y * BM + lrow)) * K + lc4 * 4;
    const float* Bp = B + ((size_t)(blockIdx.x * BN + lrow)) * K + lc4 * 4;
    const int KT = K / BK;

    unsigned long long acc[8][4];
#pragma unroll
    for (int i = 0; i < 8; i++)
#pragma unroll
        for (int j = 0; j < 4; j++) acc[i][j] = 0ull;

    float4 pa0 = *(const float4*)(Ap);
    float4 pa1 = *(const float4*)(Ap + (size_t)64 * K);
    float4 pb0 = *(const float4*)(Bp);
    float4 pb1 = *(const float4*)(Bp + (size_t)64 * K);

    auto stage = [&](float4 a0, float4 a1, float4 b0, float4 b1) {
        F4U ua0, ua1, ub0, ub1;
        ua0.f4 = a0; ua1.f4 = a1; ub0.f4 = b0; ub1.f4 = b1;
#pragma unroll
        for (int i = 0; i < 4; i++) {
            int kk = lc4 * 4 + i;
            *(unsigned long long*)&Asd[kk * ASTRIDE + 2 * lrow]        = dup_f32(ua0.f[i]);
            *(unsigned long long*)&Asd[kk * ASTRIDE + 2 * (lrow + 64)] = dup_f32(ua1.f[i]);
            Bs[kk * BSTRIDE + lrow]      = ub0.f[i];
            Bs[kk * BSTRIDE + lrow + 64] = ub1.f[i];
        }
    };
    auto compute = [&]() {
#pragma unroll
        for (int k = 0; k < BK; k++) {
            unsigned long long ad[8];
#pragma unroll
            for (int i2 = 0; i2 < 4; i2++) {
                F4U u; u.f4 = *(const float4*)&Asd[k * ASTRIDE + 16 * tm + 4 * i2];
                ad[2 * i2] = u.u2[0]; ad[2 * i2 + 1] = u.u2[1];
            }
            unsigned long long bb[4];
            {
                F4U u0; u0.f4 = *(const float4*)&Bs[k * BSTRIDE + 8 * tn];
                F4U u1; u1.f4 = *(const float4*)&Bs[k * BSTRIDE + 8 * tn + 4];
                bb[0] = u0.u2[0]; bb[1] = u0.u2[1]; bb[2] = u1.u2[0]; bb[3] = u1.u2[1];
            }
#pragma unroll
            for (int i = 0; i < 8; i++)
#pragma unroll
                for (int j = 0; j < 4; j++) fma2(acc[i][j], ad[i], bb[j]);
        }
    };

    stage(pa0, pa1, pb0, pb1);
    __syncthreads();
    for (int kt = 1; kt < KT; ++kt) {
        const float* Ak = Ap + kt * BK;
        const float* Bk = Bp + kt * BK;
        pa0 = *(const float4*)(Ak);
        pa1 = *(const float4*)(Ak + (size_t)64 * K);
        pb0 = *(const float4*)(Bk);
        pb1 = *(const float4*)(Bk + (size_t)64 * K);
        compute();
        __syncthreads();
        stage(pa0, pa1, pb0, pb1);
        __syncthreads();
    }
    compute();

    const int row0 = blockIdx.y * BM + tm * 8;
    const int col0 = blockIdx.x * BN + tn * 8;
    float bv[8];
    {
        F4U u0, u1;
        u0.f4 = *(const float4*)(bias + col0);
        u1.f4 = *(const float4*)(bias + col0 + 4);
#pragma unroll
        for (int j = 0; j < 4; j++) { bv[j] = u0.f[j]; bv[4 + j] = u1.f[j]; }
    }
#pragma unroll
    for (int i = 0; i < 8; i++) {
        float o[8];
#pragma unroll
        for (int j2 = 0; j2 < 4; j2++) {
            PDU p; p.u = acc[i][j2];
            o[2 * j2] = p.f[0] + bv[2 * j2];
            o[2 * j2 + 1] = p.f[1] + bv[2 * j2 + 1];
        }
        size_t base = (size_t)(row0 + i) * N + col0;
        if (MODE == MODE_BIAS_RES) {
            F4U r0, r1;
            r0.f4 = *(const float4*)(res + base);
            r1.f4 = *(const float4*)(res + base + 4);
#pragma unroll
            for (int j = 0; j < 4; j++) { o[j] += r0.f[j]; o[4 + j] += r1.f[j]; }
        }
        if (MODE == MODE_BIAS_GELU) {
#pragma unroll
            for (int j = 0; j < 8; j++) {
                float xg = o[j];
                o[j] = 0.5f * xg * (1.0f + erff(xg * 0.70710678118654752f));
            }
        }
        F4U w0, w1;
#pragma unroll
        for (int j = 0; j < 4; j++) { w0.f[j] = o[j]; w1.f[j] = o[4 + j]; }
        *(float4*)(C + base)     = w0.f4;
        *(float4*)(C + base + 4) = w1.f4;
    }
}

// ---------- causal flash attention (fp32, f32x2) ----------
#define ATT_SMEM_FLOATS (64 * 65 + 64 * 68 + 64 * 68)

__global__ __launch_bounds__(128)
void attn_kernel(const float* __restrict__ Qb, const float* __restrict__ Kb,
                 const float* __restrict__ Vb, float* __restrict__ Ob) {
    extern __shared__ float sm[];
    float* Qs  = sm;               // [qr*65 + d], pre-scaled by 1/8
    float* Kst = sm + 64 * 65;     // transposed: [d*68 + j]
    float* Vs  = Kst + 64 * 68;    // [j*68 + d]
    const int qt   = blockIdx.x;
    const int bh   = blockIdx.y;
    const int bb   = bh >> 4;
    const int head = bh & 15;
    const int tid  = threadIdx.x;
    const int qr   = tid >> 1;     // query row (0..63)
    const int hf   = tid & 1;      // which 32-wide half
    const int lane = tid & 31;
    const size_t hoff = (size_t)head * 64;
    const int qg = qt * 64 + qr;

    for (int idx = tid; idx < 64 * 16; idx += 128) {
        int r = idx >> 4, c4 = idx & 15;
        F4U u;
        u.f4 = *(const float4*)(Qb + ((size_t)(bb * TSEQ + qt * 64 + r)) * EMB + hoff + c4 * 4);
#pragma unroll
        for (int i = 0; i < 4; i++) Qs[r * 65 + c4 * 4 + i] = u.f[i] * 0.125f;
    }

    float m = -3.0e38f, l = 0.0f;
    unsigned long long acc[16];
#pragma unroll
    for (int i = 0; i < 16; i++) acc[i] = 0ull;

    for (int kt = 0; kt <= qt; ++kt) {
        __syncthreads();
        for (int idx = tid; idx < 64 * 16; idx += 128) {
            int r = idx >> 4, c4 = idx & 15;
            size_t gbase = ((size_t)(bb * TSEQ + kt * 64 + r)) * EMB + hoff + c4 * 4;
            F4U u; u.f4 = *(const float4*)(Kb + gbase);
#pragma unroll
            for (int i = 0; i < 4; i++) Kst[(c4 * 4 + i) * 68 + r] = u.f[i];
            *(float4*)&Vs[r * 68 + c4 * 4] = *(const float4*)(Vb + gbase);
        }
        __syncthreads();

        unsigned long long s2[16];
#pragma unroll
        for (int i = 0; i < 16; i++) s2[i] = 0ull;
#pragma unroll 8
        for (int d = 0; d < 64; ++d) {
            unsigned long long qd = dup_f32(Qs[qr * 65 + d]);
            const float4* kp = (const float4*)&Kst[d * 68 + hf * 32];
#pragma unroll
            for (int j4 = 0; j4 < 8; j4++) {
                F4U u; u.f4 = kp[j4];
                fma2(s2[2 * j4],     qd, u.u2[0]);
                fma2(s2[2 * j4 + 1], qd, u.u2[1]);
            }
        }
        float s[32];
#pragma unroll
        for (int i = 0; i < 16; i++) {
            PDU p; p.u = s2[i];
            s[2 * i] = p.f[0]; s[2 * i + 1] = p.f[1];
        }
        if (kt == qt) {
            int kg0 = kt * 64 + hf * 32;
#pragma unroll
            for (int jj = 0; jj < 32; jj++)
                if (kg0 + jj > qg) s[jj] = -1e30f;
        }
        float tmax = s[0];
#pragma unroll
        for (int jj = 1; jj < 32; jj++) tmax = fmaxf(tmax, s[jj]);
        tmax = fmaxf(tmax, __shfl_xor_sync(0xffffffffu, tmax, 1));
        float mn = fmaxf(m, tmax);
        float alpha = __expf(m - mn);
        float p[32];
        float ps = 0.0f;
#pragma unroll
        for (int jj = 0; jj < 32; jj++) { p[jj] = __expf(s[jj] - mn); ps += p[jj]; }
        ps += __shfl_xor_sync(0xffffffffu, ps, 1);
        l = l * alpha + ps;
        m = mn;
        unsigned long long al = dup_f32(alpha);
#pragma unroll
        for (int i = 0; i < 16; i++) mul2(acc[i], al);
#pragma unroll
        for (int j = 0; j < 64; j++) {
            float pj = __shfl_sync(0xffffffffu, p[j & 31], (lane & 30) | (j >> 5));
            unsigned long long pd = dup_f32(pj);
            const float4* vp = (const float4*)&Vs[j * 68 + hf * 32];
#pragma unroll
            for (int q4 = 0; q4 < 8; q4++) {
                F4U u; u.f4 = vp[q4];
                fma2(acc[2 * q4],     pd, u.u2[0]);
                fma2(acc[2 * q4 + 1], pd, u.u2[1]);
            }
        }
    }
    float inv = 1.0f / l;
    size_t obase = ((size_t)(bb * TSEQ + qg)) * EMB + hoff + hf * 32;
#pragma unroll
    for (int q4 = 0; q4 < 8; q4++) {
        PDU p0; p0.u = acc[2 * q4];
        PDU p1; p1.u = acc[2 * q4 + 1];
        F4U w;
        w.f[0] = p0.f[0] * inv; w.f[1] = p0.f[1] * inv;
        w.f[2] = p1.f[0] * inv; w.f[3] = p1.f[1] * inv;
        *(float4*)(Ob + obase + 4 * q4) = w.f4;
    }
}

// ---------- orchestration ----------
extern "C" void kernel_launch(void* const* d_in, const int* in_sizes, int n_in,
                              void* d_out, int out_size) {
    (void)in_sizes; (void)n_in; (void)out_size;
    const float* x    = (const float*)d_in[0];
    const float* Wq_w = (const float*)d_in[1];
    const float* Wq_b = (const float*)d_in[2];
    const float* Wk_w = (const float*)d_in[3];
    const float* Wk_b = (const float*)d_in[4];
    const float* Wv_w = (const float*)d_in[5];
    const float* Wv_b = (const float*)d_in[6];
    const float* Wo_w = (const float*)d_in[7];
    const float* Wo_b = (const float*)d_in[8];
    const float* l1_w = (const float*)d_in[9];
    const float* l1_b = (const float*)d_in[10];
    const float* l2_w = (const float*)d_in[11];
    const float* l2_b = (const float*)d_in[12];
    const float* n1s  = (const float*)d_in[13];
    const float* n1b  = (const float*)d_in[14];
    const float* n2s  = (const float*)d_in[15];
    const float* n2b  = (const float*)d_in[16];
    float* out = (float*)d_out;

    float *h, *q, *k, *v, *ctx, *x1, *ff, *rs, *rq, *var;
    cudaGetSymbolAddress((void**)&h,   g_h);
    cudaGetSymbolAddress((void**)&q,   g_q);
    cudaGetSymbolAddress((void**)&k,   g_k);
    cudaGetSymbolAddress((void**)&v,   g_v);
    cudaGetSymbolAddress((void**)&ctx, g_ctx);
    cudaGetSymbolAddress((void**)&x1,  g_x1);
    cudaGetSymbolAddress((void**)&ff,  g_ff);
    cudaGetSymbolAddress((void**)&rs,  g_rowsum);
    cudaGetSymbolAddress((void**)&rq,  g_rowsq);
    cudaGetSymbolAddress((void**)&var, g_var);

    const int att_smem = (int)(ATT_SMEM_FLOATS * sizeof(float));
    cudaFuncSetAttribute((const void*)attn_kernel,
                         cudaFuncAttributeMaxDynamicSharedMemorySize, att_smem);

    const int LN_BLOCKS = (N_TOK * EMB / 4) / 256;
    dim3 blk(256);
    dim3 gP(EMB / BN, N_TOK / BM);
    dim3 gF(DFF / BN, N_TOK / BM);

    // LN1
    rowstats_kernel<<<N_TOK, 256>>>(x, rs, rq);
    finalize_var_kernel<<<1, 256>>>(rs, rq, var);
    ln_apply_kernel<<<LN_BLOCKS, 256>>>(x, rs, var, n1s, n1b, h);
    // QKV projections
    sgemm_nt_kernel<MODE_BIAS><<<gP, blk>>>(h, Wq_w, Wq_b, nullptr, q, N_TOK, EMB, EMB);
    sgemm_nt_kernel<MODE_BIAS><<<gP, blk>>>(h, Wk_w, Wk_b, nullptr, k, N_TOK, EMB, EMB);
    sgemm_nt_kernel<MODE_BIAS><<<gP, blk>>>(h, Wv_w, Wv_b, nullptr, v, N_TOK, EMB, EMB);
    // attention
    attn_kernel<<<dim3(TSEQ / 64, 64), 128, att_smem>>>(q, k, v, ctx);
    // output projection + residual
    sgemm_nt_kernel<MODE_BIAS_RES><<<gP, blk>>>(ctx, Wo_w, Wo_b, x, x1, N_TOK, EMB, EMB);
    // LN2
    rowstats_kernel<<<N_TOK, 256>>>(x1, rs, rq);
    finalize_var_kernel<<<1, 256>>>(rs, rq, var);
    ln_apply_kernel<<<LN_BLOCKS, 256>>>(x1, rs, var, n2s, n2b, h);
    // FFN
    sgemm_nt_kernel<MODE_BIAS_GELU><<<gF, blk>>>(h, l1_w, l1_b, nullptr, ff, N_TOK, DFF, EMB);
    sgemm_nt_kernel<MODE_BIAS_RES><<<gP, blk>>>(ff, l2_w, l2_b, x1, out, N_TOK, EMB, DFF);
}

// round 7
// speedup vs baseline: 1.8829x; 1.8829x over previous
#include <cuda_runtime.h>
#include <cuda_bf16.h>
#include <math.h>
#include <stdint.h>

#define N_TOK 8192
#define EMB   1024
#define DFF   4096
#define TSEQ  2048

// ---------------- scratch (device globals; no allocations allowed) ----------
__device__ float g_q  [N_TOK * EMB];
__device__ float g_k  [N_TOK * EMB];
__device__ float g_v  [N_TOK * EMB];
__device__ float g_x1 [N_TOK * EMB];
__device__ float g_rowsum[N_TOK];
__device__ float g_rowsq [N_TOK];
__device__ float g_var[2];

__device__ __nv_bfloat16 g_h_hi [N_TOK * EMB];
__device__ __nv_bfloat16 g_h_lo [N_TOK * EMB];
__device__ __nv_bfloat16 g_ctx_hi[N_TOK * EMB];
__device__ __nv_bfloat16 g_ctx_lo[N_TOK * EMB];
__device__ __nv_bfloat16 g_ff_hi [N_TOK * DFF];
__device__ __nv_bfloat16 g_ff_lo [N_TOK * DFF];
__device__ __nv_bfloat16 g_wq_hi[EMB * EMB], g_wq_lo[EMB * EMB];
__device__ __nv_bfloat16 g_wk_hi[EMB * EMB], g_wk_lo[EMB * EMB];
__device__ __nv_bfloat16 g_wv_hi[EMB * EMB], g_wv_lo[EMB * EMB];
__device__ __nv_bfloat16 g_wo_hi[EMB * EMB], g_wo_lo[EMB * EMB];
__device__ __nv_bfloat16 g_l1_hi[DFF * EMB], g_l1_lo[DFF * EMB];
__device__ __nv_bfloat16 g_l2_hi[EMB * DFF], g_l2_lo[EMB * DFF];

union F4U { float4 f4; unsigned long long u2[2]; float f[4]; };
union PDU { unsigned long long u; float f[2]; };
union BF4 { __nv_bfloat16 h[4]; uint2 u; };
union BF2 { __nv_bfloat16 h[2]; uint32_t u; };

__device__ __forceinline__ unsigned long long dup_f32(float v) {
    unsigned long long r;
    asm("mov.b64 %0, {%1, %1};" : "=l"(r) : "f"(v));
    return r;
}
__device__ __forceinline__ void fma2(unsigned long long& acc,
                                     unsigned long long a, unsigned long long b) {
    asm("fma.rn.f32x2 %0, %1, %2, %0;" : "+l"(acc) : "l"(a), "l"(b));
}
__device__ __forceinline__ void mul2(unsigned long long& acc, unsigned long long a) {
    asm("mul.rn.f32x2 %0, %0, %1;" : "+l"(acc) : "l"(a));
}
__device__ __forceinline__ void split_bf16(float v, __nv_bfloat16& hi, __nv_bfloat16& lo) {
    hi = __float2bfloat16(v);
    lo = __float2bfloat16(v - __bfloat162float(hi));
}
__device__ __forceinline__ uint32_t smem_u32(const void* p) {
    uint32_t a;
    asm("{ .reg .u64 t; cvta.to.shared.u64 t, %1; cvt.u32.u64 %0, t; }" : "=r"(a) : "l"(p));
    return a;
}
__device__ __forceinline__ void cp16(uint32_t dst, const void* src) {
    asm volatile("cp.async.cg.shared.global [%0], [%1], 16;" :: "r"(dst), "l"(src) : "memory");
}
__device__ __forceinline__ void cp_commit() {
    asm volatile("cp.async.commit_group;" ::: "memory");
}
template <int N>
__device__ __forceinline__ void cp_wait() {
    asm volatile("cp.async.wait_group %0;" :: "n"(N) : "memory");
}
__device__ __forceinline__ void ldmx4(uint32_t* r, uint32_t addr) {
    asm volatile("ldmatrix.sync.aligned.m8n8.x4.shared.b16 {%0,%1,%2,%3}, [%4];"
                 : "=r"(r[0]), "=r"(r[1]), "=r"(r[2]), "=r"(r[3]) : "r"(addr));
}
__device__ __forceinline__ void mma_bf16(float* c, const uint32_t* a, const uint32_t* b) {
    asm volatile("mma.sync.aligned.m16n8k16.row.col.f32.bf16.bf16.f32 "
                 "{%0,%1,%2,%3}, {%4,%5,%6,%7}, {%8,%9}, {%0,%1,%2,%3};"
                 : "+f"(c[0]), "+f"(c[1]), "+f"(c[2]), "+f"(c[3])
                 : "r"(a[0]), "r"(a[1]), "r"(a[2]), "r"(a[3]), "r"(b[0]), "r"(b[1]));
}

// ---------------- split kernels ----------------------------------------------
__global__ void split_kernel(const float* __restrict__ x,
                             __nv_bfloat16* __restrict__ hi,
                             __nv_bfloat16* __restrict__ lo, int n4) {
    int i = blockIdx.x * blockDim.x + threadIdx.x;
    if (i >= n4) return;
    float4 v = ((const float4*)x)[i];
    BF4 H, L;
#pragma unroll
    for (int j = 0; j < 4; j++) split_bf16((&v.x)[j], H.h[j], L.h[j]);
    ((uint2*)hi)[i] = H.u;
    ((uint2*)lo)[i] = L.u;
}

// ---------------- LN pieces ---------------------------------------------------
__global__ void rowstats_kernel(const float* __restrict__ x,
                                float* __restrict__ rowsum,
                                float* __restrict__ rowsq) {
    int row = blockIdx.x, tid = threadIdx.x;
    float4 v = *(const float4*)(x + (size_t)row * EMB + tid * 4);
    float s = v.x + v.y + v.z + v.w;
    float q = v.x * v.x + v.y * v.y + v.z * v.z + v.w * v.w;
#pragma unroll
    for (int o = 16; o > 0; o >>= 1) {
        s += __shfl_down_sync(0xffffffffu, s, o);
        q += __shfl_down_sync(0xffffffffu, q, o);
    }
    __shared__ float ss[8], qs[8];
    int w = tid >> 5, lane = tid & 31;
    if (lane == 0) { ss[w] = s; qs[w] = q; }
    __syncthreads();
    if (tid == 0) {
        float S = 0.f, Q = 0.f;
#pragma unroll
        for (int i = 0; i < 8; i++) { S += ss[i]; Q += qs[i]; }
        rowsum[row] = S; rowsq[row] = Q;
    }
}

__global__ void finalize_var_kernel(const float* __restrict__ rowsum,
                                    const float* __restrict__ rowsq,
                                    float* __restrict__ varout) {
    int tid = threadIdx.x;
    double s = 0.0, q = 0.0;
    for (int i = tid; i < N_TOK; i += 256) { s += (double)rowsum[i]; q += (double)rowsq[i]; }
#pragma unroll
    for (int o = 16; o > 0; o >>= 1) {
        s += __shfl_down_sync(0xffffffffu, s, o);
        q += __shfl_down_sync(0xffffffffu, q, o);
    }
    __shared__ double sd[8], qd[8];
    int w = tid >> 5, lane = tid & 31;
    if (lane == 0) { sd[w] = s; qd[w] = q; }
    __syncthreads();
    if (tid == 0) {
        double S = 0.0, Q = 0.0;
        for (int i = 0; i < 8; i++) { S += sd[i]; Q += qd[i]; }
        double M = (double)N_TOK * (double)EMB;
        double mean = S / M;
        varout[0] = (float)(Q / M - mean * mean);
    }
}

__global__ void ln_apply_split_kernel(const float* __restrict__ x,
                                      const float* __restrict__ rowsum,
                                      const float* __restrict__ varp,
                                      const float* __restrict__ scale,
                                      const float* __restrict__ shift,
                                      __nv_bfloat16* __restrict__ hi,
                                      __nv_bfloat16* __restrict__ lo) {
    size_t i4 = (size_t)blockIdx.x * blockDim.x + threadIdx.x;
    size_t off = i4 * 4;
    int row = (int)(off >> 10), col = (int)(off & 1023);
    float invv = 1.0f / varp[0];
    float mean = rowsum[row] * (1.0f / 1024.0f);
    float4 v  = *(const float4*)(x + off);
    float4 sc = *(const float4*)(scale + col);
    float4 sh = *(const float4*)(shift + col);
    float o[4];
    o[0] = ((v.x - mean) * invv + 1e-5f) * sc.x + sh.x;
    o[1] = ((v.y - mean) * invv + 1e-5f) * sc.y + sh.y;
    o[2] = ((v.z - mean) * invv + 1e-5f) * sc.z + sh.z;
    o[3] = ((v.w - mean) * invv + 1e-5f) * sc.w + sh.w;
    BF4 H, L;
#pragma unroll
    for (int j = 0; j < 4; j++) split_bf16(o[j], H.h[j], L.h[j]);
    ((uint2*)hi)[i4] = H.u;
    ((uint2*)lo)[i4] = L.u;
}

// ---------------- mma.sync GEMM: C[M,N] = A[M,K]*B[N,K]^T --------------------
// A,B as bf16 hi/lo; fp32 emulation: AhBh + AlBh + AhBl into one fp32 acc.
enum { MODE_BIAS = 0, MODE_BIAS_RES = 1, MODE_GELU_SPLIT = 2 };

#define STAGE_BYTES 65536
#define MM_SMEM (2 * STAGE_BYTES)

template <int MODE>
__global__ __launch_bounds__(256)
void mmagemm_kernel(const __nv_bfloat16* __restrict__ Ah, const __nv_bfloat16* __restrict__ Al,
                    const __nv_bfloat16* __restrict__ Bh, const __nv_bfloat16* __restrict__ Bl,
                    const float* __restrict__ bias, const float* __restrict__ res,
                    float* __restrict__ C,
                    __nv_bfloat16* __restrict__ Oh, __nv_bfloat16* __restrict__ Ol,
                    int N, int K) {
    extern __shared__ char smg[];
    const uint32_t sb = smem_u32(smg);
    const int tid = threadIdx.x, wid = tid >> 5, lane = tid & 31;
    const int warpM = wid >> 2;    // 0..1 -> 64-row half
    const int warpN = wid & 3;     // 0..3 -> 32-col quarter
    const size_t rowA0 = (size_t)blockIdx.y * 128;
    const size_t rowB0 = (size_t)blockIdx.x * 128;

    // staging: gi = 16B group in 128B row (8), r0 = base row (0..31), 4 rows/thread/tile
    const int gi = tid & 7;
    const int r0 = tid >> 3;
    uint32_t so[4];
#pragma unroll
    for (int i = 0; i < 4; i++) {
        uint32_t o = (uint32_t)((r0 + 32 * i) * 128 + gi * 16);
        so[i] = o ^ ((o >> 3) & 0x70);
    }

    auto cpchunk = [&](int k0, int st) {
        uint32_t base = sb + st * STAGE_BYTES;
#pragma unroll
        for (int i = 0; i < 4; i++) {
            int r = r0 + 32 * i;
            size_t oa = (rowA0 + r) * (size_t)K + k0 + gi * 8;
            size_t ob = (rowB0 + r) * (size_t)K + k0 + gi * 8;
            cp16(base +         so[i], Ah + oa);
            cp16(base + 16384 + so[i], Al + oa);
            cp16(base + 32768 + so[i], Bh + ob);
            cp16(base + 49152 + so[i], Bl + ob);
        }
        cp_commit();
    };

    float acc[4][4][4];
#pragma unroll
    for (int mi = 0; mi < 4; mi++)
#pragma unroll
        for (int ni = 0; ni < 4; ni++)
#pragma unroll
            for (int j = 0; j < 4; j++) acc[mi][ni][j] = 0.0f;

    const int NC = K / 64;
    cpchunk(0, 0);
    for (int c = 0; c < NC; ++c) {
        if (c + 1 < NC) { cpchunk((c + 1) * 64, (c + 1) & 1); cp_wait<1>(); }
        else            { cp_wait<0>(); }
        __syncthreads();

        uint32_t base = sb + (c & 1) * STAGE_BYTES;
#pragma unroll
        for (int ks = 0; ks < 4; ks++) {
            uint32_t ah[4][4], al[4][4], bh[4][2], bl[4][2];
#pragma unroll
            for (int mi = 0; mi < 4; mi++) {
                int row = warpM * 64 + mi * 16 + (lane & 15);
                uint32_t o = (uint32_t)(row * 128 + ks * 32 + ((lane >> 4) << 4));
                uint32_t sw = o ^ ((o >> 3) & 0x70);
                ldmx4(ah[mi], base + sw);
                ldmx4(al[mi], base + 16384 + sw);
            }
#pragma unroll
            for (int np = 0; np < 2; np++) {
                int row = warpN * 32 + np * 16 + (lane & 15);
                uint32_t o = (uint32_t)(row * 128 + ks * 32 + ((lane >> 4) << 4));
                uint32_t sw = o ^ ((o >> 3) & 0x70);
                uint32_t t[4];
                ldmx4(t, base + 32768 + sw);
                bh[np * 2][0] = t[0]; bh[np * 2][1] = t[2];
                bh[np * 2 + 1][0] = t[1]; bh[np * 2 + 1][1] = t[3];
                ldmx4(t, base + 49152 + sw);
                bl[np * 2][0] = t[0]; bl[np * 2][1] = t[2];
                bl[np * 2 + 1][0] = t[1]; bl[np * 2 + 1][1] = t[3];
            }
#pragma unroll
            for (int mi = 0; mi < 4; mi++)
#pragma unroll
                for (int ni = 0; ni < 4; ni++) {
                    mma_bf16(acc[mi][ni], ah[mi], bh[ni]);
                    mma_bf16(acc[mi][ni], al[mi], bh[ni]);
                    mma_bf16(acc[mi][ni], ah[mi], bl[ni]);
                }
        }
        __syncthreads();
    }

    // epilogue: c0,c1 -> row rbase+mi*16, cols cbase+ni*8 (+1); c2,c3 -> row+8
    const int rbase = (int)rowA0 + warpM * 64 + (lane >> 2);
    const int cbase = (int)rowB0 + warpN * 32 + (lane & 3) * 2;
#pragma unroll
    for (int mi = 0; mi < 4; mi++) {
#pragma unroll
        for (int ni = 0; ni < 4; ni++) {
            int cg = cbase + ni * 8;
            float2 bv = *(const float2*)(bias + cg);
#pragma unroll
            for (int h = 0; h < 2; h++) {
                int rg = rbase + mi * 16 + h * 8;
                float o0 = acc[mi][ni][2 * h]     + bv.x;
                float o1 = acc[mi][ni][2 * h + 1] + bv.y;
                size_t off = (size_t)rg * N + cg;
                if (MODE == MODE_BIAS_RES) {
                    float2 r = *(const float2*)(res + off);
                    o0 += r.x; o1 += r.y;
                }
                if (MODE == MODE_GELU_SPLIT) {
                    float g0 = 0.5f * o0 * (1.0f + erff(o0 * 0.70710678118654752f));
                    float g1 = 0.5f * o1 * (1.0f + erff(o1 * 0.70710678118654752f));
                    BF2 H, L;
                    split_bf16(g0, H.h[0], L.h[0]);
                    split_bf16(g1, H.h[1], L.h[1]);
                    *(uint32_t*)(Oh + off) = H.u;
                    *(uint32_t*)(Ol + off) = L.u;
                } else {
                    float2 w; w.x = o0; w.y = o1;
                    *(float2*)(C + off) = w;
                }
            }
        }
    }
}

// ---------------- causal flash attention (fp32, f32x2) ----------------------
#define ATT_SMEM_FLOATS (64 * 65 + 64 * 68 + 64 * 68)

__global__ __launch_bounds__(128)
void attn_kernel(const float* __restrict__ Qb, const float* __restrict__ Kb,
                 const float* __restrict__ Vb,
                 __nv_bfloat16* __restrict__ Oh, __nv_bfloat16* __restrict__ Ol) {
    extern __shared__ float sm[];
    float* Qs  = sm;
    float* Kst = sm + 64 * 65;
    float* Vs  = Kst + 64 * 68;
    const int qt   = blockIdx.x;
    const int bh   = blockIdx.y;
    const int bb   = bh >> 4;
    const int head = bh & 15;
    const int tid  = threadIdx.x;
    const int qr   = tid >> 1;
    const int hf   = tid & 1;
    const int lane = tid & 31;
    const size_t hoff = (size_t)head * 64;
    const int qg = qt * 64 + qr;

    for (int idx = tid; idx < 64 * 16; idx += 128) {
        int r = idx >> 4, c4 = idx & 15;
        F4U u;
        u.f4 = *(const float4*)(Qb + ((size_t)(bb * TSEQ + qt * 64 + r)) * EMB + hoff + c4 * 4);
#pragma unroll
        for (int i = 0; i < 4; i++) Qs[r * 65 + c4 * 4 + i] = u.f[i] * 0.125f;
    }

    float m = -3.0e38f, l = 0.0f;
    unsigned long long acc[16];
#pragma unroll
    for (int i = 0; i < 16; i++) acc[i] = 0ull;

    for (int kt = 0; kt <= qt; ++kt) {
        __syncthreads();
        for (int idx = tid; idx < 64 * 16; idx += 128) {
            int r = idx >> 4, c4 = idx & 15;
            size_t gbase = ((size_t)(bb * TSEQ + kt * 64 + r)) * EMB + hoff + c4 * 4;
            F4U u; u.f4 = *(const float4*)(Kb + gbase);
#pragma unroll
            for (int i = 0; i < 4; i++) Kst[(c4 * 4 + i) * 68 + r] = u.f[i];
            *(float4*)&Vs[r * 68 + c4 * 4] = *(const float4*)(Vb + gbase);
        }
        __syncthreads();

        unsigned long long s2[16];
#pragma unroll
        for (int i = 0; i < 16; i++) s2[i] = 0ull;
#pragma unroll 8
        for (int d = 0; d < 64; ++d) {
            unsigned long long qd = dup_f32(Qs[qr * 65 + d]);
            const float4* kp = (const float4*)&Kst[d * 68 + hf * 32];
#pragma unroll
            for (int j4 = 0; j4 < 8; j4++) {
                F4U u; u.f4 = kp[j4];
                fma2(s2[2 * j4],     qd, u.u2[0]);
                fma2(s2[2 * j4 + 1], qd, u.u2[1]);
            }
        }
        float s[32];
#pragma unroll
        for (int i = 0; i < 16; i++) {
            PDU p; p.u = s2[i];
            s[2 * i] = p.f[0]; s[2 * i + 1] = p.f[1];
        }
        if (kt == qt) {
            int kg0 = kt * 64 + hf * 32;
#pragma unroll
            for (int jj = 0; jj < 32; jj++)
                if (kg0 + jj > qg) s[jj] = -1e30f;
        }
        float tmax = s[0];
#pragma unroll
        for (int jj = 1; jj < 32; jj++) tmax = fmaxf(tmax, s[jj]);
        tmax = fmaxf(tmax, __shfl_xor_sync(0xffffffffu, tmax, 1));
        float mn = fmaxf(m, tmax);
        float alpha = __expf(m - mn);
        float p[32];
        float ps = 0.0f;
#pragma unroll
        for (int jj = 0; jj < 32; jj++) { p[jj] = __expf(s[jj] - mn); ps += p[jj]; }
        ps += __shfl_xor_sync(0xffffffffu, ps, 1);
        l = l * alpha + ps;
        m = mn;
        unsigned long long al = dup_f32(alpha);
#pragma unroll
        for (int i = 0; i < 16; i++) mul2(acc[i], al);
#pragma unroll
        for (int j = 0; j < 64; j++) {
            float pj = __shfl_sync(0xffffffffu, p[j & 31], (lane & 30) | (j >> 5));
            unsigned long long pd = dup_f32(pj);
            const float4* vp = (const float4*)&Vs[j * 68 + hf * 32];
#pragma unroll
            for (int q4 = 0; q4 < 8; q4++) {
                F4U u; u.f4 = vp[q4];
                fma2(acc[2 * q4],     pd, u.u2[0]);
                fma2(acc[2 * q4 + 1], pd, u.u2[1]);
            }
        }
    }
    float inv = 1.0f / l;
    size_t obase = ((size_t)(bb * TSEQ + qg)) * EMB + hoff + hf * 32;
#pragma unroll
    for (int q4 = 0; q4 < 8; q4++) {
        PDU p0; p0.u = acc[2 * q4];
        PDU p1; p1.u = acc[2 * q4 + 1];
        float o[4] = { p0.f[0] * inv, p0.f[1] * inv, p1.f[0] * inv, p1.f[1] * inv };
        BF4 H, L;
#pragma unroll
        for (int j = 0; j < 4; j++) split_bf16(o[j], H.h[j], L.h[j]);
        *(uint2*)(Oh + obase + 4 * q4) = H.u;
        *(uint2*)(Ol + obase + 4 * q4) = L.u;
    }
}

// ---------------- orchestration ----------------------------------------------
extern "C" void kernel_launch(void* const* d_in, const int* in_sizes, int n_in,
                              void* d_out, int out_size) {
    (void)in_sizes; (void)n_in; (void)out_size;
    const float* x    = (const float*)d_in[0];
    const float* Wq_w = (const float*)d_in[1];
    const float* Wq_b = (const float*)d_in[2];
    const float* Wk_w = (const float*)d_in[3];
    const float* Wk_b = (const float*)d_in[4];
    const float* Wv_w = (const float*)d_in[5];
    const float* Wv_b = (const float*)d_in[6];
    const float* Wo_w = (const float*)d_in[7];
    const float* Wo_b = (const float*)d_in[8];
    const float* l1_w = (const float*)d_in[9];
    const float* l1_b = (const float*)d_in[10];
    const float* l2_w = (const float*)d_in[11];
    const float* l2_b = (const float*)d_in[12];
    const float* n1s  = (const float*)d_in[13];
    const float* n1b  = (const float*)d_in[14];
    const float* n2s  = (const float*)d_in[15];
    const float* n2b  = (const float*)d_in[16];
    float* out = (float*)d_out;

    float *q, *k, *v, *x1, *rs, *rq, *var;
    cudaGetSymbolAddress((void**)&q,   g_q);
    cudaGetSymbolAddress((void**)&k,   g_k);
    cudaGetSymbolAddress((void**)&v,   g_v);
    cudaGetSymbolAddress((void**)&x1,  g_x1);
    cudaGetSymbolAddress((void**)&rs,  g_rowsum);
    cudaGetSymbolAddress((void**)&rq,  g_rowsq);
    cudaGetSymbolAddress((void**)&var, g_var);

    __nv_bfloat16 *h_hi, *h_lo, *ctx_hi, *ctx_lo, *ff_hi, *ff_lo;
    __nv_bfloat16 *wq_hi, *wq_lo, *wk_hi, *wk_lo, *wv_hi, *wv_lo, *wo_hi, *wo_lo;
    __nv_bfloat16 *l1_hi, *l1_lo, *l2_hi, *l2_lo;
    cudaGetSymbolAddress((void**)&h_hi,  g_h_hi);
    cudaGetSymbolAddress((void**)&h_lo,  g_h_lo);
    cudaGetSymbolAddress((void**)&ctx_hi, g_ctx_hi);
    cudaGetSymbolAddress((void**)&ctx_lo, g_ctx_lo);
    cudaGetSymbolAddress((void**)&ff_hi, g_ff_hi);
    cudaGetSymbolAddress((void**)&ff_lo, g_ff_lo);
    cudaGetSymbolAddress((void**)&wq_hi, g_wq_hi);
    cudaGetSymbolAddress((void**)&wq_lo, g_wq_lo);
    cudaGetSymbolAddress((void**)&wk_hi, g_wk_hi);
    cudaGetSymbolAddress((void**)&wk_lo, g_wk_lo);
    cudaGetSymbolAddress((void**)&wv_hi, g_wv_hi);
    cudaGetSymbolAddress((void**)&wv_lo, g_wv_lo);
    cudaGetSymbolAddress((void**)&wo_hi, g_wo_hi);
    cudaGetSymbolAddress((void**)&wo_lo, g_wo_lo);
    cudaGetSymbolAddress((void**)&l1_hi, g_l1_hi);
    cudaGetSymbolAddress((void**)&l1_lo, g_l1_lo);
    cudaGetSymbolAddress((void**)&l2_hi, g_l2_hi);
    cudaGetSymbolAddress((void**)&l2_lo, g_l2_lo);

    const int att_smem = (int)(ATT_SMEM_FLOATS * sizeof(float));
    cudaFuncSetAttribute((const void*)attn_kernel,
                         cudaFuncAttributeMaxDynamicSharedMemorySize, att_smem);
    cudaFuncSetAttribute((const void*)mmagemm_kernel<MODE_BIAS>,
                         cudaFuncAttributeMaxDynamicSharedMemorySize, MM_SMEM);
    cudaFuncSetAttribute((const void*)mmagemm_kernel<MODE_BIAS_RES>,
                         cudaFuncAttributeMaxDynamicSharedMemorySize, MM_SMEM);
    cudaFuncSetAttribute((const void*)mmagemm_kernel<MODE_GELU_SPLIT>,
                         cudaFuncAttributeMaxDynamicSharedMemorySize, MM_SMEM);

    const int LN_BLOCKS = (N_TOK * EMB / 4) / 256;
    dim3 blk(256);
    dim3 gP(EMB / 128, N_TOK / 128);   // (8, 64)
    dim3 gF(DFF / 128, N_TOK / 128);   // (32, 64)

    // weight splits
    split_kernel<<<(EMB * EMB / 4) / 256, 256>>>(Wq_w, wq_hi, wq_lo, EMB * EMB / 4);
    split_kernel<<<(EMB * EMB / 4) / 256, 256>>>(Wk_w, wk_hi, wk_lo, EMB * EMB / 4);
    split_kernel<<<(EMB * EMB / 4) / 256, 256>>>(Wv_w, wv_hi, wv_lo, EMB * EMB / 4);
    split_kernel<<<(EMB * EMB / 4) / 256, 256>>>(Wo_w, wo_hi, wo_lo, EMB * EMB / 4);
    split_kernel<<<(DFF * EMB / 4) / 256, 256>>>(l1_w, l1_hi, l1_lo, DFF * EMB / 4);
    split_kernel<<<(EMB * DFF / 4) / 256, 256>>>(l2_w, l2_hi, l2_lo, EMB * DFF / 4);

    // LN1 -> h hi/lo
    rowstats_kernel<<<N_TOK, 256>>>(x, rs, rq);
    finalize_var_kernel<<<1, 256>>>(rs, rq, var);
    ln_apply_split_kernel<<<LN_BLOCKS, 256>>>(x, rs, var, n1s, n1b, h_hi, h_lo);

    // QKV projections
    mmagemm_kernel<MODE_BIAS><<<gP, blk, MM_SMEM>>>(
        h_hi, h_lo, wq_hi, wq_lo, Wq_b, nullptr, q, nullptr, nullptr, EMB, EMB);
    mmagemm_kernel<MODE_BIAS><<<gP, blk, MM_SMEM>>>(
        h_hi, h_lo, wk_hi, wk_lo, Wk_b, nullptr, k, nullptr, nullptr, EMB, EMB);
    mmagemm_kernel<MODE_BIAS><<<gP, blk, MM_SMEM>>>(
        h_hi, h_lo, wv_hi, wv_lo, Wv_b, nullptr, v, nullptr, nullptr, EMB, EMB);

    // attention -> ctx hi/lo
    attn_kernel<<<dim3(TSEQ / 64, 64), 128, att_smem>>>(q, k, v, ctx_hi, ctx_lo);

    // output projection + residual
    mmagemm_kernel<MODE_BIAS_RES><<<gP, blk, MM_SMEM>>>(
        ctx_hi, ctx_lo, wo_hi, wo_lo, Wo_b, x, x1, nullptr, nullptr, EMB, EMB);

    // LN2 -> h hi/lo
    rowstats_kernel<<<N_TOK, 256>>>(x1, rs, rq);
    finalize_var_kernel<<<1, 256>>>(rs, rq, var);
    ln_apply_split_kernel<<<LN_BLOCKS, 256>>>(x1, rs, var, n2s, n2b, h_hi, h_lo);

    // FFN
    mmagemm_kernel<MODE_GELU_SPLIT><<<gF, blk, MM_SMEM>>>(
        h_hi, h_lo, l1_hi, l1_lo, l1_b, nullptr, nullptr, ff_hi, ff_lo, DFF, EMB);
    mmagemm_kernel<MODE_BIAS_RES><<<gP, blk, MM_SMEM>>>(
        ff_hi, ff_lo, l2_hi, l2_lo, l2_b, x1, out, nullptr, nullptr, EMB, DFF);
}

// round 8
// speedup vs baseline: 3.1343x; 1.6646x over previous
#include <cuda_runtime.h>
#include <cuda_bf16.h>
#include <math.h>
#include <stdint.h>

#define N_TOK 8192
#define EMB   1024
#define DFF   4096
#define TSEQ  2048

// ---------------- scratch (device globals; no allocations allowed) ----------
__device__ float g_q  [N_TOK * EMB];
__device__ float g_k  [N_TOK * EMB];
__device__ float g_v  [N_TOK * EMB];
__device__ float g_x1 [N_TOK * EMB];
__device__ float g_rowsum[N_TOK];
__device__ float g_rowsq [N_TOK];
__device__ float g_var[2];

__device__ __nv_bfloat16 g_h_hi [N_TOK * EMB];
__device__ __nv_bfloat16 g_h_lo [N_TOK * EMB];
__device__ __nv_bfloat16 g_ctx_hi[N_TOK * EMB];
__device__ __nv_bfloat16 g_ctx_lo[N_TOK * EMB];
__device__ __nv_bfloat16 g_ff_hi [N_TOK * DFF];
__device__ __nv_bfloat16 g_ff_lo [N_TOK * DFF];
__device__ __nv_bfloat16 g_wq_hi[EMB * EMB], g_wq_lo[EMB * EMB];
__device__ __nv_bfloat16 g_wk_hi[EMB * EMB], g_wk_lo[EMB * EMB];
__device__ __nv_bfloat16 g_wv_hi[EMB * EMB], g_wv_lo[EMB * EMB];
__device__ __nv_bfloat16 g_wo_hi[EMB * EMB], g_wo_lo[EMB * EMB];
__device__ __nv_bfloat16 g_l1_hi[DFF * EMB], g_l1_lo[DFF * EMB];
__device__ __nv_bfloat16 g_l2_hi[EMB * DFF], g_l2_lo[EMB * DFF];

union F4U { float4 f4; unsigned long long u2[2]; float f[4]; };
union BF4 { __nv_bfloat16 h[4]; uint2 u; };
union BF2 { __nv_bfloat16 h[2]; uint32_t u; };

__device__ __forceinline__ void split_bf16(float v, __nv_bfloat16& hi, __nv_bfloat16& lo) {
    hi = __float2bfloat16(v);
    lo = __float2bfloat16(v - __bfloat162float(hi));
}
__device__ __forceinline__ uint32_t smem_u32(const void* p) {
    uint32_t a;
    asm("{ .reg .u64 t; cvta.to.shared.u64 t, %1; cvt.u32.u64 %0, t; }" : "=r"(a) : "l"(p));
    return a;
}
__device__ __forceinline__ void cp16(uint32_t dst, const void* src) {
    asm volatile("cp.async.cg.shared.global [%0], [%1], 16;" :: "r"(dst), "l"(src) : "memory");
}
__device__ __forceinline__ void cp_commit() {
    asm volatile("cp.async.commit_group;" ::: "memory");
}
template <int N>
__device__ __forceinline__ void cp_wait() {
    asm volatile("cp.async.wait_group %0;" :: "n"(N) : "memory");
}
__device__ __forceinline__ void ldmx4(uint32_t* r, uint32_t addr) {
    asm volatile("ldmatrix.sync.aligned.m8n8.x4.shared.b16 {%0,%1,%2,%3}, [%4];"
                 : "=r"(r[0]), "=r"(r[1]), "=r"(r[2]), "=r"(r[3]) : "r"(addr));
}
__device__ __forceinline__ void mma_bf16(float* c, const uint32_t* a, const uint32_t* b) {
    asm volatile("mma.sync.aligned.m16n8k16.row.col.f32.bf16.bf16.f32 "
                 "{%0,%1,%2,%3}, {%4,%5,%6,%7}, {%8,%9}, {%0,%1,%2,%3};"
                 : "+f"(c[0]), "+f"(c[1]), "+f"(c[2]), "+f"(c[3])
                 : "r"(a[0]), "r"(a[1]), "r"(a[2]), "r"(a[3]), "r"(b[0]), "r"(b[1]));
}
__device__ __forceinline__ uint32_t sw128(uint32_t o) { return o ^ ((o >> 3) & 0x70); }

// ---------------- split kernels ----------------------------------------------
__global__ void split_kernel(const float* __restrict__ x,
                             __nv_bfloat16* __restrict__ hi,
                             __nv_bfloat16* __restrict__ lo, int n4) {
    int i = blockIdx.x * blockDim.x + threadIdx.x;
    if (i >= n4) return;
    float4 v = ((const float4*)x)[i];
    BF4 H, L;
#pragma unroll
    for (int j = 0; j < 4; j++) split_bf16((&v.x)[j], H.h[j], L.h[j]);
    ((uint2*)hi)[i] = H.u;
    ((uint2*)lo)[i] = L.u;
}

// ---------------- LN pieces ---------------------------------------------------
__global__ void rowstats_kernel(const float* __restrict__ x,
                                float* __restrict__ rowsum,
                                float* __restrict__ rowsq) {
    int row = blockIdx.x, tid = threadIdx.x;
    float4 v = *(const float4*)(x + (size_t)row * EMB + tid * 4);
    float s = v.x + v.y + v.z + v.w;
    float q = v.x * v.x + v.y * v.y + v.z * v.z + v.w * v.w;
#pragma unroll
    for (int o = 16; o > 0; o >>= 1) {
        s += __shfl_down_sync(0xffffffffu, s, o);
        q += __shfl_down_sync(0xffffffffu, q, o);
    }
    __shared__ float ss[8], qs[8];
    int w = tid >> 5, lane = tid & 31;
    if (lane == 0) { ss[w] = s; qs[w] = q; }
    __syncthreads();
    if (tid == 0) {
        float S = 0.f, Q = 0.f;
#pragma unroll
        for (int i = 0; i < 8; i++) { S += ss[i]; Q += qs[i]; }
        rowsum[row] = S; rowsq[row] = Q;
    }
}

__global__ void finalize_var_kernel(const float* __restrict__ rowsum,
                                    const float* __restrict__ rowsq,
                                    float* __restrict__ varout) {
    int tid = threadIdx.x;
    double s = 0.0, q = 0.0;
    for (int i = tid; i < N_TOK; i += 256) { s += (double)rowsum[i]; q += (double)rowsq[i]; }
#pragma unroll
    for (int o = 16; o > 0; o >>= 1) {
        s += __shfl_down_sync(0xffffffffu, s, o);
        q += __shfl_down_sync(0xffffffffu, q, o);
    }
    __shared__ double sd[8], qd[8];
    int w = tid >> 5, lane = tid & 31;
    if (lane == 0) { sd[w] = s; qd[w] = q; }
    __syncthreads();
    if (tid == 0) {
        double S = 0.0, Q = 0.0;
        for (int i = 0; i < 8; i++) { S += sd[i]; Q += qd[i]; }
        double M = (double)N_TOK * (double)EMB;
        double mean = S / M;
        varout[0] = (float)(Q / M - mean * mean);
    }
}

__global__ void ln_apply_split_kernel(const float* __restrict__ x,
                                      const float* __restrict__ rowsum,
                                      const float* __restrict__ varp,
                                      const float* __restrict__ scale,
                                      const float* __restrict__ shift,
                                      __nv_bfloat16* __restrict__ hi,
                                      __nv_bfloat16* __restrict__ lo) {
    size_t i4 = (size_t)blockIdx.x * blockDim.x + threadIdx.x;
    size_t off = i4 * 4;
    int row = (int)(off >> 10), col = (int)(off & 1023);
    float invv = 1.0f / varp[0];
    float mean = rowsum[row] * (1.0f / 1024.0f);
    float4 v  = *(const float4*)(x + off);
    float4 sc = *(const float4*)(scale + col);
    float4 sh = *(const float4*)(shift + col);
    float o[4];
    o[0] = ((v.x - mean) * invv + 1e-5f) * sc.x + sh.x;
    o[1] = ((v.y - mean) * invv + 1e-5f) * sc.y + sh.y;
    o[2] = ((v.z - mean) * invv + 1e-5f) * sc.z + sh.z;
    o[3] = ((v.w - mean) * invv + 1e-5f) * sc.w + sh.w;
    BF4 H, L;
#pragma unroll
    for (int j = 0; j < 4; j++) split_bf16(o[j], H.h[j], L.h[j]);
    ((uint2*)hi)[i4] = H.u;
    ((uint2*)lo)[i4] = L.u;
}

// ---------------- mma.sync GEMM: C[M,N] = A[M,K]*B[N,K]^T --------------------
enum { MODE_BIAS = 0, MODE_BIAS_RES = 1, MODE_GELU_SPLIT = 2 };

#define STAGE_BYTES 65536
#define MM_SMEM (2 * STAGE_BYTES)

template <int MODE>
__global__ __launch_bounds__(256)
void mmagemm_kernel(const __nv_bfloat16* __restrict__ Ah, const __nv_bfloat16* __restrict__ Al,
                    const __nv_bfloat16* __restrict__ Bh, const __nv_bfloat16* __restrict__ Bl,
                    const float* __restrict__ bias, const float* __restrict__ res,
                    float* __restrict__ C,
                    __nv_bfloat16* __restrict__ Oh, __nv_bfloat16* __restrict__ Ol,
                    int N, int K) {
    extern __shared__ char smg[];
    const uint32_t sb = smem_u32(smg);
    const int tid = threadIdx.x, wid = tid >> 5, lane = tid & 31;
    const int warpM = wid >> 2;
    const int warpN = wid & 3;
    const size_t rowA0 = (size_t)blockIdx.y * 128;
    const size_t rowB0 = (size_t)blockIdx.x * 128;

    const int gi = tid & 7;
    const int r0 = tid >> 3;
    uint32_t so[4];
#pragma unroll
    for (int i = 0; i < 4; i++) {
        uint32_t o = (uint32_t)((r0 + 32 * i) * 128 + gi * 16);
        so[i] = sw128(o);
    }

    auto cpchunk = [&](int k0, int st) {
        uint32_t base = sb + st * STAGE_BYTES;
#pragma unroll
        for (int i = 0; i < 4; i++) {
            int r = r0 + 32 * i;
            size_t oa = (rowA0 + r) * (size_t)K + k0 + gi * 8;
            size_t ob = (rowB0 + r) * (size_t)K + k0 + gi * 8;
            cp16(base +         so[i], Ah + oa);
            cp16(base + 16384 + so[i], Al + oa);
            cp16(base + 32768 + so[i], Bh + ob);
            cp16(base + 49152 + so[i], Bl + ob);
        }
        cp_commit();
    };

    float acc[4][4][4];
#pragma unroll
    for (int mi = 0; mi < 4; mi++)
#pragma unroll
        for (int ni = 0; ni < 4; ni++)
#pragma unroll
            for (int j = 0; j < 4; j++) acc[mi][ni][j] = 0.0f;

    const int NC = K / 64;
    cpchunk(0, 0);
    for (int c = 0; c < NC; ++c) {
        if (c + 1 < NC) { cpchunk((c + 1) * 64, (c + 1) & 1); cp_wait<1>(); }
        else            { cp_wait<0>(); }
        __syncthreads();

        uint32_t base = sb + (c & 1) * STAGE_BYTES;
#pragma unroll
        for (int ks = 0; ks < 4; ks++) {
            uint32_t ah[4][4], al[4][4], bh[4][2], bl[4][2];
#pragma unroll
            for (int mi = 0; mi < 4; mi++) {
                int row = warpM * 64 + mi * 16 + (lane & 15);
                uint32_t sw = sw128((uint32_t)(row * 128 + ks * 32 + ((lane >> 4) << 4)));
                ldmx4(ah[mi], base + sw);
                ldmx4(al[mi], base + 16384 + sw);
            }
#pragma unroll
            for (int np = 0; np < 2; np++) {
                int row = warpN * 32 + np * 16 + (lane & 15);
                uint32_t sw = sw128((uint32_t)(row * 128 + ks * 32 + ((lane >> 4) << 4)));
                uint32_t t[4];
                ldmx4(t, base + 32768 + sw);
                bh[np * 2][0] = t[0]; bh[np * 2][1] = t[2];
                bh[np * 2 + 1][0] = t[1]; bh[np * 2 + 1][1] = t[3];
                ldmx4(t, base + 49152 + sw);
                bl[np * 2][0] = t[0]; bl[np * 2][1] = t[2];
                bl[np * 2 + 1][0] = t[1]; bl[np * 2 + 1][1] = t[3];
            }
#pragma unroll
            for (int mi = 0; mi < 4; mi++)
#pragma unroll
                for (int ni = 0; ni < 4; ni++) {
                    mma_bf16(acc[mi][ni], ah[mi], bh[ni]);
                    mma_bf16(acc[mi][ni], al[mi], bh[ni]);
                    mma_bf16(acc[mi][ni], ah[mi], bl[ni]);
                }
        }
        __syncthreads();
    }

    const int rbase = (int)rowA0 + warpM * 64 + (lane >> 2);
    const int cbase = (int)rowB0 + warpN * 32 + (lane & 3) * 2;
#pragma unroll
    for (int mi = 0; mi < 4; mi++) {
#pragma unroll
        for (int ni = 0; ni < 4; ni++) {
            int cg = cbase + ni * 8;
            float2 bv = *(const float2*)(bias + cg);
#pragma unroll
            for (int h = 0; h < 2; h++) {
                int rg = rbase + mi * 16 + h * 8;
                float o0 = acc[mi][ni][2 * h]     + bv.x;
                float o1 = acc[mi][ni][2 * h + 1] + bv.y;
                size_t off = (size_t)rg * N + cg;
                if (MODE == MODE_BIAS_RES) {
                    float2 r = *(const float2*)(res + off);
                    o0 += r.x; o1 += r.y;
                }
                if (MODE == MODE_GELU_SPLIT) {
                    float g0 = 0.5f * o0 * (1.0f + erff(o0 * 0.70710678118654752f));
                    float g1 = 0.5f * o1 * (1.0f + erff(o1 * 0.70710678118654752f));
                    BF2 H, L;
                    split_bf16(g0, H.h[0], L.h[0]);
                    split_bf16(g1, H.h[1], L.h[1]);
                    *(uint32_t*)(Oh + off) = H.u;
                    *(uint32_t*)(Ol + off) = L.u;
                } else {
                    float2 w; w.x = o0; w.y = o1;
                    *(float2*)(C + off) = w;
                }
            }
        }
    }
}

// ---------------- tensor-core causal flash attention -------------------------
// smem layout (bytes): Qh 0, Ql 8192, Kh 16384, Kl 24576, Vth 32768, Vtl 40960
#define ATT_SMEM 49152
#define AQH 0
#define AQL 8192
#define AKH 16384
#define AKL 24576
#define AVH 32768
#define AVL 40960

__global__ __launch_bounds__(128)
void attn_tc_kernel(const float* __restrict__ Qb, const float* __restrict__ Kb,
                    const float* __restrict__ Vb,
                    __nv_bfloat16* __restrict__ Oh, __nv_bfloat16* __restrict__ Ol) {
    extern __shared__ char smg[];
    const uint32_t sb = smem_u32(smg);
    const int qt   = blockIdx.x;
    const int bh   = blockIdx.y;
    const int bb   = bh >> 4;
    const int head = bh & 15;
    const int tid  = threadIdx.x;
    const int wid  = tid >> 5;
    const int lane = tid & 31;
    const size_t hoff = (size_t)head * 64;
    const size_t seq0 = (size_t)bb * TSEQ;

    // ---- convert Q tile (scaled by 1/8) into smem hi/lo ----
    for (int idx = tid; idx < 64 * 16; idx += 128) {
        int r = idx >> 4, c4 = idx & 15;
        float4 u = *(const float4*)(Qb + (seq0 + qt * 64 + r) * EMB + hoff + c4 * 4);
        BF4 H, L;
#pragma unroll
        for (int j = 0; j < 4; j++) split_bf16((&u.x)[j] * 0.125f, H.h[j], L.h[j]);
        uint32_t sw = sw128((uint32_t)(r * 128 + c4 * 8));
        *(uint2*)(smg + AQH + sw) = H.u;
        *(uint2*)(smg + AQL + sw) = L.u;
    }
    __syncthreads();

    // ---- Q fragments (A operand), per warp rows wid*16.. ----
    uint32_t qh[4][4], ql[4][4];
#pragma unroll
    for (int ks = 0; ks < 4; ks++) {
        int row = wid * 16 + (lane & 15);
        uint32_t sw = sw128((uint32_t)(row * 128 + ks * 32 + ((lane >> 4) << 4)));
        ldmx4(qh[ks], sb + AQH + sw);
        ldmx4(ql[ks], sb + AQL + sw);
    }

    float oacc[8][4];
#pragma unroll
    for (int i = 0; i < 8; i++)
#pragma unroll
        for (int j = 0; j < 4; j++) oacc[i][j] = 0.0f;
    float m0 = -3.0e38f, m1 = -3.0e38f, l0 = 0.0f, l1 = 0.0f;

    const int gr0 = qt * 64 + wid * 16 + (lane >> 2);  // global q row (c0,c1)
    const int cq  = (lane & 3) * 2;

    for (int kt = 0; kt <= qt; ++kt) {
        __syncthreads();
        // convert K tile -> smem [key][d], V tile -> smem transposed [d][key]
        for (int idx = tid; idx < 64 * 16; idx += 128) {
            int r = idx >> 4, c4 = idx & 15;
            size_t gbase = (seq0 + kt * 64 + r) * EMB + hoff + c4 * 4;
            float4 u = *(const float4*)(Kb + gbase);
            BF4 H, L;
#pragma unroll
            for (int j = 0; j < 4; j++) split_bf16((&u.x)[j], H.h[j], L.h[j]);
            uint32_t sw = sw128((uint32_t)(r * 128 + c4 * 8));
            *(uint2*)(smg + AKH + sw) = H.u;
            *(uint2*)(smg + AKL + sw) = L.u;
            float4 w = *(const float4*)(Vb + gbase);
#pragma unroll
            for (int j = 0; j < 4; j++) {
                __nv_bfloat16 vh, vl;
                split_bf16((&w.x)[j], vh, vl);
                int d = c4 * 4 + j;
                uint32_t o = (uint32_t)(d * 128 + r * 2);
                *(__nv_bfloat16*)(smg + AVH + sw128(o)) = vh;
                *(__nv_bfloat16*)(smg + AVL + sw128(o)) = vl;
            }
        }
        __syncthreads();

        // ---- S = Q K^T (3-pass) ----
        float sacc[8][4];
#pragma unroll
        for (int i = 0; i < 8; i++)
#pragma unroll
            for (int j = 0; j < 4; j++) sacc[i][j] = 0.0f;
#pragma unroll
        for (int ks = 0; ks < 4; ks++) {
            uint32_t kh[8][2], kl[8][2];
#pragma unroll
            for (int kp = 0; kp < 4; kp++) {
                int row = kp * 16 + (lane & 15);
                uint32_t sw = sw128((uint32_t)(row * 128 + ks * 32 + ((lane >> 4) << 4)));
                uint32_t t[4];
                ldmx4(t, sb + AKH + sw);
                kh[kp * 2][0] = t[0]; kh[kp * 2][1] = t[2];
                kh[kp * 2 + 1][0] = t[1]; kh[kp * 2 + 1][1] = t[3];
                ldmx4(t, sb + AKL + sw);
                kl[kp * 2][0] = t[0]; kl[kp * 2][1] = t[2];
                kl[kp * 2 + 1][0] = t[1]; kl[kp * 2 + 1][1] = t[3];
            }
#pragma unroll
            for (int nt = 0; nt < 8; nt++) {
                mma_bf16(sacc[nt], qh[ks], kh[nt]);
                mma_bf16(sacc[nt], ql[ks], kh[nt]);
                mma_bf16(sacc[nt], qh[ks], kl[nt]);
            }
        }

        // ---- causal mask on diagonal tile ----
        if (kt == qt) {
#pragma unroll
            for (int nt = 0; nt < 8; nt++) {
                int c0 = kt * 64 + nt * 8 + cq;
                if (c0 > gr0)     sacc[nt][0] = -1e30f;
                if (c0 + 1 > gr0) sacc[nt][1] = -1e30f;
                if (c0 > gr0 + 8)     sacc[nt][2] = -1e30f;
                if (c0 + 1 > gr0 + 8) sacc[nt][3] = -1e30f;
            }
        }

        // ---- online softmax (rows r and r+8 per thread) ----
        float t0 = -3.0e38f, t1 = -3.0e38f;
#pragma unroll
        for (int nt = 0; nt < 8; nt++) {
            t0 = fmaxf(t0, fmaxf(sacc[nt][0], sacc[nt][1]));
            t1 = fmaxf(t1, fmaxf(sacc[nt][2], sacc[nt][3]));
        }
        t0 = fmaxf(t0, __shfl_xor_sync(0xffffffffu, t0, 1));
        t0 = fmaxf(t0, __shfl_xor_sync(0xffffffffu, t0, 2));
        t1 = fmaxf(t1, __shfl_xor_sync(0xffffffffu, t1, 1));
        t1 = fmaxf(t1, __shfl_xor_sync(0xffffffffu, t1, 2));
        float mn0 = fmaxf(m0, t0), mn1 = fmaxf(m1, t1);
        float al0 = __expf(m0 - mn0), al1 = __expf(m1 - mn1);
        m0 = mn0; m1 = mn1;

        uint32_t pH[8][2], pL[8][2];
        float ps0 = 0.0f, ps1 = 0.0f;
#pragma unroll
        for (int nt = 0; nt < 8; nt++) {
            float p0 = __expf(sacc[nt][0] - mn0);
            float p1 = __expf(sacc[nt][1] - mn0);
            float p2 = __expf(sacc[nt][2] - mn1);
            float p3 = __expf(sacc[nt][3] - mn1);
            ps0 += p0 + p1; ps1 += p2 + p3;
            BF2 H, L;
            split_bf16(p0, H.h[0], L.h[0]);
            split_bf16(p1, H.h[1], L.h[1]);
            pH[nt][0] = H.u; pL[nt][0] = L.u;
            split_bf16(p2, H.h[0], L.h[0]);
            split_bf16(p3, H.h[1], L.h[1]);
            pH[nt][1] = H.u; pL[nt][1] = L.u;
        }
        ps0 += __shfl_xor_sync(0xffffffffu, ps0, 1);
        ps0 += __shfl_xor_sync(0xffffffffu, ps0, 2);
        ps1 += __shfl_xor_sync(0xffffffffu, ps1, 1);
        ps1 += __shfl_xor_sync(0xffffffffu, ps1, 2);
        l0 = l0 * al0 + ps0;
        l1 = l1 * al1 + ps1;

#pragma unroll
        for (int dt = 0; dt < 8; dt++) {
            oacc[dt][0] *= al0; oacc[dt][1] *= al0;
            oacc[dt][2] *= al1; oacc[dt][3] *= al1;
        }

        // ---- PV (3-pass), B from Vt[d][s] ----
#pragma unroll
        for (int ks = 0; ks < 4; ks++) {
            uint32_t aH[4] = { pH[2 * ks][0], pH[2 * ks][1], pH[2 * ks + 1][0], pH[2 * ks + 1][1] };
            uint32_t aL[4] = { pL[2 * ks][0], pL[2 * ks][1], pL[2 * ks + 1][0], pL[2 * ks + 1][1] };
            uint32_t vh[8][2], vl[8][2];
#pragma unroll
            for (int dp = 0; dp < 4; dp++) {
                int row = dp * 16 + (lane & 15);
                uint32_t sw = sw128((uint32_t)(row * 128 + ks * 32 + ((lane >> 4) << 4)));
                uint32_t t[4];
                ldmx4(t, sb + AVH + sw);
                vh[dp * 2][0] = t[0]; vh[dp * 2][1] = t[2];
                vh[dp * 2 + 1][0] = t[1]; vh[dp * 2 + 1][1] = t[3];
                ldmx4(t, sb + AVL + sw);
                vl[dp * 2][0] = t[0]; vl[dp * 2][1] = t[2];
                vl[dp * 2 + 1][0] = t[1]; vl[dp * 2 + 1][1] = t[3];
            }
#pragma unroll
            for (int dt = 0; dt < 8; dt++) {
                mma_bf16(oacc[dt], aH, vh[dt]);
                mma_bf16(oacc[dt], aL, vh[dt]);
                mma_bf16(oacc[dt], aH, vl[dt]);
            }
        }
    }

    // ---- epilogue: /l, split to bf16 hi/lo, store ----
    float inv0 = 1.0f / l0, inv1 = 1.0f / l1;
#pragma unroll
    for (int dt = 0; dt < 8; dt++) {
        int cg = dt * 8 + cq;
        size_t off0 = (seq0 + gr0) * EMB + hoff + cg;
        size_t off1 = (seq0 + gr0 + 8) * EMB + hoff + cg;
        BF2 H, L;
        split_bf16(oacc[dt][0] * inv0, H.h[0], L.h[0]);
        split_bf16(oacc[dt][1] * inv0, H.h[1], L.h[1]);
        *(uint32_t*)(Oh + off0) = H.u;
        *(uint32_t*)(Ol + off0) = L.u;
        split_bf16(oacc[dt][2] * inv1, H.h[0], L.h[0]);
        split_bf16(oacc[dt][3] * inv1, H.h[1], L.h[1]);
        *(uint32_t*)(Oh + off1) = H.u;
        *(uint32_t*)(Ol + off1) = L.u;
    }
}

// ---------------- orchestration ----------------------------------------------
extern "C" void kernel_launch(void* const* d_in, const int* in_sizes, int n_in,
                              void* d_out, int out_size) {
    (void)in_sizes; (void)n_in; (void)out_size;
    const float* x    = (const float*)d_in[0];
    const float* Wq_w = (const float*)d_in[1];
    const float* Wq_b = (const float*)d_in[2];
    const float* Wk_w = (const float*)d_in[3];
    const float* Wk_b = (const float*)d_in[4];
    const float* Wv_w = (const float*)d_in[5];
    const float* Wv_b = (const float*)d_in[6];
    const float* Wo_w = (const float*)d_in[7];
    const float* Wo_b = (const float*)d_in[8];
    const float* l1_w = (const float*)d_in[9];
    const float* l1_b = (const float*)d_in[10];
    const float* l2_w = (const float*)d_in[11];
    const float* l2_b = (const float*)d_in[12];
    const float* n1s  = (const float*)d_in[13];
    const float* n1b  = (const float*)d_in[14];
    const float* n2s  = (const float*)d_in[15];
    const float* n2b  = (const float*)d_in[16];
    float* out = (float*)d_out;

    float *q, *k, *v, *x1, *rs, *rq, *var;
    cudaGetSymbolAddress((void**)&q,   g_q);
    cudaGetSymbolAddress((void**)&k,   g_k);
    cudaGetSymbolAddress((void**)&v,   g_v);
    cudaGetSymbolAddress((void**)&x1,  g_x1);
    cudaGetSymbolAddress((void**)&rs,  g_rowsum);
    cudaGetSymbolAddress((void**)&rq,  g_rowsq);
    cudaGetSymbolAddress((void**)&var, g_var);

    __nv_bfloat16 *h_hi, *h_lo, *ctx_hi, *ctx_lo, *ff_hi, *ff_lo;
    __nv_bfloat16 *wq_hi, *wq_lo, *wk_hi, *wk_lo, *wv_hi, *wv_lo, *wo_hi, *wo_lo;
    __nv_bfloat16 *l1_hi, *l1_lo, *l2_hi, *l2_lo;
    cudaGetSymbolAddress((void**)&h_hi,  g_h_hi);
    cudaGetSymbolAddress((void**)&h_lo,  g_h_lo);
    cudaGetSymbolAddress((void**)&ctx_hi, g_ctx_hi);
    cudaGetSymbolAddress((void**)&ctx_lo, g_ctx_lo);
    cudaGetSymbolAddress((void**)&ff_hi, g_ff_hi);
    cudaGetSymbolAddress((void**)&ff_lo, g_ff_lo);
    cudaGetSymbolAddress((void**)&wq_hi, g_wq_hi);
    cudaGetSymbolAddress((void**)&wq_lo, g_wq_lo);
    cudaGetSymbolAddress((void**)&wk_hi, g_wk_hi);
    cudaGetSymbolAddress((void**)&wk_lo, g_wk_lo);
    cudaGetSymbolAddress((void**)&wv_hi, g_wv_hi);
    cudaGetSymbolAddress((void**)&wv_lo, g_wv_lo);
    cudaGetSymbolAddress((void**)&wo_hi, g_wo_hi);
    cudaGetSymbolAddress((void**)&wo_lo, g_wo_lo);
    cudaGetSymbolAddress((void**)&l1_hi, g_l1_hi);
    cudaGetSymbolAddress((void**)&l1_lo, g_l1_lo);
    cudaGetSymbolAddress((void**)&l2_hi, g_l2_hi);
    cudaGetSymbolAddress((void**)&l2_lo, g_l2_lo);

    cudaFuncSetAttribute((const void*)attn_tc_kernel,
                         cudaFuncAttributeMaxDynamicSharedMemorySize, ATT_SMEM);
    cudaFuncSetAttribute((const void*)mmagemm_kernel<MODE_BIAS>,
                         cudaFuncAttributeMaxDynamicSharedMemorySize, MM_SMEM);
    cudaFuncSetAttribute((const void*)mmagemm_kernel<MODE_BIAS_RES>,
                         cudaFuncAttributeMaxDynamicSharedMemorySize, MM_SMEM);
    cudaFuncSetAttribute((const void*)mmagemm_kernel<MODE_GELU_SPLIT>,
                         cudaFuncAttributeMaxDynamicSharedMemorySize, MM_SMEM);

    const int LN_BLOCKS = (N_TOK * EMB / 4) / 256;
    dim3 blk(256);
    dim3 gP(EMB / 128, N_TOK / 128);
    dim3 gF(DFF / 128, N_TOK / 128);

    // weight splits
    split_kernel<<<(EMB * EMB / 4) / 256, 256>>>(Wq_w, wq_hi, wq_lo, EMB * EMB / 4);
    split_kernel<<<(EMB * EMB / 4) / 256, 256>>>(Wk_w, wk_hi, wk_lo, EMB * EMB / 4);
    split_kernel<<<(EMB * EMB / 4) / 256, 256>>>(Wv_w, wv_hi, wv_lo, EMB * EMB / 4);
    split_kernel<<<(EMB * EMB / 4) / 256, 256>>>(Wo_w, wo_hi, wo_lo, EMB * EMB / 4);
    split_kernel<<<(DFF * EMB / 4) / 256, 256>>>(l1_w, l1_hi, l1_lo, DFF * EMB / 4);
    split_kernel<<<(EMB * DFF / 4) / 256, 256>>>(l2_w, l2_hi, l2_lo, EMB * DFF / 4);

    // LN1 -> h hi/lo
    rowstats_kernel<<<N_TOK, 256>>>(x, rs, rq);
    finalize_var_kernel<<<1, 256>>>(rs, rq, var);
    ln_apply_split_kernel<<<LN_BLOCKS, 256>>>(x, rs, var, n1s, n1b, h_hi, h_lo);

    // QKV projections
    mmagemm_kernel<MODE_BIAS><<<gP, blk, MM_SMEM>>>(
        h_hi, h_lo, wq_hi, wq_lo, Wq_b, nullptr, q, nullptr, nullptr, EMB, EMB);
    mmagemm_kernel<MODE_BIAS><<<gP, blk, MM_SMEM>>>(
        h_hi, h_lo, wk_hi, wk_lo, Wk_b, nullptr, k, nullptr, nullptr, EMB, EMB);
    mmagemm_kernel<MODE_BIAS><<<gP, blk, MM_SMEM>>>(
        h_hi, h_lo, wv_hi, wv_lo, Wv_b, nullptr, v, nullptr, nullptr, EMB, EMB);

    // tensor-core attention -> ctx hi/lo
    attn_tc_kernel<<<dim3(TSEQ / 64, 64), 128, ATT_SMEM>>>(q, k, v, ctx_hi, ctx_lo);

    // output projection + residual
    mmagemm_kernel<MODE_BIAS_RES><<<gP, blk, MM_SMEM>>>(
        ctx_hi, ctx_lo, wo_hi, wo_lo, Wo_b, x, x1, nullptr, nullptr, EMB, EMB);

    // LN2 -> h hi/lo
    rowstats_kernel<<<N_TOK, 256>>>(x1, rs, rq);
    finalize_var_kernel<<<1, 256>>>(rs, rq, var);
    ln_apply_split_kernel<<<LN_BLOCKS, 256>>>(x1, rs, var, n2s, n2b, h_hi, h_lo);

    // FFN
    mmagemm_kernel<MODE_GELU_SPLIT><<<gF, blk, MM_SMEM>>>(
        h_hi, h_lo, l1_hi, l1_lo, l1_b, nullptr, nullptr, ff_hi, ff_lo, DFF, EMB);
    mmagemm_kernel<MODE_BIAS_RES><<<gP, blk, MM_SMEM>>>(
        ff_hi, ff_lo, l2_hi, l2_lo, l2_b, x1, out, nullptr, nullptr, EMB, DFF);
}

// round 9
// speedup vs baseline: 3.4758x; 1.1090x over previous
#include <cuda_runtime.h>
#include <cuda_bf16.h>
#include <math.h>
#include <stdint.h>

#define N_TOK 8192
#define EMB   1024
#define DFF   4096
#define TSEQ  2048

// ---------------- scratch (device globals; no allocations allowed) ----------
__device__ float g_x1 [N_TOK * EMB];
__device__ float g_rowsum[N_TOK];
__device__ float g_rowsq [N_TOK];
__device__ float g_var[2];

__device__ __nv_bfloat16 g_h_hi [N_TOK * EMB];
__device__ __nv_bfloat16 g_h_lo [N_TOK * EMB];
__device__ __nv_bfloat16 g_qh[N_TOK * EMB], g_ql[N_TOK * EMB];
__device__ __nv_bfloat16 g_kh[N_TOK * EMB], g_kl[N_TOK * EMB];
__device__ __nv_bfloat16 g_vh[N_TOK * EMB], g_vl[N_TOK * EMB];
__device__ __nv_bfloat16 g_ctx_hi[N_TOK * EMB];
__device__ __nv_bfloat16 g_ctx_lo[N_TOK * EMB];
__device__ __nv_bfloat16 g_ff_hi [N_TOK * DFF];
__device__ __nv_bfloat16 g_ff_lo [N_TOK * DFF];
__device__ __nv_bfloat16 g_wq_hi[EMB * EMB], g_wq_lo[EMB * EMB];
__device__ __nv_bfloat16 g_wk_hi[EMB * EMB], g_wk_lo[EMB * EMB];
__device__ __nv_bfloat16 g_wv_hi[EMB * EMB], g_wv_lo[EMB * EMB];
__device__ __nv_bfloat16 g_wo_hi[EMB * EMB], g_wo_lo[EMB * EMB];
__device__ __nv_bfloat16 g_l1_hi[DFF * EMB], g_l1_lo[DFF * EMB];
__device__ __nv_bfloat16 g_l2_hi[EMB * DFF], g_l2_lo[EMB * DFF];

union BF4 { __nv_bfloat16 h[4]; uint2 u; };
union BF2 { __nv_bfloat16 h[2]; uint32_t u; };

__device__ __forceinline__ void split_bf16(float v, __nv_bfloat16& hi, __nv_bfloat16& lo) {
    hi = __float2bfloat16(v);
    lo = __float2bfloat16(v - __bfloat162float(hi));
}
__device__ __forceinline__ uint32_t smem_u32(const void* p) {
    uint32_t a;
    asm("{ .reg .u64 t; cvta.to.shared.u64 t, %1; cvt.u32.u64 %0, t; }" : "=r"(a) : "l"(p));
    return a;
}
__device__ __forceinline__ void cp16(uint32_t dst, const void* src) {
    asm volatile("cp.async.cg.shared.global [%0], [%1], 16;" :: "r"(dst), "l"(src) : "memory");
}
__device__ __forceinline__ void cp_commit() {
    asm volatile("cp.async.commit_group;" ::: "memory");
}
template <int N>
__device__ __forceinline__ void cp_wait() {
    asm volatile("cp.async.wait_group %0;" :: "n"(N) : "memory");
}
__device__ __forceinline__ void ldmx4(uint32_t* r, uint32_t addr) {
    asm volatile("ldmatrix.sync.aligned.m8n8.x4.shared.b16 {%0,%1,%2,%3}, [%4];"
                 : "=r"(r[0]), "=r"(r[1]), "=r"(r[2]), "=r"(r[3]) : "r"(addr));
}
__device__ __forceinline__ void ldmx4t(uint32_t* r, uint32_t addr) {
    asm volatile("ldmatrix.sync.aligned.m8n8.x4.trans.shared.b16 {%0,%1,%2,%3}, [%4];"
                 : "=r"(r[0]), "=r"(r[1]), "=r"(r[2]), "=r"(r[3]) : "r"(addr));
}
__device__ __forceinline__ void mma_bf16(float* c, const uint32_t* a, const uint32_t* b) {
    asm volatile("mma.sync.aligned.m16n8k16.row.col.f32.bf16.bf16.f32 "
                 "{%0,%1,%2,%3}, {%4,%5,%6,%7}, {%8,%9}, {%0,%1,%2,%3};"
                 : "+f"(c[0]), "+f"(c[1]), "+f"(c[2]), "+f"(c[3])
                 : "r"(a[0]), "r"(a[1]), "r"(a[2]), "r"(a[3]), "r"(b[0]), "r"(b[1]));
}
__device__ __forceinline__ uint32_t sw128(uint32_t o) { return o ^ ((o >> 3) & 0x70); }

// ---------------- split kernels ----------------------------------------------
__global__ void split_kernel(const float* __restrict__ x,
                             __nv_bfloat16* __restrict__ hi,
                             __nv_bfloat16* __restrict__ lo, int n4) {
    int i = blockIdx.x * blockDim.x + threadIdx.x;
    if (i >= n4) return;
    float4 v = ((const float4*)x)[i];
    BF4 H, L;
#pragma unroll
    for (int j = 0; j < 4; j++) split_bf16((&v.x)[j], H.h[j], L.h[j]);
    ((uint2*)hi)[i] = H.u;
    ((uint2*)lo)[i] = L.u;
}

// ---------------- LN pieces ---------------------------------------------------
__global__ void rowstats_kernel(const float* __restrict__ x,
                                float* __restrict__ rowsum,
                                float* __restrict__ rowsq) {
    int row = blockIdx.x, tid = threadIdx.x;
    float4 v = *(const float4*)(x + (size_t)row * EMB + tid * 4);
    float s = v.x + v.y + v.z + v.w;
    float q = v.x * v.x + v.y * v.y + v.z * v.z + v.w * v.w;
#pragma unroll
    for (int o = 16; o > 0; o >>= 1) {
        s += __shfl_down_sync(0xffffffffu, s, o);
        q += __shfl_down_sync(0xffffffffu, q, o);
    }
    __shared__ float ss[8], qs[8];
    int w = tid >> 5, lane = tid & 31;
    if (lane == 0) { ss[w] = s; qs[w] = q; }
    __syncthreads();
    if (tid == 0) {
        float S = 0.f, Q = 0.f;
#pragma unroll
        for (int i = 0; i < 8; i++) { S += ss[i]; Q += qs[i]; }
        rowsum[row] = S; rowsq[row] = Q;
    }
}

__global__ void finalize_var_kernel(const float* __restrict__ rowsum,
                                    const float* __restrict__ rowsq,
                                    float* __restrict__ varout) {
    int tid = threadIdx.x;
    double s = 0.0, q = 0.0;
    for (int i = tid; i < N_TOK; i += 256) { s += (double)rowsum[i]; q += (double)rowsq[i]; }
#pragma unroll
    for (int o = 16; o > 0; o >>= 1) {
        s += __shfl_down_sync(0xffffffffu, s, o);
        q += __shfl_down_sync(0xffffffffu, q, o);
    }
    __shared__ double sd[8], qd[8];
    int w = tid >> 5, lane = tid & 31;
    if (lane == 0) { sd[w] = s; qd[w] = q; }
    __syncthreads();
    if (tid == 0) {
        double S = 0.0, Q = 0.0;
        for (int i = 0; i < 8; i++) { S += sd[i]; Q += qd[i]; }
        double M = (double)N_TOK * (double)EMB;
        double mean = S / M;
        varout[0] = (float)(Q / M - mean * mean);
    }
}

__global__ void ln_apply_split_kernel(const float* __restrict__ x,
                                      const float* __restrict__ rowsum,
                                      const float* __restrict__ varp,
                                      const float* __restrict__ scale,
                                      const float* __restrict__ shift,
                                      __nv_bfloat16* __restrict__ hi,
                                      __nv_bfloat16* __restrict__ lo) {
    size_t i4 = (size_t)blockIdx.x * blockDim.x + threadIdx.x;
    size_t off = i4 * 4;
    int row = (int)(off >> 10), col = (int)(off & 1023);
    float invv = 1.0f / varp[0];
    float mean = rowsum[row] * (1.0f / 1024.0f);
    float4 v  = *(const float4*)(x + off);
    float4 sc = *(const float4*)(scale + col);
    float4 sh = *(const float4*)(shift + col);
    float o[4];
    o[0] = ((v.x - mean) * invv + 1e-5f) * sc.x + sh.x;
    o[1] = ((v.y - mean) * invv + 1e-5f) * sc.y + sh.y;
    o[2] = ((v.z - mean) * invv + 1e-5f) * sc.z + sh.z;
    o[3] = ((v.w - mean) * invv + 1e-5f) * sc.w + sh.w;
    BF4 H, L;
#pragma unroll
    for (int j = 0; j < 4; j++) split_bf16(o[j], H.h[j], L.h[j]);
    ((uint2*)hi)[i4] = H.u;
    ((uint2*)lo)[i4] = L.u;
}

// ---------------- mma.sync GEMM: C[M,N] = A[M,K]*B[N,K]^T --------------------
enum { MODE_BIAS = 0, MODE_BIAS_RES = 1, MODE_GELU_SPLIT = 2, MODE_BIAS_SPLIT = 3 };

#define STAGE_BYTES 65536
#define MM_SMEM (2 * STAGE_BYTES)

template <int MODE>
__global__ __launch_bounds__(256)
void mmagemm_kernel(const __nv_bfloat16* __restrict__ Ah, const __nv_bfloat16* __restrict__ Al,
                    const __nv_bfloat16* __restrict__ Bh, const __nv_bfloat16* __restrict__ Bl,
                    const float* __restrict__ bias, const float* __restrict__ res,
                    float* __restrict__ C,
                    __nv_bfloat16* __restrict__ Oh, __nv_bfloat16* __restrict__ Ol,
                    int N, int K, float oscale) {
    extern __shared__ char smg[];
    const uint32_t sb = smem_u32(smg);
    const int tid = threadIdx.x, wid = tid >> 5, lane = tid & 31;
    const int warpM = wid >> 2;
    const int warpN = wid & 3;
    const size_t rowA0 = (size_t)blockIdx.y * 128;
    const size_t rowB0 = (size_t)blockIdx.x * 128;

    const int gi = tid & 7;
    const int r0 = tid >> 3;
    uint32_t so[4];
#pragma unroll
    for (int i = 0; i < 4; i++) {
        uint32_t o = (uint32_t)((r0 + 32 * i) * 128 + gi * 16);
        so[i] = sw128(o);
    }

    auto cpchunk = [&](int k0, int st) {
        uint32_t base = sb + st * STAGE_BYTES;
#pragma unroll
        for (int i = 0; i < 4; i++) {
            int r = r0 + 32 * i;
            size_t oa = (rowA0 + r) * (size_t)K + k0 + gi * 8;
            size_t ob = (rowB0 + r) * (size_t)K + k0 + gi * 8;
            cp16(base +         so[i], Ah + oa);
            cp16(base + 16384 + so[i], Al + oa);
            cp16(base + 32768 + so[i], Bh + ob);
            cp16(base + 49152 + so[i], Bl + ob);
        }
        cp_commit();
    };

    float acc[4][4][4];
#pragma unroll
    for (int mi = 0; mi < 4; mi++)
#pragma unroll
        for (int ni = 0; ni < 4; ni++)
#pragma unroll
            for (int j = 0; j < 4; j++) acc[mi][ni][j] = 0.0f;

    const int NC = K / 64;
    cpchunk(0, 0);
    for (int c = 0; c < NC; ++c) {
        if (c + 1 < NC) { cpchunk((c + 1) * 64, (c + 1) & 1); cp_wait<1>(); }
        else            { cp_wait<0>(); }
        __syncthreads();

        uint32_t base = sb + (c & 1) * STAGE_BYTES;
#pragma unroll
        for (int ks = 0; ks < 4; ks++) {
            uint32_t ah[4][4], al[4][4], bh[4][2], bl[4][2];
#pragma unroll
            for (int mi = 0; mi < 4; mi++) {
                int row = warpM * 64 + mi * 16 + (lane & 15);
                uint32_t sw = sw128((uint32_t)(row * 128 + ks * 32 + ((lane >> 4) << 4)));
                ldmx4(ah[mi], base + sw);
                ldmx4(al[mi], base + 16384 + sw);
            }
#pragma unroll
            for (int np = 0; np < 2; np++) {
                int row = warpN * 32 + np * 16 + (lane & 15);
                uint32_t sw = sw128((uint32_t)(row * 128 + ks * 32 + ((lane >> 4) << 4)));
                uint32_t t[4];
                ldmx4(t, base + 32768 + sw);
                bh[np * 2][0] = t[0]; bh[np * 2][1] = t[2];
                bh[np * 2 + 1][0] = t[1]; bh[np * 2 + 1][1] = t[3];
                ldmx4(t, base + 49152 + sw);
                bl[np * 2][0] = t[0]; bl[np * 2][1] = t[2];
                bl[np * 2 + 1][0] = t[1]; bl[np * 2 + 1][1] = t[3];
            }
#pragma unroll
            for (int mi = 0; mi < 4; mi++)
#pragma unroll
                for (int ni = 0; ni < 4; ni++) {
                    mma_bf16(acc[mi][ni], ah[mi], bh[ni]);
                    mma_bf16(acc[mi][ni], al[mi], bh[ni]);
                    mma_bf16(acc[mi][ni], ah[mi], bl[ni]);
                }
        }
        __syncthreads();
    }

    const int rbase = (int)rowA0 + warpM * 64 + (lane >> 2);
    const int cbase = (int)rowB0 + warpN * 32 + (lane & 3) * 2;
#pragma unroll
    for (int mi = 0; mi < 4; mi++) {
#pragma unroll
        for (int ni = 0; ni < 4; ni++) {
            int cg = cbase + ni * 8;
            float2 bv = *(const float2*)(bias + cg);
#pragma unroll
            for (int h = 0; h < 2; h++) {
                int rg = rbase + mi * 16 + h * 8;
                float o0 = acc[mi][ni][2 * h]     + bv.x;
                float o1 = acc[mi][ni][2 * h + 1] + bv.y;
                size_t off = (size_t)rg * N + cg;
                if (MODE == MODE_BIAS_RES) {
                    float2 r = *(const float2*)(res + off);
                    o0 += r.x; o1 += r.y;
                    float2 w; w.x = o0; w.y = o1;
                    *(float2*)(C + off) = w;
                } else if (MODE == MODE_GELU_SPLIT) {
                    float g0 = 0.5f * o0 * (1.0f + erff(o0 * 0.70710678118654752f));
                    float g1 = 0.5f * o1 * (1.0f + erff(o1 * 0.70710678118654752f));
                    BF2 H, L;
                    split_bf16(g0, H.h[0], L.h[0]);
                    split_bf16(g1, H.h[1], L.h[1]);
                    *(uint32_t*)(Oh + off) = H.u;
                    *(uint32_t*)(Ol + off) = L.u;
                } else if (MODE == MODE_BIAS_SPLIT) {
                    BF2 H, L;
                    split_bf16(o0 * oscale, H.h[0], L.h[0]);
                    split_bf16(o1 * oscale, H.h[1], L.h[1]);
                    *(uint32_t*)(Oh + off) = H.u;
                    *(uint32_t*)(Ol + off) = L.u;
                } else {
                    float2 w; w.x = o0; w.y = o1;
                    *(float2*)(C + off) = w;
                }
            }
        }
    }
}

// ---------------- tensor-core causal flash attention (pre-split inputs) -----
// smem: Qh 0, Ql 8192; stages at 16384 + st*32768: Kh+0, Kl+8192, Vh+16384, Vl+24576
#define ATT_STAGE0 16384
#define ATT_STSZ   32768
#define ATT_SMEM   (ATT_STAGE0 + 2 * ATT_STSZ)

__global__ __launch_bounds__(128)
void attn_tc_kernel(const __nv_bfloat16* __restrict__ Qh_, const __nv_bfloat16* __restrict__ Ql_,
                    const __nv_bfloat16* __restrict__ Kh_, const __nv_bfloat16* __restrict__ Kl_,
                    const __nv_bfloat16* __restrict__ Vh_, const __nv_bfloat16* __restrict__ Vl_,
                    __nv_bfloat16* __restrict__ Oh, __nv_bfloat16* __restrict__ Ol) {
    extern __shared__ char smg[];
    const uint32_t sb = smem_u32(smg);
    const int qt   = (TSEQ / 64 - 1) - blockIdx.x;  // heavy blocks first
    const int bh   = blockIdx.y;
    const int bb   = bh >> 4;
    const int head = bh & 15;
    const int tid  = threadIdx.x;
    const int wid  = tid >> 5;
    const int lane = tid & 31;
    const size_t hoff = (size_t)head * 64;
    const size_t seq0 = (size_t)bb * TSEQ;

    const int gi = tid & 7;      // 16B group within 128B row
    const int r4 = tid >> 3;     // 0..15

    // Q tile (already scaled by 1/8 at projection time)
    {
#pragma unroll
        for (int i = 0; i < 4; i++) {
            int r = r4 + 16 * i;
            size_t g = (seq0 + qt * 64 + r) * EMB + hoff + gi * 8;
            uint32_t sw = sw128((uint32_t)(r * 128 + gi * 16));
            cp16(sb + sw, Qh_ + g);
            cp16(sb + 8192 + sw, Ql_ + g);
        }
        cp_commit();
    }
    auto cpKV = [&](int kt, int st) {
        uint32_t base = sb + ATT_STAGE0 + st * ATT_STSZ;
#pragma unroll
        for (int i = 0; i < 4; i++) {
            int r = r4 + 16 * i;
            size_t g = (seq0 + kt * 64 + r) * EMB + hoff + gi * 8;
            uint32_t sw = sw128((uint32_t)(r * 128 + gi * 16));
            cp16(base + sw, Kh_ + g);
            cp16(base + 8192 + sw, Kl_ + g);
            cp16(base + 16384 + sw, Vh_ + g);
            cp16(base + 24576 + sw, Vl_ + g);
        }
        cp_commit();
    };
    cpKV(0, 0);
    cp_wait<0>();
    __syncthreads();

    // Q fragments (A operand), per warp rows wid*16..
    uint32_t qh[4][4], ql[4][4];
#pragma unroll
    for (int ks = 0; ks < 4; ks++) {
        int row = wid * 16 + (lane & 15);
        uint32_t sw = sw128((uint32_t)(row * 128 + ks * 32 + (lane & 16)));
        ldmx4(qh[ks], sb + sw);
        ldmx4(ql[ks], sb + 8192 + sw);
    }

    float oacc[8][4];
#pragma unroll
    for (int i = 0; i < 8; i++)
#pragma unroll
        for (int j = 0; j < 4; j++) oacc[i][j] = 0.0f;
    float m0 = -3.0e38f, m1 = -3.0e38f, l0 = 0.0f, l1 = 0.0f;

    const int gr0 = qt * 64 + wid * 16 + (lane >> 2);
    const int cq  = (lane & 3) * 2;

    for (int kt = 0; kt <= qt; ++kt) {
        if (kt > 0) { cp_wait<0>(); __syncthreads(); }
        if (kt < qt) cpKV(kt + 1, (kt + 1) & 1);
        uint32_t base = sb + ATT_STAGE0 + (kt & 1) * ATT_STSZ;

        // ---- S = Q K^T (3-pass) ----
        float sacc[8][4];
#pragma unroll
        for (int i = 0; i < 8; i++)
#pragma unroll
            for (int j = 0; j < 4; j++) sacc[i][j] = 0.0f;
#pragma unroll
        for (int ks = 0; ks < 4; ks++) {
            uint32_t kh[8][2], kl[8][2];
#pragma unroll
            for (int kp = 0; kp < 4; kp++) {
                int row = kp * 16 + (lane & 15);
                uint32_t sw = sw128((uint32_t)(row * 128 + ks * 32 + (lane & 16)));
                uint32_t t[4];
                ldmx4(t, base + sw);
                kh[kp * 2][0] = t[0]; kh[kp * 2][1] = t[2];
                kh[kp * 2 + 1][0] = t[1]; kh[kp * 2 + 1][1] = t[3];
                ldmx4(t, base + 8192 + sw);
                kl[kp * 2][0] = t[0]; kl[kp * 2][1] = t[2];
                kl[kp * 2 + 1][0] = t[1]; kl[kp * 2 + 1][1] = t[3];
            }
#pragma unroll
            for (int nt = 0; nt < 8; nt++) {
                mma_bf16(sacc[nt], qh[ks], kh[nt]);
                mma_bf16(sacc[nt], ql[ks], kh[nt]);
                mma_bf16(sacc[nt], qh[ks], kl[nt]);
            }
        }

        if (kt == qt) {
#pragma unroll
            for (int nt = 0; nt < 8; nt++) {
                int c0 = kt * 64 + nt * 8 + cq;
                if (c0 > gr0)     sacc[nt][0] = -1e30f;
                if (c0 + 1 > gr0) sacc[nt][1] = -1e30f;
                if (c0 > gr0 + 8)     sacc[nt][2] = -1e30f;
                if (c0 + 1 > gr0 + 8) sacc[nt][3] = -1e30f;
            }
        }

        // ---- online softmax ----
        float t0 = -3.0e38f, t1 = -3.0e38f;
#pragma unroll
        for (int nt = 0; nt < 8; nt++) {
            t0 = fmaxf(t0, fmaxf(sacc[nt][0], sacc[nt][1]));
            t1 = fmaxf(t1, fmaxf(sacc[nt][2], sacc[nt][3]));
        }
        t0 = fmaxf(t0, __shfl_xor_sync(0xffffffffu, t0, 1));
        t0 = fmaxf(t0, __shfl_xor_sync(0xffffffffu, t0, 2));
        t1 = fmaxf(t1, __shfl_xor_sync(0xffffffffu, t1, 1));
        t1 = fmaxf(t1, __shfl_xor_sync(0xffffffffu, t1, 2));
        float mn0 = fmaxf(m0, t0), mn1 = fmaxf(m1, t1);
        float al0 = __expf(m0 - mn0), al1 = __expf(m1 - mn1);
        m0 = mn0; m1 = mn1;

        uint32_t pH[8][2], pL[8][2];
        float ps0 = 0.0f, ps1 = 0.0f;
#pragma unroll
        for (int nt = 0; nt < 8; nt++) {
            float p0 = __expf(sacc[nt][0] - mn0);
            float p1 = __expf(sacc[nt][1] - mn0);
            float p2 = __expf(sacc[nt][2] - mn1);
            float p3 = __expf(sacc[nt][3] - mn1);
            ps0 += p0 + p1; ps1 += p2 + p3;
            BF2 H, L;
            split_bf16(p0, H.h[0], L.h[0]);
            split_bf16(p1, H.h[1], L.h[1]);
            pH[nt][0] = H.u; pL[nt][0] = L.u;
            split_bf16(p2, H.h[0], L.h[0]);
            split_bf16(p3, H.h[1], L.h[1]);
            pH[nt][1] = H.u; pL[nt][1] = L.u;
        }
        ps0 += __shfl_xor_sync(0xffffffffu, ps0, 1);
        ps0 += __shfl_xor_sync(0xffffffffu, ps0, 2);
        ps1 += __shfl_xor_sync(0xffffffffu, ps1, 1);
        ps1 += __shfl_xor_sync(0xffffffffu, ps1, 2);
        l0 = l0 * al0 + ps0;
        l1 = l1 * al1 + ps1;

#pragma unroll
        for (int dt = 0; dt < 8; dt++) {
            oacc[dt][0] *= al0; oacc[dt][1] *= al0;
            oacc[dt][2] *= al1; oacc[dt][3] *= al1;
        }

        // ---- PV (3-pass), B via ldmatrix.trans on row-major V[s][d] ----
#pragma unroll
        for (int ks = 0; ks < 4; ks++) {
            uint32_t aH[4] = { pH[2 * ks][0], pH[2 * ks][1], pH[2 * ks + 1][0], pH[2 * ks + 1][1] };
            uint32_t aL[4] = { pL[2 * ks][0], pL[2 * ks][1], pL[2 * ks + 1][0], pL[2 * ks + 1][1] };
#pragma unroll
            for (int dp = 0; dp < 4; dp++) {
                uint32_t sw = sw128((uint32_t)((ks * 16 + (lane & 15)) * 128 + dp * 32 + (lane & 16)));
                uint32_t th[4], tl[4];
                ldmx4t(th, base + 16384 + sw);
                ldmx4t(tl, base + 24576 + sw);
                uint32_t b0h[2] = { th[0], th[1] }, b1h[2] = { th[2], th[3] };
                uint32_t b0l[2] = { tl[0], tl[1] }, b1l[2] = { tl[2], tl[3] };
                mma_bf16(oacc[2 * dp],     aH, b0h);
                mma_bf16(oacc[2 * dp],     aL, b0h);
                mma_bf16(oacc[2 * dp],     aH, b0l);
                mma_bf16(oacc[2 * dp + 1], aH, b1h);
                mma_bf16(oacc[2 * dp + 1], aL, b1h);
                mma_bf16(oacc[2 * dp + 1], aH, b1l);
            }
        }
    }

    // ---- epilogue ----
    float inv0 = 1.0f / l0, inv1 = 1.0f / l1;
#pragma unroll
    for (int dt = 0; dt < 8; dt++) {
        int cg = dt * 8 + cq;
        size_t off0 = (seq0 + gr0) * EMB + hoff + cg;
        size_t off1 = (seq0 + gr0 + 8) * EMB + hoff + cg;
        BF2 H, L;
        split_bf16(oacc[dt][0] * inv0, H.h[0], L.h[0]);
        split_bf16(oacc[dt][1] * inv0, H.h[1], L.h[1]);
        *(uint32_t*)(Oh + off0) = H.u;
        *(uint32_t*)(Ol + off0) = L.u;
        split_bf16(oacc[dt][2] * inv1, H.h[0], L.h[0]);
        split_bf16(oacc[dt][3] * inv1, H.h[1], L.h[1]);
        *(uint32_t*)(Oh + off1) = H.u;
        *(uint32_t*)(Ol + off1) = L.u;
    }
}

// ---------------- orchestration ----------------------------------------------
extern "C" void kernel_launch(void* const* d_in, const int* in_sizes, int n_in,
                              void* d_out, int out_size) {
    (void)in_sizes; (void)n_in; (void)out_size;
    const float* x    = (const float*)d_in[0];
    const float* Wq_w = (const float*)d_in[1];
    const float* Wq_b = (const float*)d_in[2];
    const float* Wk_w = (const float*)d_in[3];
    const float* Wk_b = (const float*)d_in[4];
    const float* Wv_w = (const float*)d_in[5];
    const float* Wv_b = (const float*)d_in[6];
    const float* Wo_w = (const float*)d_in[7];
    const float* Wo_b = (const float*)d_in[8];
    const float* l1_w = (const float*)d_in[9];
    const float* l1_b = (const float*)d_in[10];
    const float* l2_w = (const float*)d_in[11];
    const float* l2_b = (const float*)d_in[12];
    const float* n1s  = (const float*)d_in[13];
    const float* n1b  = (const float*)d_in[14];
    const float* n2s  = (const float*)d_in[15];
    const float* n2b  = (const float*)d_in[16];
    float* out = (float*)d_out;

    float *x1, *rs, *rq, *var;
    cudaGetSymbolAddress((void**)&x1,  g_x1);
    cudaGetSymbolAddress((void**)&rs,  g_rowsum);
    cudaGetSymbolAddress((void**)&rq,  g_rowsq);
    cudaGetSymbolAddress((void**)&var, g_var);

    __nv_bfloat16 *h_hi, *h_lo, *ctx_hi, *ctx_lo, *ff_hi, *ff_lo;
    __nv_bfloat16 *qh, *ql, *kh, *kl, *vh, *vl;
    __nv_bfloat16 *wq_hi, *wq_lo, *wk_hi, *wk_lo, *wv_hi, *wv_lo, *wo_hi, *wo_lo;
    __nv_bfloat16 *l1_hi, *l1_lo, *l2_hi, *l2_lo;
    cudaGetSymbolAddress((void**)&h_hi,  g_h_hi);
    cudaGetSymbolAddress((void**)&h_lo,  g_h_lo);
    cudaGetSymbolAddress((void**)&qh, g_qh);
    cudaGetSymbolAddress((void**)&ql, g_ql);
    cudaGetSymbolAddress((void**)&kh, g_kh);
    cudaGetSymbolAddress((void**)&kl, g_kl);
    cudaGetSymbolAddress((void**)&vh, g_vh);
    cudaGetSymbolAddress((void**)&vl, g_vl);
    cudaGetSymbolAddress((void**)&ctx_hi, g_ctx_hi);
    cudaGetSymbolAddress((void**)&ctx_lo, g_ctx_lo);
    cudaGetSymbolAddress((void**)&ff_hi, g_ff_hi);
    cudaGetSymbolAddress((void**)&ff_lo, g_ff_lo);
    cudaGetSymbolAddress((void**)&wq_hi, g_wq_hi);
    cudaGetSymbolAddress((void**)&wq_lo, g_wq_lo);
    cudaGetSymbolAddress((void**)&wk_hi, g_wk_hi);
    cudaGetSymbolAddress((void**)&wk_lo, g_wk_lo);
    cudaGetSymbolAddress((void**)&wv_hi, g_wv_hi);
    cudaGetSymbolAddress((void**)&wv_lo, g_wv_lo);
    cudaGetSymbolAddress((void**)&wo_hi, g_wo_hi);
    cudaGetSymbolAddress((void**)&wo_lo, g_wo_lo);
    cudaGetSymbolAddress((void**)&l1_hi, g_l1_hi);
    cudaGetSymbolAddress((void**)&l1_lo, g_l1_lo);
    cudaGetSymbolAddress((void**)&l2_hi, g_l2_hi);
    cudaGetSymbolAddress((void**)&l2_lo, g_l2_lo);

    cudaFuncSetAttribute((const void*)attn_tc_kernel,
                         cudaFuncAttributeMaxDynamicSharedMemorySize, ATT_SMEM);
    cudaFuncSetAttribute((const void*)mmagemm_kernel<MODE_BIAS_SPLIT>,
                         cudaFuncAttributeMaxDynamicSharedMemorySize, MM_SMEM);
    cudaFuncSetAttribute((const void*)mmagemm_kernel<MODE_BIAS_RES>,
                         cudaFuncAttributeMaxDynamicSharedMemorySize, MM_SMEM);
    cudaFuncSetAttribute((const void*)mmagemm_kernel<MODE_GELU_SPLIT>,
                         cudaFuncAttributeMaxDynamicSharedMemorySize, MM_SMEM);

    const int LN_BLOCKS = (N_TOK * EMB / 4) / 256;
    dim3 blk(256);
    dim3 gP(EMB / 128, N_TOK / 128);
    dim3 gF(DFF / 128, N_TOK / 128);

    // weight splits
    split_kernel<<<(EMB * EMB / 4) / 256, 256>>>(Wq_w, wq_hi, wq_lo, EMB * EMB / 4);
    split_kernel<<<(EMB * EMB / 4) / 256, 256>>>(Wk_w, wk_hi, wk_lo, EMB * EMB / 4);
    split_kernel<<<(EMB * EMB / 4) / 256, 256>>>(Wv_w, wv_hi, wv_lo, EMB * EMB / 4);
    split_kernel<<<(EMB * EMB / 4) / 256, 256>>>(Wo_w, wo_hi, wo_lo, EMB * EMB / 4);
    split_kernel<<<(DFF * EMB / 4) / 256, 256>>>(l1_w, l1_hi, l1_lo, DFF * EMB / 4);
    split_kernel<<<(EMB * DFF / 4) / 256, 256>>>(l2_w, l2_hi, l2_lo, EMB * DFF / 4);

    // LN1 -> h hi/lo
    rowstats_kernel<<<N_TOK, 256>>>(x, rs, rq);
    finalize_var_kernel<<<1, 256>>>(rs, rq, var);
    ln_apply_split_kernel<<<LN_BLOCKS, 256>>>(x, rs, var, n1s, n1b, h_hi, h_lo);

    // QKV projections -> pre-split bf16 hi/lo (Q pre-scaled by 1/8)
    mmagemm_kernel<MODE_BIAS_SPLIT><<<gP, blk, MM_SMEM>>>(
        h_hi, h_lo, wq_hi, wq_lo, Wq_b, nullptr, nullptr, qh, ql, EMB, EMB, 0.125f);
    mmagemm_kernel<MODE_BIAS_SPLIT><<<gP, blk, MM_SMEM>>>(
        h_hi, h_lo, wk_hi, wk_lo, Wk_b, nullptr, nullptr, kh, kl, EMB, EMB, 1.0f);
    mmagemm_kernel<MODE_BIAS_SPLIT><<<gP, blk, MM_SMEM>>>(
        h_hi, h_lo, wv_hi, wv_lo, Wv_b, nullptr, nullptr, vh, vl, EMB, EMB, 1.0f);

    // tensor-core attention -> ctx hi/lo
    attn_tc_kernel<<<dim3(TSEQ / 64, 64), 128, ATT_SMEM>>>(qh, ql, kh, kl, vh, vl,
                                                           ctx_hi, ctx_lo);

    // output projection + residual
    mmagemm_kernel<MODE_BIAS_RES><<<gP, blk, MM_SMEM>>>(
        ctx_hi, ctx_lo, wo_hi, wo_lo, Wo_b, x, x1, nullptr, nullptr, EMB, EMB, 1.0f);

    // LN2 -> h hi/lo
    rowstats_kernel<<<N_TOK, 256>>>(x1, rs, rq);
    finalize_var_kernel<<<1, 256>>>(rs, rq, var);
    ln_apply_split_kernel<<<LN_BLOCKS, 256>>>(x1, rs, var, n2s, n2b, h_hi, h_lo);

    // FFN
    mmagemm_kernel<MODE_GELU_SPLIT><<<gF, blk, MM_SMEM>>>(
        h_hi, h_lo, l1_hi, l1_lo, l1_b, nullptr, nullptr, ff_hi, ff_lo, DFF, EMB, 1.0f);
    mmagemm_kernel<MODE_BIAS_RES><<<gP, blk, MM_SMEM>>>(
        ff_hi, ff_lo, l2_hi, l2_lo, l2_b, x1, out, nullptr, nullptr, EMB, DFF, 1.0f);
}

// round 10
// speedup vs baseline: 3.7466x; 1.0779x over previous
#include <cuda_runtime.h>
#include <cuda_bf16.h>
#include <math.h>
#include <stdint.h>

#define N_TOK 8192
#define EMB   1024
#define DFF   4096
#define TSEQ  2048

// ---------------- scratch (device globals; no allocations allowed) ----------
__device__ float g_x1 [N_TOK * EMB];
__device__ float g_rowsum[N_TOK];
__device__ float g_rowsq [N_TOK];
__device__ float g_var[2];

__device__ __nv_bfloat16 g_h_hi [N_TOK * EMB];
__device__ __nv_bfloat16 g_h_lo [N_TOK * EMB];
__device__ __nv_bfloat16 g_qh[N_TOK * EMB], g_ql[N_TOK * EMB];
__device__ __nv_bfloat16 g_kh[N_TOK * EMB], g_kl[N_TOK * EMB];
__device__ __nv_bfloat16 g_vh[N_TOK * EMB], g_vl[N_TOK * EMB];
__device__ __nv_bfloat16 g_ctx_hi[N_TOK * EMB];
__device__ __nv_bfloat16 g_ctx_lo[N_TOK * EMB];
__device__ __nv_bfloat16 g_ff_hi [N_TOK * DFF];
__device__ __nv_bfloat16 g_ff_lo [N_TOK * DFF];
__device__ __nv_bfloat16 g_wq_hi[EMB * EMB], g_wq_lo[EMB * EMB];
__device__ __nv_bfloat16 g_wk_hi[EMB * EMB], g_wk_lo[EMB * EMB];
__device__ __nv_bfloat16 g_wv_hi[EMB * EMB], g_wv_lo[EMB * EMB];
__device__ __nv_bfloat16 g_wo_hi[EMB * EMB], g_wo_lo[EMB * EMB];
__device__ __nv_bfloat16 g_l1_hi[DFF * EMB], g_l1_lo[DFF * EMB];
__device__ __nv_bfloat16 g_l2_hi[EMB * DFF], g_l2_lo[EMB * DFF];

union BF4 { __nv_bfloat16 h[4]; uint2 u; };
union BF2 { __nv_bfloat16 h[2]; uint32_t u; };

__device__ __forceinline__ void split_bf16(float v, __nv_bfloat16& hi, __nv_bfloat16& lo) {
    hi = __float2bfloat16(v);
    lo = __float2bfloat16(v - __bfloat162float(hi));
}
__device__ __forceinline__ uint32_t smem_u32(const void* p) {
    uint32_t a;
    asm("{ .reg .u64 t; cvta.to.shared.u64 t, %1; cvt.u32.u64 %0, t; }" : "=r"(a) : "l"(p));
    return a;
}
__device__ __forceinline__ void cp16(uint32_t dst, const void* src) {
    asm volatile("cp.async.cg.shared.global [%0], [%1], 16;" :: "r"(dst), "l"(src) : "memory");
}
__device__ __forceinline__ void cp_commit() {
    asm volatile("cp.async.commit_group;" ::: "memory");
}
template <int N>
__device__ __forceinline__ void cp_wait() {
    asm volatile("cp.async.wait_group %0;" :: "n"(N) : "memory");
}
__device__ __forceinline__ void ldmx4(uint32_t* r, uint32_t addr) {
    asm volatile("ldmatrix.sync.aligned.m8n8.x4.shared.b16 {%0,%1,%2,%3}, [%4];"
                 : "=r"(r[0]), "=r"(r[1]), "=r"(r[2]), "=r"(r[3]) : "r"(addr));
}
__device__ __forceinline__ void ldmx4t(uint32_t* r, uint32_t addr) {
    asm volatile("ldmatrix.sync.aligned.m8n8.x4.trans.shared.b16 {%0,%1,%2,%3}, [%4];"
                 : "=r"(r[0]), "=r"(r[1]), "=r"(r[2]), "=r"(r[3]) : "r"(addr));
}
__device__ __forceinline__ void mma_bf16(float* c, const uint32_t* a, const uint32_t* b) {
    asm volatile("mma.sync.aligned.m16n8k16.row.col.f32.bf16.bf16.f32 "
                 "{%0,%1,%2,%3}, {%4,%5,%6,%7}, {%8,%9}, {%0,%1,%2,%3};"
                 : "+f"(c[0]), "+f"(c[1]), "+f"(c[2]), "+f"(c[3])
                 : "r"(a[0]), "r"(a[1]), "r"(a[2]), "r"(a[3]), "r"(b[0]), "r"(b[1]));
}
__device__ __forceinline__ uint32_t sw128(uint32_t o) { return o ^ ((o >> 3) & 0x70); }
__device__ __forceinline__ uint32_t sw64(uint32_t o)  { return o ^ ((o >> 3) & 0x30); }

// ---------------- split kernels ----------------------------------------------
__global__ void split_kernel(const float* __restrict__ x,
                             __nv_bfloat16* __restrict__ hi,
                             __nv_bfloat16* __restrict__ lo, int n4) {
    int i = blockIdx.x * blockDim.x + threadIdx.x;
    if (i >= n4) return;
    float4 v = ((const float4*)x)[i];
    BF4 H, L;
#pragma unroll
    for (int j = 0; j < 4; j++) split_bf16((&v.x)[j], H.h[j], L.h[j]);
    ((uint2*)hi)[i] = H.u;
    ((uint2*)lo)[i] = L.u;
}

// ---------------- LN pieces ---------------------------------------------------
__global__ void rowstats_kernel(const float* __restrict__ x,
                                float* __restrict__ rowsum,
                                float* __restrict__ rowsq) {
    int row = blockIdx.x, tid = threadIdx.x;
    float4 v = *(const float4*)(x + (size_t)row * EMB + tid * 4);
    float s = v.x + v.y + v.z + v.w;
    float q = v.x * v.x + v.y * v.y + v.z * v.z + v.w * v.w;
#pragma unroll
    for (int o = 16; o > 0; o >>= 1) {
        s += __shfl_down_sync(0xffffffffu, s, o);
        q += __shfl_down_sync(0xffffffffu, q, o);
    }
    __shared__ float ss[8], qs[8];
    int w = tid >> 5, lane = tid & 31;
    if (lane == 0) { ss[w] = s; qs[w] = q; }
    __syncthreads();
    if (tid == 0) {
        float S = 0.f, Q = 0.f;
#pragma unroll
        for (int i = 0; i < 8; i++) { S += ss[i]; Q += qs[i]; }
        rowsum[row] = S; rowsq[row] = Q;
    }
}

__global__ void finalize_var_kernel(const float* __restrict__ rowsum,
                                    const float* __restrict__ rowsq,
                                    float* __restrict__ varout) {
    int tid = threadIdx.x;
    double s = 0.0, q = 0.0;
    for (int i = tid; i < N_TOK; i += 256) { s += (double)rowsum[i]; q += (double)rowsq[i]; }
#pragma unroll
    for (int o = 16; o > 0; o >>= 1) {
        s += __shfl_down_sync(0xffffffffu, s, o);
        q += __shfl_down_sync(0xffffffffu, q, o);
    }
    __shared__ double sd[8], qd[8];
    int w = tid >> 5, lane = tid & 31;
    if (lane == 0) { sd[w] = s; qd[w] = q; }
    __syncthreads();
    if (tid == 0) {
        double S = 0.0, Q = 0.0;
        for (int i = 0; i < 8; i++) { S += sd[i]; Q += qd[i]; }
        double M = (double)N_TOK * (double)EMB;
        double mean = S / M;
        varout[0] = (float)(Q / M - mean * mean);
    }
}

__global__ void ln_apply_split_kernel(const float* __restrict__ x,
                                      const float* __restrict__ rowsum,
                                      const float* __restrict__ varp,
                                      const float* __restrict__ scale,
                                      const float* __restrict__ shift,
                                      __nv_bfloat16* __restrict__ hi,
                                      __nv_bfloat16* __restrict__ lo) {
    size_t i4 = (size_t)blockIdx.x * blockDim.x + threadIdx.x;
    size_t off = i4 * 4;
    int row = (int)(off >> 10), col = (int)(off & 1023);
    float invv = 1.0f / varp[0];
    float mean = rowsum[row] * (1.0f / 1024.0f);
    float4 v  = *(const float4*)(x + off);
    float4 sc = *(const float4*)(scale + col);
    float4 sh = *(const float4*)(shift + col);
    float o[4];
    o[0] = ((v.x - mean) * invv + 1e-5f) * sc.x + sh.x;
    o[1] = ((v.y - mean) * invv + 1e-5f) * sc.y + sh.y;
    o[2] = ((v.z - mean) * invv + 1e-5f) * sc.z + sh.z;
    o[3] = ((v.w - mean) * invv + 1e-5f) * sc.w + sh.w;
    BF4 H, L;
#pragma unroll
    for (int j = 0; j < 4; j++) split_bf16(o[j], H.h[j], L.h[j]);
    ((uint2*)hi)[i4] = H.u;
    ((uint2*)lo)[i4] = L.u;
}

// ---------------- mma.sync GEMM body: C[M,N] = A[M,K]*B[N,K]^T ---------------
// BK=32, stage 32KB, double-buffered, 2 CTAs/SM.
enum { MODE_BIAS_RES = 1, MODE_GELU_SPLIT = 2, MODE_BIAS_SPLIT = 3 };

#define STAGE_BYTES 32768
#define MM_SMEM (2 * STAGE_BYTES)

template <int MODE>
__device__ __forceinline__ void gemm_body(
    const __nv_bfloat16* __restrict__ Ah, const __nv_bfloat16* __restrict__ Al,
    const __nv_bfloat16* __restrict__ Bh, const __nv_bfloat16* __restrict__ Bl,
    const float* __restrict__ bias, const float* __restrict__ res,
    float* __restrict__ C, __nv_bfloat16* __restrict__ Oh, __nv_bfloat16* __restrict__ Ol,
    int N, int K, float oscale, int bxx, int byy, char* smg) {
    const uint32_t sb = smem_u32(smg);
    const int tid = threadIdx.x, wid = tid >> 5, lane = tid & 31;
    const int warpM = wid >> 2;
    const int warpN = wid & 3;
    const size_t rowA0 = (size_t)byy * 128;
    const size_t rowB0 = (size_t)bxx * 128;

    // staging: 64B rows (32 bf16); thread -> gi = tid&3 (16B group), r0 = tid>>2 (0..63)
    const int gi = tid & 3;
    const int r0 = tid >> 2;
    uint32_t so[2];
#pragma unroll
    for (int i = 0; i < 2; i++)
        so[i] = sw64((uint32_t)((r0 + 64 * i) * 64 + gi * 16));

    auto cpchunk = [&](int k0, int st) {
        uint32_t base = sb + st * STAGE_BYTES;
#pragma unroll
        for (int i = 0; i < 2; i++) {
            int r = r0 + 64 * i;
            size_t oa = (rowA0 + r) * (size_t)K + k0 + gi * 8;
            size_t ob = (rowB0 + r) * (size_t)K + k0 + gi * 8;
            cp16(base +         so[i], Ah + oa);
            cp16(base +  8192 + so[i], Al + oa);
            cp16(base + 16384 + so[i], Bh + ob);
            cp16(base + 24576 + so[i], Bl + ob);
        }
        cp_commit();
    };

    float acc[4][4][4];
#pragma unroll
    for (int mi = 0; mi < 4; mi++)
#pragma unroll
        for (int ni = 0; ni < 4; ni++)
#pragma unroll
            for (int j = 0; j < 4; j++) acc[mi][ni][j] = 0.0f;

    const int NC = K / 32;
    cpchunk(0, 0);
    for (int c = 0; c < NC; ++c) {
        if (c + 1 < NC) { cpchunk((c + 1) * 32, (c + 1) & 1); cp_wait<1>(); }
        else            { cp_wait<0>(); }
        __syncthreads();

        uint32_t base = sb + (c & 1) * STAGE_BYTES;
#pragma unroll
        for (int ks = 0; ks < 2; ks++) {
            uint32_t bh[4][2], bl[4][2];
#pragma unroll
            for (int np = 0; np < 2; np++) {
                int row = warpN * 32 + np * 16 + (lane & 15);
                uint32_t sw = sw64((uint32_t)(row * 64 + ks * 32 + (lane & 16)));
                uint32_t t[4];
                ldmx4(t, base + 16384 + sw);
                bh[np * 2][0] = t[0]; bh[np * 2][1] = t[2];
                bh[np * 2 + 1][0] = t[1]; bh[np * 2 + 1][1] = t[3];
                ldmx4(t, base + 24576 + sw);
                bl[np * 2][0] = t[0]; bl[np * 2][1] = t[2];
                bl[np * 2 + 1][0] = t[1]; bl[np * 2 + 1][1] = t[3];
            }
#pragma unroll
            for (int mi = 0; mi < 4; mi++) {
                int row = warpM * 64 + mi * 16 + (lane & 15);
                uint32_t sw = sw64((uint32_t)(row * 64 + ks * 32 + (lane & 16)));
                uint32_t ah[4], al[4];
                ldmx4(ah, base + sw);
                ldmx4(al, base + 8192 + sw);
#pragma unroll
                for (int ni = 0; ni < 4; ni++) {
                    mma_bf16(acc[mi][ni], ah, bh[ni]);
                    mma_bf16(acc[mi][ni], al, bh[ni]);
                    mma_bf16(acc[mi][ni], ah, bl[ni]);
                }
            }
        }
        __syncthreads();
    }

    const int rbase = (int)rowA0 + warpM * 64 + (lane >> 2);
    const int cbase = (int)rowB0 + warpN * 32 + (lane & 3) * 2;
#pragma unroll
    for (int mi = 0; mi < 4; mi++) {
#pragma unroll
        for (int ni = 0; ni < 4; ni++) {
            int cg = cbase + ni * 8;
            float2 bv = *(const float2*)(bias + cg);
#pragma unroll
            for (int h = 0; h < 2; h++) {
                int rg = rbase + mi * 16 + h * 8;
                float o0 = acc[mi][ni][2 * h]     + bv.x;
                float o1 = acc[mi][ni][2 * h + 1] + bv.y;
                size_t off = (size_t)rg * N + cg;
                if (MODE == MODE_BIAS_RES) {
                    float2 r = *(const float2*)(res + off);
                    o0 += r.x; o1 += r.y;
                    float2 w; w.x = o0; w.y = o1;
                    *(float2*)(C + off) = w;
                } else if (MODE == MODE_GELU_SPLIT) {
                    float g0 = 0.5f * o0 * (1.0f + erff(o0 * 0.70710678118654752f));
                    float g1 = 0.5f * o1 * (1.0f + erff(o1 * 0.70710678118654752f));
                    BF2 H, L;
                    split_bf16(g0, H.h[0], L.h[0]);
                    split_bf16(g1, H.h[1], L.h[1]);
                    *(uint32_t*)(Oh + off) = H.u;
                    *(uint32_t*)(Ol + off) = L.u;
                } else {
                    BF2 H, L;
                    split_bf16(o0 * oscale, H.h[0], L.h[0]);
                    split_bf16(o1 * oscale, H.h[1], L.h[1]);
                    *(uint32_t*)(Oh + off) = H.u;
                    *(uint32_t*)(Ol + off) = L.u;
                }
            }
        }
    }
}

template <int MODE>
__global__ __launch_bounds__(256, 2)
void mmagemm_kernel(const __nv_bfloat16* __restrict__ Ah, const __nv_bfloat16* __restrict__ Al,
                    const __nv_bfloat16* __restrict__ Bh, const __nv_bfloat16* __restrict__ Bl,
                    const float* __restrict__ bias, const float* __restrict__ res,
                    float* __restrict__ C,
                    __nv_bfloat16* __restrict__ Oh, __nv_bfloat16* __restrict__ Ol,
                    int N, int K, float oscale) {
    extern __shared__ char smg[];
    gemm_body<MODE>(Ah, Al, Bh, Bl, bias, res, C, Oh, Ol, N, K, oscale,
                    blockIdx.x, blockIdx.y, smg);
}

// fused QKV: blockIdx.x in [0,24): sel = x>>3 chooses Q/K/V, col block = x&7
__global__ __launch_bounds__(256, 2)
void qkv_kernel(const __nv_bfloat16* __restrict__ Ah, const __nv_bfloat16* __restrict__ Al,
                const __nv_bfloat16* __restrict__ B0h, const __nv_bfloat16* __restrict__ B0l,
                const __nv_bfloat16* __restrict__ B1h, const __nv_bfloat16* __restrict__ B1l,
                const __nv_bfloat16* __restrict__ B2h, const __nv_bfloat16* __restrict__ B2l,
                const float* __restrict__ b0, const float* __restrict__ b1,
                const float* __restrict__ b2,
                __nv_bfloat16* __restrict__ O0h, __nv_bfloat16* __restrict__ O0l,
                __nv_bfloat16* __restrict__ O1h, __nv_bfloat16* __restrict__ O1l,
                __nv_bfloat16* __restrict__ O2h, __nv_bfloat16* __restrict__ O2l) {
    extern __shared__ char smg[];
    const int sel = blockIdx.x >> 3;
    const int bxx = blockIdx.x & 7;
    const __nv_bfloat16* Bh = (sel == 0) ? B0h : (sel == 1) ? B1h : B2h;
    const __nv_bfloat16* Bl = (sel == 0) ? B0l : (sel == 1) ? B1l : B2l;
    const float* bias       = (sel == 0) ? b0  : (sel == 1) ? b1  : b2;
    __nv_bfloat16* Oh       = (sel == 0) ? O0h : (sel == 1) ? O1h : O2h;
    __nv_bfloat16* Ol       = (sel == 0) ? O0l : (sel == 1) ? O1l : O2l;
    const float sc = (sel == 0) ? 0.125f : 1.0f;
    gemm_body<MODE_BIAS_SPLIT>(Ah, Al, Bh, Bl, bias, nullptr, nullptr, Oh, Ol,
                               EMB, EMB, sc, bxx, blockIdx.y, smg);
}

// ---------------- tensor-core causal flash attention (pre-split inputs) -----
#define ATT_STAGE0 16384
#define ATT_STSZ   32768
#define ATT_SMEM   (ATT_STAGE0 + 2 * ATT_STSZ)

__global__ __launch_bounds__(128)
void attn_tc_kernel(const __nv_bfloat16* __restrict__ Qh_, const __nv_bfloat16* __restrict__ Ql_,
                    const __nv_bfloat16* __restrict__ Kh_, const __nv_bfloat16* __restrict__ Kl_,
                    const __nv_bfloat16* __restrict__ Vh_, const __nv_bfloat16* __restrict__ Vl_,
                    __nv_bfloat16* __restrict__ Oh, __nv_bfloat16* __restrict__ Ol) {
    extern __shared__ char smg[];
    const uint32_t sb = smem_u32(smg);
    const int qt   = (TSEQ / 64 - 1) - blockIdx.x;
    const int bh   = blockIdx.y;
    const int bb   = bh >> 4;
    const int head = bh & 15;
    const int tid  = threadIdx.x;
    const int wid  = tid >> 5;
    const int lane = tid & 31;
    const size_t hoff = (size_t)head * 64;
    const size_t seq0 = (size_t)bb * TSEQ;

    const int gi = tid & 7;
    const int r4 = tid >> 3;

    {
#pragma unroll
        for (int i = 0; i < 4; i++) {
            int r = r4 + 16 * i;
            size_t g = (seq0 + qt * 64 + r) * EMB + hoff + gi * 8;
            uint32_t sw = sw128((uint32_t)(r * 128 + gi * 16));
            cp16(sb + sw, Qh_ + g);
            cp16(sb + 8192 + sw, Ql_ + g);
        }
        cp_commit();
    }
    auto cpKV = [&](int kt, int st) {
        uint32_t base = sb + ATT_STAGE0 + st * ATT_STSZ;
#pragma unroll
        for (int i = 0; i < 4; i++) {
            int r = r4 + 16 * i;
            size_t g = (seq0 + kt * 64 + r) * EMB + hoff + gi * 8;
            uint32_t sw = sw128((uint32_t)(r * 128 + gi * 16));
            cp16(base + sw, Kh_ + g);
            cp16(base + 8192 + sw, Kl_ + g);
            cp16(base + 16384 + sw, Vh_ + g);
            cp16(base + 24576 + sw, Vl_ + g);
        }
        cp_commit();
    };
    cpKV(0, 0);
    cp_wait<0>();
    __syncthreads();

    uint32_t qh[4][4], ql[4][4];
#pragma unroll
    for (int ks = 0; ks < 4; ks++) {
        int row = wid * 16 + (lane & 15);
        uint32_t sw = sw128((uint32_t)(row * 128 + ks * 32 + (lane & 16)));
        ldmx4(qh[ks], sb + sw);
        ldmx4(ql[ks], sb + 8192 + sw);
    }

    float oacc[8][4];
#pragma unroll
    for (int i = 0; i < 8; i++)
#pragma unroll
        for (int j = 0; j < 4; j++) oacc[i][j] = 0.0f;
    float m0 = -3.0e38f, m1 = -3.0e38f, l0 = 0.0f, l1 = 0.0f;

    const int gr0 = qt * 64 + wid * 16 + (lane >> 2);
    const int cq  = (lane & 3) * 2;

    for (int kt = 0; kt <= qt; ++kt) {
        if (kt > 0) { cp_wait<0>(); __syncthreads(); }
        if (kt < qt) cpKV(kt + 1, (kt + 1) & 1);
        uint32_t base = sb + ATT_STAGE0 + (kt & 1) * ATT_STSZ;

        float sacc[8][4];
#pragma unroll
        for (int i = 0; i < 8; i++)
#pragma unroll
            for (int j = 0; j < 4; j++) sacc[i][j] = 0.0f;
#pragma unroll
        for (int ks = 0; ks < 4; ks++) {
            uint32_t kh[8][2], kl[8][2];
#pragma unroll
            for (int kp = 0; kp < 4; kp++) {
                int row = kp * 16 + (lane & 15);
                uint32_t sw = sw128((uint32_t)(row * 128 + ks * 32 + (lane & 16)));
                uint32_t t[4];
                ldmx4(t, base + sw);
                kh[kp * 2][0] = t[0]; kh[kp * 2][1] = t[2];
                kh[kp * 2 + 1][0] = t[1]; kh[kp * 2 + 1][1] = t[3];
                ldmx4(t, base + 8192 + sw);
                kl[kp * 2][0] = t[0]; kl[kp * 2][1] = t[2];
                kl[kp * 2 + 1][0] = t[1]; kl[kp * 2 + 1][1] = t[3];
            }
#pragma unroll
            for (int nt = 0; nt < 8; nt++) {
                mma_bf16(sacc[nt], qh[ks], kh[nt]);
                mma_bf16(sacc[nt], ql[ks], kh[nt]);
                mma_bf16(sacc[nt], qh[ks], kl[nt]);
            }
        }

        if (kt == qt) {
#pragma unroll
            for (int nt = 0; nt < 8; nt++) {
                int c0 = kt * 64 + nt * 8 + cq;
                if (c0 > gr0)     sacc[nt][0] = -1e30f;
                if (c0 + 1 > gr0) sacc[nt][1] = -1e30f;
                if (c0 > gr0 + 8)     sacc[nt][2] = -1e30f;
                if (c0 + 1 > gr0 + 8) sacc[nt][3] = -1e30f;
            }
        }

        float t0 = -3.0e38f, t1 = -3.0e38f;
#pragma unroll
        for (int nt = 0; nt < 8; nt++) {
            t0 = fmaxf(t0, fmaxf(sacc[nt][0], sacc[nt][1]));
            t1 = fmaxf(t1, fmaxf(sacc[nt][2], sacc[nt][3]));
        }
        t0 = fmaxf(t0, __shfl_xor_sync(0xffffffffu, t0, 1));
        t0 = fmaxf(t0, __shfl_xor_sync(0xffffffffu, t0, 2));
        t1 = fmaxf(t1, __shfl_xor_sync(0xffffffffu, t1, 1));
        t1 = fmaxf(t1, __shfl_xor_sync(0xffffffffu, t1, 2));
        float mn0 = fmaxf(m0, t0), mn1 = fmaxf(m1, t1);
        float al0 = __expf(m0 - mn0), al1 = __expf(m1 - mn1);
        m0 = mn0; m1 = mn1;

        uint32_t pH[8][2], pL[8][2];
        float ps0 = 0.0f, ps1 = 0.0f;
#pragma unroll
        for (int nt = 0; nt < 8; nt++) {
            float p0 = __expf(sacc[nt][0] - mn0);
            float p1 = __expf(sacc[nt][1] - mn0);
            float p2 = __expf(sacc[nt][2] - mn1);
            float p3 = __expf(sacc[nt][3] - mn1);
            ps0 += p0 + p1; ps1 += p2 + p3;
            BF2 H, L;
            split_bf16(p0, H.h[0], L.h[0]);
            split_bf16(p1, H.h[1], L.h[1]);
            pH[nt][0] = H.u; pL[nt][0] = L.u;
            split_bf16(p2, H.h[0], L.h[0]);
            split_bf16(p3, H.h[1], L.h[1]);
            pH[nt][1] = H.u; pL[nt][1] = L.u;
        }
        ps0 += __shfl_xor_sync(0xffffffffu, ps0, 1);
        ps0 += __shfl_xor_sync(0xffffffffu, ps0, 2);
        ps1 += __shfl_xor_sync(0xffffffffu, ps1, 1);
        ps1 += __shfl_xor_sync(0xffffffffu, ps1, 2);
        l0 = l0 * al0 + ps0;
        l1 = l1 * al1 + ps1;

#pragma unroll
        for (int dt = 0; dt < 8; dt++) {
            oacc[dt][0] *= al0; oacc[dt][1] *= al0;
            oacc[dt][2] *= al1; oacc[dt][3] *= al1;
        }

#pragma unroll
        for (int ks = 0; ks < 4; ks++) {
            uint32_t aH[4] = { pH[2 * ks][0], pH[2 * ks][1], pH[2 * ks + 1][0], pH[2 * ks + 1][1] };
            uint32_t aL[4] = { pL[2 * ks][0], pL[2 * ks][1], pL[2 * ks + 1][0], pL[2 * ks + 1][1] };
#pragma unroll
            for (int dp = 0; dp < 4; dp++) {
                uint32_t sw = sw128((uint32_t)((ks * 16 + (lane & 15)) * 128 + dp * 32 + (lane & 16)));
                uint32_t th[4], tl[4];
                ldmx4t(th, base + 16384 + sw);
                ldmx4t(tl, base + 24576 + sw);
                uint32_t b0h[2] = { th[0], th[1] }, b1h[2] = { th[2], th[3] };
                uint32_t b0l[2] = { tl[0], tl[1] }, b1l[2] = { tl[2], tl[3] };
                mma_bf16(oacc[2 * dp],     aH, b0h);
                mma_bf16(oacc[2 * dp],     aL, b0h);
                mma_bf16(oacc[2 * dp],     aH, b0l);
                mma_bf16(oacc[2 * dp + 1], aH, b1h);
                mma_bf16(oacc[2 * dp + 1], aL, b1h);
                mma_bf16(oacc[2 * dp + 1], aH, b1l);
            }
        }
    }

    float inv0 = 1.0f / l0, inv1 = 1.0f / l1;
#pragma unroll
    for (int dt = 0; dt < 8; dt++) {
        int cg = dt * 8 + cq;
        size_t off0 = (seq0 + gr0) * EMB + hoff + cg;
        size_t off1 = (seq0 + gr0 + 8) * EMB + hoff + cg;
        BF2 H, L;
        split_bf16(oacc[dt][0] * inv0, H.h[0], L.h[0]);
        split_bf16(oacc[dt][1] * inv0, H.h[1], L.h[1]);
        *(uint32_t*)(Oh + off0) = H.u;
        *(uint32_t*)(Ol + off0) = L.u;
        split_bf16(oacc[dt][2] * inv1, H.h[0], L.h[0]);
        split_bf16(oacc[dt][3] * inv1, H.h[1], L.h[1]);
        *(uint32_t*)(Oh + off1) = H.u;
        *(uint32_t*)(Ol + off1) = L.u;
    }
}

// ---------------- orchestration ----------------------------------------------
extern "C" void kernel_launch(void* const* d_in, const int* in_sizes, int n_in,
                              void* d_out, int out_size) {
    (void)in_sizes; (void)n_in; (void)out_size;
    const float* x    = (const float*)d_in[0];
    const float* Wq_w = (const float*)d_in[1];
    const float* Wq_b = (const float*)d_in[2];
    const float* Wk_w = (const float*)d_in[3];
    const float* Wk_b = (const float*)d_in[4];
    const float* Wv_w = (const float*)d_in[5];
    const float* Wv_b = (const float*)d_in[6];
    const float* Wo_w = (const float*)d_in[7];
    const float* Wo_b = (const float*)d_in[8];
    const float* l1_w = (const float*)d_in[9];
    const float* l1_b = (const float*)d_in[10];
    const float* l2_w = (const float*)d_in[11];
    const float* l2_b = (const float*)d_in[12];
    const float* n1s  = (const float*)d_in[13];
    const float* n1b  = (const float*)d_in[14];
    const float* n2s  = (const float*)d_in[15];
    const float* n2b  = (const float*)d_in[16];
    float* out = (float*)d_out;

    float *x1, *rs, *rq, *var;
    cudaGetSymbolAddress((void**)&x1,  g_x1);
    cudaGetSymbolAddress((void**)&rs,  g_rowsum);
    cudaGetSymbolAddress((void**)&rq,  g_rowsq);
    cudaGetSymbolAddress((void**)&var, g_var);

    __nv_bfloat16 *h_hi, *h_lo, *ctx_hi, *ctx_lo, *ff_hi, *ff_lo;
    __nv_bfloat16 *qh, *ql, *kh, *kl, *vh, *vl;
    __nv_bfloat16 *wq_hi, *wq_lo, *wk_hi, *wk_lo, *wv_hi, *wv_lo, *wo_hi, *wo_lo;
    __nv_bfloat16 *l1_hi, *l1_lo, *l2_hi, *l2_lo;
    cudaGetSymbolAddress((void**)&h_hi,  g_h_hi);
    cudaGetSymbolAddress((void**)&h_lo,  g_h_lo);
    cudaGetSymbolAddress((void**)&qh, g_qh);
    cudaGetSymbolAddress((void**)&ql, g_ql);
    cudaGetSymbolAddress((void**)&kh, g_kh);
    cudaGetSymbolAddress((void**)&kl, g_kl);
    cudaGetSymbolAddress((void**)&vh, g_vh);
    cudaGetSymbolAddress((void**)&vl, g_vl);
    cudaGetSymbolAddress((void**)&ctx_hi, g_ctx_hi);
    cudaGetSymbolAddress((void**)&ctx_lo, g_ctx_lo);
    cudaGetSymbolAddress((void**)&ff_hi, g_ff_hi);
    cudaGetSymbolAddress((void**)&ff_lo, g_ff_lo);
    cudaGetSymbolAddress((void**)&wq_hi, g_wq_hi);
    cudaGetSymbolAddress((void**)&wq_lo, g_wq_lo);
    cudaGetSymbolAddress((void**)&wk_hi, g_wk_hi);
    cudaGetSymbolAddress((void**)&wk_lo, g_wk_lo);
    cudaGetSymbolAddress((void**)&wv_hi, g_wv_hi);
    cudaGetSymbolAddress((void**)&wv_lo, g_wv_lo);
    cudaGetSymbolAddress((void**)&wo_hi, g_wo_hi);
    cudaGetSymbolAddress((void**)&wo_lo, g_wo_lo);
    cudaGetSymbolAddress((void**)&l1_hi, g_l1_hi);
    cudaGetSymbolAddress((void**)&l1_lo, g_l1_lo);
    cudaGetSymbolAddress((void**)&l2_hi, g_l2_hi);
    cudaGetSymbolAddress((void**)&l2_lo, g_l2_lo);

    cudaFuncSetAttribute((const void*)attn_tc_kernel,
                         cudaFuncAttributeMaxDynamicSharedMemorySize, ATT_SMEM);
    cudaFuncSetAttribute((const void*)qkv_kernel,
                         cudaFuncAttributeMaxDynamicSharedMemorySize, MM_SMEM);
    cudaFuncSetAttribute((const void*)mmagemm_kernel<MODE_BIAS_RES>,
                         cudaFuncAttributeMaxDynamicSharedMemorySize, MM_SMEM);
    cudaFuncSetAttribute((const void*)mmagemm_kernel<MODE_GELU_SPLIT>,
                         cudaFuncAttributeMaxDynamicSharedMemorySize, MM_SMEM);

    const int LN_BLOCKS = (N_TOK * EMB / 4) / 256;
    dim3 blk(256);
    dim3 gP(EMB / 128, N_TOK / 128);
    dim3 gF(DFF / 128, N_TOK / 128);
    dim3 gQKV(3 * EMB / 128, N_TOK / 128);

    // weight splits
    split_kernel<<<(EMB * EMB / 4) / 256, 256>>>(Wq_w, wq_hi, wq_lo, EMB * EMB / 4);
    split_kernel<<<(EMB * EMB / 4) / 256, 256>>>(Wk_w, wk_hi, wk_lo, EMB * EMB / 4);
    split_kernel<<<(EMB * EMB / 4) / 256, 256>>>(Wv_w, wv_hi, wv_lo, EMB * EMB / 4);
    split_kernel<<<(EMB * EMB / 4) / 256, 256>>>(Wo_w, wo_hi, wo_lo, EMB * EMB / 4);
    split_kernel<<<(DFF * EMB / 4) / 256, 256>>>(l1_w, l1_hi, l1_lo, DFF * EMB / 4);
    split_kernel<<<(EMB * DFF / 4) / 256, 256>>>(l2_w, l2_hi, l2_lo, EMB * DFF / 4);

    // LN1 -> h hi/lo
    rowstats_kernel<<<N_TOK, 256>>>(x, rs, rq);
    finalize_var_kernel<<<1, 256>>>(rs, rq, var);
    ln_apply_split_kernel<<<LN_BLOCKS, 256>>>(x, rs, var, n1s, n1b, h_hi, h_lo);

    // fused QKV projections -> pre-split bf16 hi/lo (Q pre-scaled by 1/8)
    qkv_kernel<<<gQKV, blk, MM_SMEM>>>(h_hi, h_lo,
                                       wq_hi, wq_lo, wk_hi, wk_lo, wv_hi, wv_lo,
                                       Wq_b, Wk_b, Wv_b,
                                       qh, ql, kh, kl, vh, vl);

    // tensor-core attention -> ctx hi/lo
    attn_tc_kernel<<<dim3(TSEQ / 64, 64), 128, ATT_SMEM>>>(qh, ql, kh, kl, vh, vl,
                                                           ctx_hi, ctx_lo);

    // output projection + residual
    mmagemm_kernel<MODE_BIAS_RES><<<gP, blk, MM_SMEM>>>(
        ctx_hi, ctx_lo, wo_hi, wo_lo, Wo_b, x, x1, nullptr, nullptr, EMB, EMB, 1.0f);

    // LN2 -> h hi/lo
    rowstats_kernel<<<N_TOK, 256>>>(x1, rs, rq);
    finalize_var_kernel<<<1, 256>>>(rs, rq, var);
    ln_apply_split_kernel<<<LN_BLOCKS, 256>>>(x1, rs, var, n2s, n2b, h_hi, h_lo);

    // FFN
    mmagemm_kernel<MODE_GELU_SPLIT><<<gF, blk, MM_SMEM>>>(
        h_hi, h_lo, l1_hi, l1_lo, l1_b, nullptr, nullptr, ff_hi, ff_lo, DFF, EMB, 1.0f);
    mmagemm_kernel<MODE_BIAS_RES><<<gP, blk, MM_SMEM>>>(
        ff_hi, ff_lo, l2_hi, l2_lo, l2_b, x1, out, nullptr, nullptr, EMB, DFF, 1.0f);
}

// round 11
// speedup vs baseline: 5.0842x; 1.3570x over previous
#include <cuda_runtime.h>
#include <cuda_fp16.h>
#include <math.h>
#include <stdint.h>

#define N_TOK 8192
#define EMB   1024
#define DFF   4096
#define TSEQ  2048

// ---------------- scratch (device globals; no allocations allowed) ----------
__device__ float g_x1 [N_TOK * EMB];
__device__ float g_rowsum[N_TOK];
__device__ float g_rowsq [N_TOK];
__device__ float g_var[2];

__device__ __half g_h_hi [N_TOK * EMB];
__device__ __half g_h_lo [N_TOK * EMB];
__device__ __half g_qh[N_TOK * EMB], g_ql[N_TOK * EMB];
__device__ __half g_kh[N_TOK * EMB];
__device__ __half g_vh[N_TOK * EMB];
__device__ __half g_ctx_hi[N_TOK * EMB];
__device__ __half g_ctx_lo[N_TOK * EMB];
__device__ __half g_ff_hi [N_TOK * DFF];
__device__ __half g_ff_lo [N_TOK * DFF];
__device__ __half g_wq[EMB * EMB], g_wk[EMB * EMB], g_wv[EMB * EMB], g_wo[EMB * EMB];
__device__ __half g_l1[DFF * EMB], g_l2[EMB * DFF];

union HF2 { __half h[2]; uint32_t u; };
union HF4 { __half h[4]; uint2 u; };

__device__ __forceinline__ void split_f16(float v, __half& hi, __half& lo) {
    hi = __float2half_rn(v);
    lo = __float2half_rn(v - __half2float(hi));
}
__device__ __forceinline__ uint32_t smem_u32(const void* p) {
    uint32_t a;
    asm("{ .reg .u64 t; cvta.to.shared.u64 t, %1; cvt.u32.u64 %0, t; }" : "=r"(a) : "l"(p));
    return a;
}
__device__ __forceinline__ void cp16(uint32_t dst, const void* src) {
    asm volatile("cp.async.cg.shared.global [%0], [%1], 16;" :: "r"(dst), "l"(src) : "memory");
}
__device__ __forceinline__ void cp_commit() {
    asm volatile("cp.async.commit_group;" ::: "memory");
}
template <int N>
__device__ __forceinline__ void cp_wait() {
    asm volatile("cp.async.wait_group %0;" :: "n"(N) : "memory");
}
__device__ __forceinline__ void ldmx4(uint32_t* r, uint32_t addr) {
    asm volatile("ldmatrix.sync.aligned.m8n8.x4.shared.b16 {%0,%1,%2,%3}, [%4];"
                 : "=r"(r[0]), "=r"(r[1]), "=r"(r[2]), "=r"(r[3]) : "r"(addr));
}
__device__ __forceinline__ void ldmx4t(uint32_t* r, uint32_t addr) {
    asm volatile("ldmatrix.sync.aligned.m8n8.x4.trans.shared.b16 {%0,%1,%2,%3}, [%4];"
                 : "=r"(r[0]), "=r"(r[1]), "=r"(r[2]), "=r"(r[3]) : "r"(addr));
}
__device__ __forceinline__ void mma_f16(float* c, const uint32_t* a, const uint32_t* b) {
    asm volatile("mma.sync.aligned.m16n8k16.row.col.f32.f16.f16.f32 "
                 "{%0,%1,%2,%3}, {%4,%5,%6,%7}, {%8,%9}, {%0,%1,%2,%3};"
                 : "+f"(c[0]), "+f"(c[1]), "+f"(c[2]), "+f"(c[3])
                 : "r"(a[0]), "r"(a[1]), "r"(a[2]), "r"(a[3]), "r"(b[0]), "r"(b[1]));
}
__device__ __forceinline__ uint32_t sw128(uint32_t o) { return o ^ ((o >> 3) & 0x70); }
__device__ __forceinline__ uint32_t sw64(uint32_t o)  { return o ^ ((o >> 3) & 0x30); }

// ---------------- weight split (hi only) -------------------------------------
__global__ void split_hi_kernel(const float* __restrict__ x,
                                __half* __restrict__ hi, int n4) {
    int i = blockIdx.x * blockDim.x + threadIdx.x;
    if (i >= n4) return;
    float4 v = ((const float4*)x)[i];
    HF4 H;
#pragma unroll
    for (int j = 0; j < 4; j++) H.h[j] = __float2half_rn((&v.x)[j]);
    ((uint2*)hi)[i] = H.u;
}

// ---------------- LN pieces ---------------------------------------------------
__global__ void rowstats_kernel(const float* __restrict__ x,
                                float* __restrict__ rowsum,
                                float* __restrict__ rowsq) {
    int row = blockIdx.x, tid = threadIdx.x;
    float4 v = *(const float4*)(x + (size_t)row * EMB + tid * 4);
    float s = v.x + v.y + v.z + v.w;
    float q = v.x * v.x + v.y * v.y + v.z * v.z + v.w * v.w;
#pragma unroll
    for (int o = 16; o > 0; o >>= 1) {
        s += __shfl_down_sync(0xffffffffu, s, o);
        q += __shfl_down_sync(0xffffffffu, q, o);
    }
    __shared__ float ss[8], qs[8];
    int w = tid >> 5, lane = tid & 31;
    if (lane == 0) { ss[w] = s; qs[w] = q; }
    __syncthreads();
    if (tid == 0) {
        float S = 0.f, Q = 0.f;
#pragma unroll
        for (int i = 0; i < 8; i++) { S += ss[i]; Q += qs[i]; }
        rowsum[row] = S; rowsq[row] = Q;
    }
}

__global__ void finalize_var_kernel(const float* __restrict__ rowsum,
                                    const float* __restrict__ rowsq,
                                    float* __restrict__ varout) {
    int tid = threadIdx.x;
    double s = 0.0, q = 0.0;
    for (int i = tid; i < N_TOK; i += 256) { s += (double)rowsum[i]; q += (double)rowsq[i]; }
#pragma unroll
    for (int o = 16; o > 0; o >>= 1) {
        s += __shfl_down_sync(0xffffffffu, s, o);
        q += __shfl_down_sync(0xffffffffu, q, o);
    }
    __shared__ double sd[8], qd[8];
    int w = tid >> 5, lane = tid & 31;
    if (lane == 0) { sd[w] = s; qd[w] = q; }
    __syncthreads();
    if (tid == 0) {
        double S = 0.0, Q = 0.0;
        for (int i = 0; i < 8; i++) { S += sd[i]; Q += qd[i]; }
        double M = (double)N_TOK * (double)EMB;
        double mean = S / M;
        varout[0] = (float)(Q / M - mean * mean);
    }
}

__global__ void ln_apply_split_kernel(const float* __restrict__ x,
                                      const float* __restrict__ rowsum,
                                      const float* __restrict__ varp,
                                      const float* __restrict__ scale,
                                      const float* __restrict__ shift,
                                      __half* __restrict__ hi,
                                      __half* __restrict__ lo) {
    size_t i4 = (size_t)blockIdx.x * blockDim.x + threadIdx.x;
    size_t off = i4 * 4;
    int row = (int)(off >> 10), col = (int)(off & 1023);
    float invv = 1.0f / varp[0];
    float mean = rowsum[row] * (1.0f / 1024.0f);
    float4 v  = *(const float4*)(x + off);
    float4 sc = *(const float4*)(scale + col);
    float4 sh = *(const float4*)(shift + col);
    float o[4];
    o[0] = ((v.x - mean) * invv + 1e-5f) * sc.x + sh.x;
    o[1] = ((v.y - mean) * invv + 1e-5f) * sc.y + sh.y;
    o[2] = ((v.z - mean) * invv + 1e-5f) * sc.z + sh.z;
    o[3] = ((v.w - mean) * invv + 1e-5f) * sc.w + sh.w;
    HF4 H, L;
#pragma unroll
    for (int j = 0; j < 4; j++) split_f16(o[j], H.h[j], L.h[j]);
    ((uint2*)hi)[i4] = H.u;
    ((uint2*)lo)[i4] = L.u;
}

// ---------------- fp16 2-pass GEMM: C[M,N] = A[M,K]*B[N,K]^T -----------------
// A = Ah + Al (fp16 pair), B = Bh only. D = AhBh + AlBh. err ~2^-12.
enum { MODE_BIAS_RES = 1, MODE_GELU_SPLIT = 2, MODE_BIAS_SPLIT = 3 };

#define STAGE_BYTES 24576
#define MM_SMEM (2 * STAGE_BYTES)

template <int MODE>
__device__ __forceinline__ void gemm_body(
    const __half* __restrict__ Ah, const __half* __restrict__ Al,
    const __half* __restrict__ Bh,
    const float* __restrict__ bias, const float* __restrict__ res,
    float* __restrict__ C, __half* __restrict__ Oh, __half* __restrict__ Ol,
    int N, int K, float oscale, int bxx, int byy, char* smg) {
    const uint32_t sb = smem_u32(smg);
    const int tid = threadIdx.x, wid = tid >> 5, lane = tid & 31;
    const int warpM = wid >> 2;
    const int warpN = wid & 3;
    const size_t rowA0 = (size_t)byy * 128;
    const size_t rowB0 = (size_t)bxx * 128;

    const int gi = tid & 3;     // 16B group in 64B row
    const int r0 = tid >> 2;    // 0..63
    uint32_t so[2];
#pragma unroll
    for (int i = 0; i < 2; i++)
        so[i] = sw64((uint32_t)((r0 + 64 * i) * 64 + gi * 16));

    auto cpchunk = [&](int k0, int st) {
        uint32_t base = sb + st * STAGE_BYTES;
#pragma unroll
        for (int i = 0; i < 2; i++) {
            int r = r0 + 64 * i;
            size_t oa = (rowA0 + r) * (size_t)K + k0 + gi * 8;
            size_t ob = (rowB0 + r) * (size_t)K + k0 + gi * 8;
            cp16(base +         so[i], Ah + oa);
            cp16(base +  8192 + so[i], Al + oa);
            cp16(base + 16384 + so[i], Bh + ob);
        }
        cp_commit();
    };

    float acc[4][4][4];
#pragma unroll
    for (int mi = 0; mi < 4; mi++)
#pragma unroll
        for (int ni = 0; ni < 4; ni++)
#pragma unroll
            for (int j = 0; j < 4; j++) acc[mi][ni][j] = 0.0f;

    const int NC = K / 32;
    cpchunk(0, 0);
    for (int c = 0; c < NC; ++c) {
        if (c + 1 < NC) { cpchunk((c + 1) * 32, (c + 1) & 1); cp_wait<1>(); }
        else            { cp_wait<0>(); }
        __syncthreads();

        uint32_t base = sb + (c & 1) * STAGE_BYTES;
#pragma unroll
        for (int ks = 0; ks < 2; ks++) {
            uint32_t bh[4][2];
#pragma unroll
            for (int np = 0; np < 2; np++) {
                int row = warpN * 32 + np * 16 + (lane & 15);
                uint32_t sw = sw64((uint32_t)(row * 64 + ks * 32 + (lane & 16)));
                uint32_t t[4];
                ldmx4(t, base + 16384 + sw);
                bh[np * 2][0] = t[0]; bh[np * 2][1] = t[2];
                bh[np * 2 + 1][0] = t[1]; bh[np * 2 + 1][1] = t[3];
            }
#pragma unroll
            for (int mi = 0; mi < 4; mi++) {
                int row = warpM * 64 + mi * 16 + (lane & 15);
                uint32_t sw = sw64((uint32_t)(row * 64 + ks * 32 + (lane & 16)));
                uint32_t ah[4], al[4];
                ldmx4(ah, base + sw);
                ldmx4(al, base + 8192 + sw);
#pragma unroll
                for (int ni = 0; ni < 4; ni++) {
                    mma_f16(acc[mi][ni], ah, bh[ni]);
                    mma_f16(acc[mi][ni], al, bh[ni]);
                }
            }
        }
        __syncthreads();
    }

    const int rbase = (int)rowA0 + warpM * 64 + (lane >> 2);
    const int cbase = (int)rowB0 + warpN * 32 + (lane & 3) * 2;
#pragma unroll
    for (int mi = 0; mi < 4; mi++) {
#pragma unroll
        for (int ni = 0; ni < 4; ni++) {
            int cg = cbase + ni * 8;
            float2 bv = *(const float2*)(bias + cg);
#pragma unroll
            for (int h = 0; h < 2; h++) {
                int rg = rbase + mi * 16 + h * 8;
                float o0 = acc[mi][ni][2 * h]     + bv.x;
                float o1 = acc[mi][ni][2 * h + 1] + bv.y;
                size_t off = (size_t)rg * N + cg;
                if (MODE == MODE_BIAS_RES) {
                    float2 r = *(const float2*)(res + off);
                    o0 += r.x; o1 += r.y;
                    float2 w; w.x = o0; w.y = o1;
                    *(float2*)(C + off) = w;
                } else if (MODE == MODE_GELU_SPLIT) {
                    float g0 = 0.5f * o0 * (1.0f + erff(o0 * 0.70710678118654752f));
                    float g1 = 0.5f * o1 * (1.0f + erff(o1 * 0.70710678118654752f));
                    HF2 H, L;
                    split_f16(g0, H.h[0], L.h[0]);
                    split_f16(g1, H.h[1], L.h[1]);
                    *(uint32_t*)(Oh + off) = H.u;
                    *(uint32_t*)(Ol + off) = L.u;
                } else {  // MODE_BIAS_SPLIT
                    float s0 = o0 * oscale, s1 = o1 * oscale;
                    HF2 H;
                    H.h[0] = __float2half_rn(s0);
                    H.h[1] = __float2half_rn(s1);
                    *(uint32_t*)(Oh + off) = H.u;
                    if (Ol) {
                        HF2 L;
                        L.h[0] = __float2half_rn(s0 - __half2float(H.h[0]));
                        L.h[1] = __float2half_rn(s1 - __half2float(H.h[1]));
                        *(uint32_t*)(Ol + off) = L.u;
                    }
                }
            }
        }
    }
}

template <int MODE>
__global__ __launch_bounds__(256, 2)
void mmagemm_kernel(const __half* __restrict__ Ah, const __half* __restrict__ Al,
                    const __half* __restrict__ Bh,
                    const float* __restrict__ bias, const float* __restrict__ res,
                    float* __restrict__ C,
                    __half* __restrict__ Oh, __half* __restrict__ Ol,
                    int N, int K, float oscale) {
    extern __shared__ char smg[];
    gemm_body<MODE>(Ah, Al, Bh, bias, res, C, Oh, Ol, N, K, oscale,
                    blockIdx.x, blockIdx.y, smg);
}

// fused QKV: blockIdx.x in [0,24): sel = x>>3, col block = x&7
__global__ __launch_bounds__(256, 2)
void qkv_kernel(const __half* __restrict__ Ah, const __half* __restrict__ Al,
                const __half* __restrict__ Bq, const __half* __restrict__ Bk,
                const __half* __restrict__ Bv,
                const float* __restrict__ b0, const float* __restrict__ b1,
                const float* __restrict__ b2,
                __half* __restrict__ Qh, __half* __restrict__ Ql,
                __half* __restrict__ Kh, __half* __restrict__ Vh) {
    extern __shared__ char smg[];
    const int sel = blockIdx.x >> 3;
    const int bxx = blockIdx.x & 7;
    const __half* Bh = (sel == 0) ? Bq : (sel == 1) ? Bk : Bv;
    const float* bias = (sel == 0) ? b0 : (sel == 1) ? b1 : b2;
    __half* Oh = (sel == 0) ? Qh : (sel == 1) ? Kh : Vh;
    __half* Ol = (sel == 0) ? Ql : nullptr;
    const float sc = (sel == 0) ? 0.125f : 1.0f;
    gemm_body<MODE_BIAS_SPLIT>(Ah, Al, Bh, bias, nullptr, nullptr, Oh, Ol,
                               EMB, EMB, sc, bxx, blockIdx.y, smg);
}

// ---------------- fp16 tensor-core causal flash attention --------------------
// q-tile 128 rows, 256 threads. smem: Qh 0 (16K), Ql 16384; stages at
// 32768 + st*16384: Kh +0 (8K), Vh +8192. Total 64KB.
#define ATT_SMEM 65536

__global__ __launch_bounds__(256)
void attn_tc_kernel(const __half* __restrict__ Qh_, const __half* __restrict__ Ql_,
                    const __half* __restrict__ Kh_, const __half* __restrict__ Vh_,
                    __half* __restrict__ Oh, __half* __restrict__ Ol) {
    extern __shared__ char smg[];
    const uint32_t sb = smem_u32(smg);
    const int qt   = (TSEQ / 128 - 1) - blockIdx.x;  // heavy blocks first
    const int bh   = blockIdx.y;
    const int bb   = bh >> 4;
    const int head = bh & 15;
    const int tid  = threadIdx.x;
    const int wid  = tid >> 5;
    const int lane = tid & 31;
    const size_t hoff = (size_t)head * 64;
    const size_t seq0 = (size_t)bb * TSEQ;

    const int gi  = tid & 7;
    const int r32 = tid >> 3;  // 0..31

    // Q tile (128 rows, pre-scaled by 1/8 at projection)
    {
#pragma unroll
        for (int i = 0; i < 4; i++) {
            int r = r32 + 32 * i;
            size_t g = (seq0 + qt * 128 + r) * EMB + hoff + gi * 8;
            uint32_t sw = sw128((uint32_t)(r * 128 + gi * 16));
            cp16(sb + sw, Qh_ + g);
            cp16(sb + 16384 + sw, Ql_ + g);
        }
        cp_commit();
    }
    auto cpKV = [&](int kt, int st) {
        uint32_t base = sb + 32768 + st * 16384;
#pragma unroll
        for (int i = 0; i < 2; i++) {
            int r = r32 + 32 * i;
            size_t g = (seq0 + kt * 64 + r) * EMB + hoff + gi * 8;
            uint32_t sw = sw128((uint32_t)(r * 128 + gi * 16));
            cp16(base + sw, Kh_ + g);
            cp16(base + 8192 + sw, Vh_ + g);
        }
        cp_commit();
    };
    cpKV(0, 0);
    cp_wait<0>();
    __syncthreads();

    // Q fragments: warp w owns rows wid*16..wid*16+15
    uint32_t qh[4][4], ql[4][4];
#pragma unroll
    for (int ks = 0; ks < 4; ks++) {
        int row = wid * 16 + (lane & 15);
        uint32_t sw = sw128((uint32_t)(row * 128 + ks * 32 + (lane & 16)));
        ldmx4(qh[ks], sb + sw);
        ldmx4(ql[ks], sb + 16384 + sw);
    }

    float oacc[8][4];
#pragma unroll
    for (int i = 0; i < 8; i++)
#pragma unroll
        for (int j = 0; j < 4; j++) oacc[i][j] = 0.0f;
    float m0 = -3.0e38f, m1 = -3.0e38f, l0 = 0.0f, l1 = 0.0f;

    const int gr0 = qt * 128 + wid * 16 + (lane >> 2);
    const int cq  = (lane & 3) * 2;
    const int ktlast = 2 * qt + 1;

    for (int kt = 0; kt <= ktlast; ++kt) {
        if (kt > 0) { cp_wait<0>(); __syncthreads(); }
        if (kt < ktlast) cpKV(kt + 1, (kt + 1) & 1);
        uint32_t base = sb + 32768 + (kt & 1) * 16384;

        // warp-uniform skip of fully-masked diagonal tiles
        if (kt * 64 > qt * 128 + wid * 16 + 15) continue;

        // ---- S = Q K^T (2-pass fp16) ----
        float sacc[8][4];
#pragma unroll
        for (int i = 0; i < 8; i++)
#pragma unroll
            for (int j = 0; j < 4; j++) sacc[i][j] = 0.0f;
#pragma unroll
        for (int ks = 0; ks < 4; ks++) {
            uint32_t kh[8][2];
#pragma unroll
            for (int kp = 0; kp < 4; kp++) {
                int row = kp * 16 + (lane & 15);
                uint32_t sw = sw128((uint32_t)(row * 128 + ks * 32 + (lane & 16)));
                uint32_t t[4];
                ldmx4(t, base + sw);
                kh[kp * 2][0] = t[0]; kh[kp * 2][1] = t[2];
                kh[kp * 2 + 1][0] = t[1]; kh[kp * 2 + 1][1] = t[3];
            }
#pragma unroll
            for (int nt = 0; nt < 8; nt++) {
                mma_f16(sacc[nt], qh[ks], kh[nt]);
                mma_f16(sacc[nt], ql[ks], kh[nt]);
            }
        }

        // causal mask (only needed near the diagonal)
        if (kt * 64 + 63 > qt * 128 + wid * 16) {
#pragma unroll
            for (int nt = 0; nt < 8; nt++) {
                int c0 = kt * 64 + nt * 8 + cq;
                if (c0 > gr0)     sacc[nt][0] = -1e30f;
                if (c0 + 1 > gr0) sacc[nt][1] = -1e30f;
                if (c0 > gr0 + 8)     sacc[nt][2] = -1e30f;
                if (c0 + 1 > gr0 + 8) sacc[nt][3] = -1e30f;
            }
        }

        // ---- online softmax ----
        float t0 = -3.0e38f, t1 = -3.0e38f;
#pragma unroll
        for (int nt = 0; nt < 8; nt++) {
            t0 = fmaxf(t0, fmaxf(sacc[nt][0], sacc[nt][1]));
            t1 = fmaxf(t1, fmaxf(sacc[nt][2], sacc[nt][3]));
        }
        t0 = fmaxf(t0, __shfl_xor_sync(0xffffffffu, t0, 1));
        t0 = fmaxf(t0, __shfl_xor_sync(0xffffffffu, t0, 2));
        t1 = fmaxf(t1, __shfl_xor_sync(0xffffffffu, t1, 1));
        t1 = fmaxf(t1, __shfl_xor_sync(0xffffffffu, t1, 2));
        float mn0 = fmaxf(m0, t0), mn1 = fmaxf(m1, t1);
        float al0 = __expf(m0 - mn0), al1 = __expf(m1 - mn1);
        m0 = mn0; m1 = mn1;

        uint32_t pH[8][2], pL[8][2];
        float ps0 = 0.0f, ps1 = 0.0f;
#pragma unroll
        for (int nt = 0; nt < 8; nt++) {
            float p0 = __expf(sacc[nt][0] - mn0);
            float p1 = __expf(sacc[nt][1] - mn0);
            float p2 = __expf(sacc[nt][2] - mn1);
            float p3 = __expf(sacc[nt][3] - mn1);
            ps0 += p0 + p1; ps1 += p2 + p3;
            HF2 H, L;
            split_f16(p0, H.h[0], L.h[0]);
            split_f16(p1, H.h[1], L.h[1]);
            pH[nt][0] = H.u; pL[nt][0] = L.u;
            split_f16(p2, H.h[0], L.h[0]);
            split_f16(p3, H.h[1], L.h[1]);
            pH[nt][1] = H.u; pL[nt][1] = L.u;
        }
        ps0 += __shfl_xor_sync(0xffffffffu, ps0, 1);
        ps0 += __shfl_xor_sync(0xffffffffu, ps0, 2);
        ps1 += __shfl_xor_sync(0xffffffffu, ps1, 1);
        ps1 += __shfl_xor_sync(0xffffffffu, ps1, 2);
        l0 = l0 * al0 + ps0;
        l1 = l1 * al1 + ps1;

#pragma unroll
        for (int dt = 0; dt < 8; dt++) {
            oacc[dt][0] *= al0; oacc[dt][1] *= al0;
            oacc[dt][2] *= al1; oacc[dt][3] *= al1;
        }

        // ---- PV (2-pass fp16), V hi only via ldmatrix.trans ----
#pragma unroll
        for (int ks = 0; ks < 4; ks++) {
            uint32_t aH[4] = { pH[2 * ks][0], pH[2 * ks][1], pH[2 * ks + 1][0], pH[2 * ks + 1][1] };
            uint32_t aL[4] = { pL[2 * ks][0], pL[2 * ks][1], pL[2 * ks + 1][0], pL[2 * ks + 1][1] };
#pragma unroll
            for (int dp = 0; dp < 4; dp++) {
                uint32_t sw = sw128((uint32_t)((ks * 16 + (lane & 15)) * 128 + dp * 32 + (lane & 16)));
                uint32_t th[4];
                ldmx4t(th, base + 8192 + sw);
                uint32_t b0h[2] = { th[0], th[1] }, b1h[2] = { th[2], th[3] };
                mma_f16(oacc[2 * dp],     aH, b0h);
                mma_f16(oacc[2 * dp],     aL, b0h);
                mma_f16(oacc[2 * dp + 1], aH, b1h);
                mma_f16(oacc[2 * dp + 1], aL, b1h);
            }
        }
    }

    // ---- epilogue: /l, split fp16 hi/lo ----
    float inv0 = 1.0f / l0, inv1 = 1.0f / l1;
#pragma unroll
    for (int dt = 0; dt < 8; dt++) {
        int cg = dt * 8 + cq;
        size_t off0 = (seq0 + gr0) * EMB + hoff + cg;
        size_t off1 = (seq0 + gr0 + 8) * EMB + hoff + cg;
        HF2 H, L;
        split_f16(oacc[dt][0] * inv0, H.h[0], L.h[0]);
        split_f16(oacc[dt][1] * inv0, H.h[1], L.h[1]);
        *(uint32_t*)(Oh + off0) = H.u;
        *(uint32_t*)(Ol + off0) = L.u;
        split_f16(oacc[dt][2] * inv1, H.h[0], L.h[0]);
        split_f16(oacc[dt][3] * inv1, H.h[1], L.h[1]);
        *(uint32_t*)(Oh + off1) = H.u;
        *(uint32_t*)(Ol + off1) = L.u;
    }
}

// ---------------- orchestration ----------------------------------------------
extern "C" void kernel_launch(void* const* d_in, const int* in_sizes, int n_in,
                              void* d_out, int out_size) {
    (void)in_sizes; (void)n_in; (void)out_size;
    const float* x    = (const float*)d_in[0];
    const float* Wq_w = (const float*)d_in[1];
    const float* Wq_b = (const float*)d_in[2];
    const float* Wk_w = (const float*)d_in[3];
    const float* Wk_b = (const float*)d_in[4];
    const float* Wv_w = (const float*)d_in[5];
    const float* Wv_b = (const float*)d_in[6];
    const float* Wo_w = (const float*)d_in[7];
    const float* Wo_b = (const float*)d_in[8];
    const float* l1_w = (const float*)d_in[9];
    const float* l1_b = (const float*)d_in[10];
    const float* l2_w = (const float*)d_in[11];
    const float* l2_b = (const float*)d_in[12];
    const float* n1s  = (const float*)d_in[13];
    const float* n1b  = (const float*)d_in[14];
    const float* n2s  = (const float*)d_in[15];
    const float* n2b  = (const float*)d_in[16];
    float* out = (float*)d_out;

    float *x1, *rs, *rq, *var;
    cudaGetSymbolAddress((void**)&x1,  g_x1);
    cudaGetSymbolAddress((void**)&rs,  g_rowsum);
    cudaGetSymbolAddress((void**)&rq,  g_rowsq);
    cudaGetSymbolAddress((void**)&var, g_var);

    __half *h_hi, *h_lo, *ctx_hi, *ctx_lo, *ff_hi, *ff_lo;
    __half *qh, *ql, *kh, *vh;
    __half *wq, *wk, *wv, *wo, *l1, *l2;
    cudaGetSymbolAddress((void**)&h_hi, g_h_hi);
    cudaGetSymbolAddress((void**)&h_lo, g_h_lo);
    cudaGetSymbolAddress((void**)&qh, g_qh);
    cudaGetSymbolAddress((void**)&ql, g_ql);
    cudaGetSymbolAddress((void**)&kh, g_kh);
    cudaGetSymbolAddress((void**)&vh, g_vh);
    cudaGetSymbolAddress((void**)&ctx_hi, g_ctx_hi);
    cudaGetSymbolAddress((void**)&ctx_lo, g_ctx_lo);
    cudaGetSymbolAddress((void**)&ff_hi, g_ff_hi);
    cudaGetSymbolAddress((void**)&ff_lo, g_ff_lo);
    cudaGetSymbolAddress((void**)&wq, g_wq);
    cudaGetSymbolAddress((void**)&wk, g_wk);
    cudaGetSymbolAddress((void**)&wv, g_wv);
    cudaGetSymbolAddress((void**)&wo, g_wo);
    cudaGetSymbolAddress((void**)&l1, g_l1);
    cudaGetSymbolAddress((void**)&l2, g_l2);

    cudaFuncSetAttribute((const void*)attn_tc_kernel,
                         cudaFuncAttributeMaxDynamicSharedMemorySize, ATT_SMEM);
    cudaFuncSetAttribute((const void*)qkv_kernel,
                         cudaFuncAttributeMaxDynamicSharedMemorySize, MM_SMEM);
    cudaFuncSetAttribute((const void*)mmagemm_kernel<MODE_BIAS_RES>,
                         cudaFuncAttributeMaxDynamicSharedMemorySize, MM_SMEM);
    cudaFuncSetAttribute((const void*)mmagemm_kernel<MODE_GELU_SPLIT>,
                         cudaFuncAttributeMaxDynamicSharedMemorySize, MM_SMEM);

    const int LN_BLOCKS = (N_TOK * EMB / 4) / 256;
    dim3 blk(256);
    dim3 gP(EMB / 128, N_TOK / 128);
    dim3 gF(DFF / 128, N_TOK / 128);
    dim3 gQKV(3 * EMB / 128, N_TOK / 128);

    // weight splits (hi only)
    split_hi_kernel<<<(EMB * EMB / 4) / 256, 256>>>(Wq_w, wq, EMB * EMB / 4);
    split_hi_kernel<<<(EMB * EMB / 4) / 256, 256>>>(Wk_w, wk, EMB * EMB / 4);
    split_hi_kernel<<<(EMB * EMB / 4) / 256, 256>>>(Wv_w, wv, EMB * EMB / 4);
    split_hi_kernel<<<(EMB * EMB / 4) / 256, 256>>>(Wo_w, wo, EMB * EMB / 4);
    split_hi_kernel<<<(DFF * EMB / 4) / 256, 256>>>(l1_w, l1, DFF * EMB / 4);
    split_hi_kernel<<<(EMB * DFF / 4) / 256, 256>>>(l2_w, l2, EMB * DFF / 4);

    // LN1 -> h hi/lo
    rowstats_kernel<<<N_TOK, 256>>>(x, rs, rq);
    finalize_var_kernel<<<1, 256>>>(rs, rq, var);
    ln_apply_split_kernel<<<LN_BLOCKS, 256>>>(x, rs, var, n1s, n1b, h_hi, h_lo);

    // fused QKV projections (Q pre-scaled 1/8, hi+lo; K/V hi only)
    qkv_kernel<<<gQKV, blk, MM_SMEM>>>(h_hi, h_lo, wq, wk, wv,
                                       Wq_b, Wk_b, Wv_b, qh, ql, kh, vh);

    // attention -> ctx hi/lo
    attn_tc_kernel<<<dim3(TSEQ / 128, 64), 256, ATT_SMEM>>>(qh, ql, kh, vh,
                                                            ctx_hi, ctx_lo);

    // output projection + residual
    mmagemm_kernel<MODE_BIAS_RES><<<gP, blk, MM_SMEM>>>(
        ctx_hi, ctx_lo, wo, Wo_b, x, x1, nullptr, nullptr, EMB, EMB, 1.0f);

    // LN2 -> h hi/lo
    rowstats_kernel<<<N_TOK, 256>>>(x1, rs, rq);
    finalize_var_kernel<<<1, 256>>>(rs, rq, var);
    ln_apply_split_kernel<<<LN_BLOCKS, 256>>>(x1, rs, var, n2s, n2b, h_hi, h_lo);

    // FFN
    mmagemm_kernel<MODE_GELU_SPLIT><<<gF, blk, MM_SMEM>>>(
        h_hi, h_lo, l1, l1_b, nullptr, nullptr, ff_hi, ff_lo, DFF, EMB, 1.0f);
    mmagemm_kernel<MODE_BIAS_RES><<<gP, blk, MM_SMEM>>>(
        ff_hi, ff_lo, l2, l2_b, x1, out, nullptr, nullptr, EMB, DFF, 1.0f);
}

// round 12
// speedup vs baseline: 5.2335x; 1.0294x over previous
#include <cuda_runtime.h>
#include <cuda_fp16.h>
#include <math.h>
#include <stdint.h>

#define N_TOK 8192
#define EMB   1024
#define DFF   4096
#define TSEQ  2048

// ---------------- scratch (device globals; no allocations allowed) ----------
__device__ float g_x1 [N_TOK * EMB];
__device__ float g_rowsum[N_TOK];
__device__ float g_rowsq [N_TOK];
__device__ float g_var[2];

__device__ __half g_h_hi [N_TOK * EMB];
__device__ __half g_h_lo [N_TOK * EMB];
__device__ __half g_qh[N_TOK * EMB], g_ql[N_TOK * EMB];
__device__ __half g_kh[N_TOK * EMB];
__device__ __half g_vh[N_TOK * EMB];
__device__ __half g_ctx_hi[N_TOK * EMB];
__device__ __half g_ctx_lo[N_TOK * EMB];
__device__ __half g_ff_hi [N_TOK * DFF];
__device__ __half g_ff_lo [N_TOK * DFF];
__device__ __half g_wq[EMB * EMB], g_wk[EMB * EMB], g_wv[EMB * EMB], g_wo[EMB * EMB];
__device__ __half g_l1[DFF * EMB], g_l2[EMB * DFF];

union HF2 { __half h[2]; uint32_t u; };
union HF4 { __half h[4]; uint2 u; };

__device__ __forceinline__ void split_f16(float v, __half& hi, __half& lo) {
    hi = __float2half_rn(v);
    lo = __float2half_rn(v - __half2float(hi));
}
__device__ __forceinline__ uint32_t smem_u32(const void* p) {
    uint32_t a;
    asm("{ .reg .u64 t; cvta.to.shared.u64 t, %1; cvt.u32.u64 %0, t; }" : "=r"(a) : "l"(p));
    return a;
}
__device__ __forceinline__ void cp16(uint32_t dst, const void* src) {
    asm volatile("cp.async.cg.shared.global [%0], [%1], 16;" :: "r"(dst), "l"(src) : "memory");
}
__device__ __forceinline__ void cp_commit() {
    asm volatile("cp.async.commit_group;" ::: "memory");
}
template <int N>
__device__ __forceinline__ void cp_wait() {
    asm volatile("cp.async.wait_group %0;" :: "n"(N) : "memory");
}
__device__ __forceinline__ void ldmx4(uint32_t* r, uint32_t addr) {
    asm volatile("ldmatrix.sync.aligned.m8n8.x4.shared.b16 {%0,%1,%2,%3}, [%4];"
                 : "=r"(r[0]), "=r"(r[1]), "=r"(r[2]), "=r"(r[3]) : "r"(addr));
}
__device__ __forceinline__ void ldmx4t(uint32_t* r, uint32_t addr) {
    asm volatile("ldmatrix.sync.aligned.m8n8.x4.trans.shared.b16 {%0,%1,%2,%3}, [%4];"
                 : "=r"(r[0]), "=r"(r[1]), "=r"(r[2]), "=r"(r[3]) : "r"(addr));
}
__device__ __forceinline__ void mma_f16(float* c, const uint32_t* a, const uint32_t* b) {
    asm volatile("mma.sync.aligned.m16n8k16.row.col.f32.f16.f16.f32 "
                 "{%0,%1,%2,%3}, {%4,%5,%6,%7}, {%8,%9}, {%0,%1,%2,%3};"
                 : "+f"(c[0]), "+f"(c[1]), "+f"(c[2]), "+f"(c[3])
                 : "r"(a[0]), "r"(a[1]), "r"(a[2]), "r"(a[3]), "r"(b[0]), "r"(b[1]));
}
__device__ __forceinline__ uint32_t sw128(uint32_t o) { return o ^ ((o >> 3) & 0x70); }
__device__ __forceinline__ uint32_t sw64(uint32_t o)  { return o ^ ((o >> 3) & 0x30); }

// ---------------- fused weight split (all 6 matrices, hi only) ---------------
#define SQ4 (EMB * EMB / 4)       // 262144 float4s per square weight
#define SL4 (DFF * EMB / 4)       // 1048576 float4s per FF weight
#define SPLIT_TOTAL4 (4 * SQ4 + 2 * SL4)

__global__ void split_all_kernel(const float* __restrict__ wq, const float* __restrict__ wk,
                                 const float* __restrict__ wv, const float* __restrict__ wo,
                                 const float* __restrict__ l1, const float* __restrict__ l2,
                                 __half* __restrict__ dq, __half* __restrict__ dk,
                                 __half* __restrict__ dv, __half* __restrict__ doo,
                                 __half* __restrict__ d1, __half* __restrict__ d2) {
    int i = blockIdx.x * blockDim.x + threadIdx.x;
    const float* src;
    __half* dst;
    int j;
    if (i < 4 * SQ4) {
        int m = i >> 18;          // SQ4 = 2^18
        j = i & (SQ4 - 1);
        src = (m == 0) ? wq : (m == 1) ? wk : (m == 2) ? wv : wo;
        dst = (m == 0) ? dq : (m == 1) ? dk : (m == 2) ? dv : doo;
    } else {
        int t = i - 4 * SQ4;
        if (t < SL4) { src = l1; dst = d1; j = t; }
        else         { src = l2; dst = d2; j = t - SL4; }
    }
    float4 v = ((const float4*)src)[j];
    HF4 H;
#pragma unroll
    for (int c = 0; c < 4; c++) H.h[c] = __float2half_rn((&v.x)[c]);
    ((uint2*)dst)[j] = H.u;
}

// ---------------- LN pieces ---------------------------------------------------
__global__ void rowstats_kernel(const float* __restrict__ x,
                                float* __restrict__ rowsum,
                                float* __restrict__ rowsq) {
    int row = blockIdx.x, tid = threadIdx.x;
    float4 v = *(const float4*)(x + (size_t)row * EMB + tid * 4);
    float s = v.x + v.y + v.z + v.w;
    float q = v.x * v.x + v.y * v.y + v.z * v.z + v.w * v.w;
#pragma unroll
    for (int o = 16; o > 0; o >>= 1) {
        s += __shfl_down_sync(0xffffffffu, s, o);
        q += __shfl_down_sync(0xffffffffu, q, o);
    }
    __shared__ float ss[8], qs[8];
    int w = tid >> 5, lane = tid & 31;
    if (lane == 0) { ss[w] = s; qs[w] = q; }
    __syncthreads();
    if (tid == 0) {
        float S = 0.f, Q = 0.f;
#pragma unroll
        for (int i = 0; i < 8; i++) { S += ss[i]; Q += qs[i]; }
        rowsum[row] = S; rowsq[row] = Q;
    }
}

__global__ void finalize_var_kernel(const float* __restrict__ rowsum,
                                    const float* __restrict__ rowsq,
                                    float* __restrict__ varout) {
    int tid = threadIdx.x;
    double s = 0.0, q = 0.0;
    for (int i = tid; i < N_TOK; i += 256) { s += (double)rowsum[i]; q += (double)rowsq[i]; }
#pragma unroll
    for (int o = 16; o > 0; o >>= 1) {
        s += __shfl_down_sync(0xffffffffu, s, o);
        q += __shfl_down_sync(0xffffffffu, q, o);
    }
    __shared__ double sd[8], qd[8];
    int w = tid >> 5, lane = tid & 31;
    if (lane == 0) { sd[w] = s; qd[w] = q; }
    __syncthreads();
    if (tid == 0) {
        double S = 0.0, Q = 0.0;
        for (int i = 0; i < 8; i++) { S += sd[i]; Q += qd[i]; }
        double M = (double)N_TOK * (double)EMB;
        double mean = S / M;
        varout[0] = (float)(Q / M - mean * mean);
    }
}

__global__ void ln_apply_split_kernel(const float* __restrict__ x,
                                      const float* __restrict__ rowsum,
                                      const float* __restrict__ varp,
                                      const float* __restrict__ scale,
                                      const float* __restrict__ shift,
                                      __half* __restrict__ hi,
                                      __half* __restrict__ lo) {
    size_t i4 = (size_t)blockIdx.x * blockDim.x + threadIdx.x;
    size_t off = i4 * 4;
    int row = (int)(off >> 10), col = (int)(off & 1023);
    float invv = 1.0f / varp[0];
    float mean = rowsum[row] * (1.0f / 1024.0f);
    float4 v  = *(const float4*)(x + off);
    float4 sc = *(const float4*)(scale + col);
    float4 sh = *(const float4*)(shift + col);
    float o[4];
    o[0] = ((v.x - mean) * invv + 1e-5f) * sc.x + sh.x;
    o[1] = ((v.y - mean) * invv + 1e-5f) * sc.y + sh.y;
    o[2] = ((v.z - mean) * invv + 1e-5f) * sc.z + sh.z;
    o[3] = ((v.w - mean) * invv + 1e-5f) * sc.w + sh.w;
    HF4 H, L;
#pragma unroll
    for (int j = 0; j < 4; j++) split_f16(o[j], H.h[j], L.h[j]);
    ((uint2*)hi)[i4] = H.u;
    ((uint2*)lo)[i4] = L.u;
}

// ---------------- fp16 2-pass GEMM: C[M,N] = A[M,K]*B[N,K]^T -----------------
enum { MODE_BIAS_RES = 1, MODE_GELU_SPLIT = 2, MODE_BIAS_SPLIT = 3 };

#define STAGE_BYTES 24576
#define MM_SMEM (2 * STAGE_BYTES)

template <int MODE>
__device__ __forceinline__ void gemm_body(
    const __half* __restrict__ Ah, const __half* __restrict__ Al,
    const __half* __restrict__ Bh,
    const float* __restrict__ bias, const float* __restrict__ res,
    float* __restrict__ C, __half* __restrict__ Oh, __half* __restrict__ Ol,
    int N, int K, float oscale, int bxx, int byy, char* smg) {
    const uint32_t sb = smem_u32(smg);
    const int tid = threadIdx.x, wid = tid >> 5, lane = tid & 31;
    const int warpM = wid >> 2;
    const int warpN = wid & 3;
    const size_t rowA0 = (size_t)byy * 128;
    const size_t rowB0 = (size_t)bxx * 128;

    const int gi = tid & 3;
    const int r0 = tid >> 2;
    uint32_t so[2];
#pragma unroll
    for (int i = 0; i < 2; i++)
        so[i] = sw64((uint32_t)((r0 + 64 * i) * 64 + gi * 16));

    auto cpchunk = [&](int k0, int st) {
        uint32_t base = sb + st * STAGE_BYTES;
#pragma unroll
        for (int i = 0; i < 2; i++) {
            int r = r0 + 64 * i;
            size_t oa = (rowA0 + r) * (size_t)K + k0 + gi * 8;
            size_t ob = (rowB0 + r) * (size_t)K + k0 + gi * 8;
            cp16(base +         so[i], Ah + oa);
            cp16(base +  8192 + so[i], Al + oa);
            cp16(base + 16384 + so[i], Bh + ob);
        }
        cp_commit();
    };

    float acc[4][4][4];
#pragma unroll
    for (int mi = 0; mi < 4; mi++)
#pragma unroll
        for (int ni = 0; ni < 4; ni++)
#pragma unroll
            for (int j = 0; j < 4; j++) acc[mi][ni][j] = 0.0f;

    const int NC = K / 32;
    cpchunk(0, 0);
    for (int c = 0; c < NC; ++c) {
        if (c + 1 < NC) { cpchunk((c + 1) * 32, (c + 1) & 1); cp_wait<1>(); }
        else            { cp_wait<0>(); }
        __syncthreads();

        uint32_t base = sb + (c & 1) * STAGE_BYTES;
#pragma unroll
        for (int ks = 0; ks < 2; ks++) {
            uint32_t bh[4][2];
#pragma unroll
            for (int np = 0; np < 2; np++) {
                int row = warpN * 32 + np * 16 + (lane & 15);
                uint32_t sw = sw64((uint32_t)(row * 64 + ks * 32 + (lane & 16)));
                uint32_t t[4];
                ldmx4(t, base + 16384 + sw);
                bh[np * 2][0] = t[0]; bh[np * 2][1] = t[2];
                bh[np * 2 + 1][0] = t[1]; bh[np * 2 + 1][1] = t[3];
            }
#pragma unroll
            for (int mi = 0; mi < 4; mi++) {
                int row = warpM * 64 + mi * 16 + (lane & 15);
                uint32_t sw = sw64((uint32_t)(row * 64 + ks * 32 + (lane & 16)));
                uint32_t ah[4], al[4];
                ldmx4(ah, base + sw);
                ldmx4(al, base + 8192 + sw);
#pragma unroll
                for (int ni = 0; ni < 4; ni++) {
                    mma_f16(acc[mi][ni], ah, bh[ni]);
                    mma_f16(acc[mi][ni], al, bh[ni]);
                }
            }
        }
        __syncthreads();
    }

    const int rbase = (int)rowA0 + warpM * 64 + (lane >> 2);
    const int cbase = (int)rowB0 + warpN * 32 + (lane & 3) * 2;
#pragma unroll
    for (int mi = 0; mi < 4; mi++) {
#pragma unroll
        for (int ni = 0; ni < 4; ni++) {
            int cg = cbase + ni * 8;
            float2 bv = *(const float2*)(bias + cg);
#pragma unroll
            for (int h = 0; h < 2; h++) {
                int rg = rbase + mi * 16 + h * 8;
                float o0 = acc[mi][ni][2 * h]     + bv.x;
                float o1 = acc[mi][ni][2 * h + 1] + bv.y;
                size_t off = (size_t)rg * N + cg;
                if (MODE == MODE_BIAS_RES) {
                    float2 r = *(const float2*)(res + off);
                    o0 += r.x; o1 += r.y;
                    float2 w; w.x = o0; w.y = o1;
                    *(float2*)(C + off) = w;
                } else if (MODE == MODE_GELU_SPLIT) {
                    float g0 = 0.5f * o0 * (1.0f + erff(o0 * 0.70710678118654752f));
                    float g1 = 0.5f * o1 * (1.0f + erff(o1 * 0.70710678118654752f));
                    HF2 H, L;
                    split_f16(g0, H.h[0], L.h[0]);
                    split_f16(g1, H.h[1], L.h[1]);
                    *(uint32_t*)(Oh + off) = H.u;
                    *(uint32_t*)(Ol + off) = L.u;
                } else {  // MODE_BIAS_SPLIT
                    float s0 = o0 * oscale, s1 = o1 * oscale;
                    HF2 H;
                    H.h[0] = __float2half_rn(s0);
                    H.h[1] = __float2half_rn(s1);
                    *(uint32_t*)(Oh + off) = H.u;
                    if (Ol) {
                        HF2 L;
                        L.h[0] = __float2half_rn(s0 - __half2float(H.h[0]));
                        L.h[1] = __float2half_rn(s1 - __half2float(H.h[1]));
                        *(uint32_t*)(Ol + off) = L.u;
                    }
                }
            }
        }
    }
}

template <int MODE>
__global__ __launch_bounds__(256, 2)
void mmagemm_kernel(const __half* __restrict__ Ah, const __half* __restrict__ Al,
                    const __half* __restrict__ Bh,
                    const float* __restrict__ bias, const float* __restrict__ res,
                    float* __restrict__ C,
                    __half* __restrict__ Oh, __half* __restrict__ Ol,
                    int N, int K, float oscale) {
    extern __shared__ char smg[];
    gemm_body<MODE>(Ah, Al, Bh, bias, res, C, Oh, Ol, N, K, oscale,
                    blockIdx.x, blockIdx.y, smg);
}

__global__ __launch_bounds__(256, 2)
void qkv_kernel(const __half* __restrict__ Ah, const __half* __restrict__ Al,
                const __half* __restrict__ Bq, const __half* __restrict__ Bk,
                const __half* __restrict__ Bv,
                const float* __restrict__ b0, const float* __restrict__ b1,
                const float* __restrict__ b2,
                __half* __restrict__ Qh, __half* __restrict__ Ql,
                __half* __restrict__ Kh, __half* __restrict__ Vh) {
    extern __shared__ char smg[];
    const int sel = blockIdx.x >> 3;
    const int bxx = blockIdx.x & 7;
    const __half* Bh = (sel == 0) ? Bq : (sel == 1) ? Bk : Bv;
    const float* bias = (sel == 0) ? b0 : (sel == 1) ? b1 : b2;
    __half* Oh = (sel == 0) ? Qh : (sel == 1) ? Kh : Vh;
    __half* Ol = (sel == 0) ? Ql : nullptr;
    const float sc = (sel == 0) ? 0.125f : 1.0f;
    gemm_body<MODE_BIAS_SPLIT>(Ah, Al, Bh, bias, nullptr, nullptr, Oh, Ol,
                               EMB, EMB, sc, bxx, blockIdx.y, smg);
}

// ---------------- fp16 tensor-core causal flash attention --------------------
// S = 2-pass (Qh+Ql)·Kh ; PV = 1-pass Ph·Vh.
#define ATT_SMEM 65536

__global__ __launch_bounds__(256)
void attn_tc_kernel(const __half* __restrict__ Qh_, const __half* __restrict__ Ql_,
                    const __half* __restrict__ Kh_, const __half* __restrict__ Vh_,
                    __half* __restrict__ Oh, __half* __restrict__ Ol) {
    extern __shared__ char smg[];
    const uint32_t sb = smem_u32(smg);
    const int qt   = (TSEQ / 128 - 1) - blockIdx.x;
    const int bh   = blockIdx.y;
    const int bb   = bh >> 4;
    const int head = bh & 15;
    const int tid  = threadIdx.x;
    const int wid  = tid >> 5;
    const int lane = tid & 31;
    const size_t hoff = (size_t)head * 64;
    const size_t seq0 = (size_t)bb * TSEQ;

    const int gi  = tid & 7;
    const int r32 = tid >> 3;

    {
#pragma unroll
        for (int i = 0; i < 4; i++) {
            int r = r32 + 32 * i;
            size_t g = (seq0 + qt * 128 + r) * EMB + hoff + gi * 8;
            uint32_t sw = sw128((uint32_t)(r * 128 + gi * 16));
            cp16(sb + sw, Qh_ + g);
            cp16(sb + 16384 + sw, Ql_ + g);
        }
        cp_commit();
    }
    auto cpKV = [&](int kt, int st) {
        uint32_t base = sb + 32768 + st * 16384;
#pragma unroll
        for (int i = 0; i < 2; i++) {
            int r = r32 + 32 * i;
            size_t g = (seq0 + kt * 64 + r) * EMB + hoff + gi * 8;
            uint32_t sw = sw128((uint32_t)(r * 128 + gi * 16));
            cp16(base + sw, Kh_ + g);
            cp16(base + 8192 + sw, Vh_ + g);
        }
        cp_commit();
    };
    cpKV(0, 0);
    cp_wait<0>();
    __syncthreads();

    uint32_t qh[4][4], ql[4][4];
#pragma unroll
    for (int ks = 0; ks < 4; ks++) {
        int row = wid * 16 + (lane & 15);
        uint32_t sw = sw128((uint32_t)(row * 128 + ks * 32 + (lane & 16)));
        ldmx4(qh[ks], sb + sw);
        ldmx4(ql[ks], sb + 16384 + sw);
    }

    float oacc[8][4];
#pragma unroll
    for (int i = 0; i < 8; i++)
#pragma unroll
        for (int j = 0; j < 4; j++) oacc[i][j] = 0.0f;
    float m0 = -3.0e38f, m1 = -3.0e38f, l0 = 0.0f, l1 = 0.0f;

    const int gr0 = qt * 128 + wid * 16 + (lane >> 2);
    const int cq  = (lane & 3) * 2;
    const int ktlast = 2 * qt + 1;

    for (int kt = 0; kt <= ktlast; ++kt) {
        if (kt > 0) { cp_wait<0>(); __syncthreads(); }
        if (kt < ktlast) cpKV(kt + 1, (kt + 1) & 1);
        uint32_t base = sb + 32768 + (kt & 1) * 16384;

        if (kt * 64 > qt * 128 + wid * 16 + 15) continue;

        // ---- S = Q K^T (2-pass) ----
        float sacc[8][4];
#pragma unroll
        for (int i = 0; i < 8; i++)
#pragma unroll
            for (int j = 0; j < 4; j++) sacc[i][j] = 0.0f;
#pragma unroll
        for (int ks = 0; ks < 4; ks++) {
            uint32_t kh[8][2];
#pragma unroll
            for (int kp = 0; kp < 4; kp++) {
                int row = kp * 16 + (lane & 15);
                uint32_t sw = sw128((uint32_t)(row * 128 + ks * 32 + (lane & 16)));
                uint32_t t[4];
                ldmx4(t, base + sw);
                kh[kp * 2][0] = t[0]; kh[kp * 2][1] = t[2];
                kh[kp * 2 + 1][0] = t[1]; kh[kp * 2 + 1][1] = t[3];
            }
#pragma unroll
            for (int nt = 0; nt < 8; nt++) {
                mma_f16(sacc[nt], qh[ks], kh[nt]);
                mma_f16(sacc[nt], ql[ks], kh[nt]);
            }
        }

        if (kt * 64 + 63 > qt * 128 + wid * 16) {
#pragma unroll
            for (int nt = 0; nt < 8; nt++) {
                int c0 = kt * 64 + nt * 8 + cq;
                if (c0 > gr0)     sacc[nt][0] = -1e30f;
                if (c0 + 1 > gr0) sacc[nt][1] = -1e30f;
                if (c0 > gr0 + 8)     sacc[nt][2] = -1e30f;
                if (c0 + 1 > gr0 + 8) sacc[nt][3] = -1e30f;
            }
        }

        // ---- online softmax ----
        float t0 = -3.0e38f, t1 = -3.0e38f;
#pragma unroll
        for (int nt = 0; nt < 8; nt++) {
            t0 = fmaxf(t0, fmaxf(sacc[nt][0], sacc[nt][1]));
            t1 = fmaxf(t1, fmaxf(sacc[nt][2], sacc[nt][3]));
        }
        t0 = fmaxf(t0, __shfl_xor_sync(0xffffffffu, t0, 1));
        t0 = fmaxf(t0, __shfl_xor_sync(0xffffffffu, t0, 2));
        t1 = fmaxf(t1, __shfl_xor_sync(0xffffffffu, t1, 1));
        t1 = fmaxf(t1, __shfl_xor_sync(0xffffffffu, t1, 2));
        float mn0 = fmaxf(m0, t0), mn1 = fmaxf(m1, t1);
        float al0 = __expf(m0 - mn0), al1 = __expf(m1 - mn1);
        m0 = mn0; m1 = mn1;

        uint32_t pH[8][2];
        float ps0 = 0.0f, ps1 = 0.0f;
#pragma unroll
        for (int nt = 0; nt < 8; nt++) {
            float p0 = __expf(sacc[nt][0] - mn0);
            float p1 = __expf(sacc[nt][1] - mn0);
            float p2 = __expf(sacc[nt][2] - mn1);
            float p3 = __expf(sacc[nt][3] - mn1);
            ps0 += p0 + p1; ps1 += p2 + p3;
            HF2 H;
            H.h[0] = __float2half_rn(p0);
            H.h[1] = __float2half_rn(p1);
            pH[nt][0] = H.u;
            H.h[0] = __float2half_rn(p2);
            H.h[1] = __float2half_rn(p3);
            pH[nt][1] = H.u;
        }
        ps0 += __shfl_xor_sync(0xffffffffu, ps0, 1);
        ps0 += __shfl_xor_sync(0xffffffffu, ps0, 2);
        ps1 += __shfl_xor_sync(0xffffffffu, ps1, 1);
        ps1 += __shfl_xor_sync(0xffffffffu, ps1, 2);
        l0 = l0 * al0 + ps0;
        l1 = l1 * al1 + ps1;

#pragma unroll
        for (int dt = 0; dt < 8; dt++) {
            oacc[dt][0] *= al0; oacc[dt][1] *= al0;
            oacc[dt][2] *= al1; oacc[dt][3] *= al1;
        }

        // ---- PV (1-pass: Ph·Vh) ----
#pragma unroll
        for (int ks = 0; ks < 4; ks++) {
            uint32_t aH[4] = { pH[2 * ks][0], pH[2 * ks][1], pH[2 * ks + 1][0], pH[2 * ks + 1][1] };
#pragma unroll
            for (int dp = 0; dp < 4; dp++) {
                uint32_t sw = sw128((uint32_t)((ks * 16 + (lane & 15)) * 128 + dp * 32 + (lane & 16)));
                uint32_t th[4];
                ldmx4t(th, base + 8192 + sw);
                uint32_t b0h[2] = { th[0], th[1] }, b1h[2] = { th[2], th[3] };
                mma_f16(oacc[2 * dp],     aH, b0h);
                mma_f16(oacc[2 * dp + 1], aH, b1h);
            }
        }
    }

    float inv0 = 1.0f / l0, inv1 = 1.0f / l1;
#pragma unroll
    for (int dt = 0; dt < 8; dt++) {
        int cg = dt * 8 + cq;
        size_t off0 = (seq0 + gr0) * EMB + hoff + cg;
        size_t off1 = (seq0 + gr0 + 8) * EMB + hoff + cg;
        HF2 H, L;
        split_f16(oacc[dt][0] * inv0, H.h[0], L.h[0]);
        split_f16(oacc[dt][1] * inv0, H.h[1], L.h[1]);
        *(uint32_t*)(Oh + off0) = H.u;
        *(uint32_t*)(Ol + off0) = L.u;
        split_f16(oacc[dt][2] * inv1, H.h[0], L.h[0]);
        split_f16(oacc[dt][3] * inv1, H.h[1], L.h[1]);
        *(uint32_t*)(Oh + off1) = H.u;
        *(uint32_t*)(Ol + off1) = L.u;
    }
}

// ---------------- orchestration ----------------------------------------------
extern "C" void kernel_launch(void* const* d_in, const int* in_sizes, int n_in,
                              void* d_out, int out_size) {
    (void)in_sizes; (void)n_in; (void)out_size;
    const float* x    = (const float*)d_in[0];
    const float* Wq_w = (const float*)d_in[1];
    const float* Wq_b = (const float*)d_in[2];
    const float* Wk_w = (const float*)d_in[3];
    const float* Wk_b = (const float*)d_in[4];
    const float* Wv_w = (const float*)d_in[5];
    const float* Wv_b = (const float*)d_in[6];
    const float* Wo_w = (const float*)d_in[7];
    const float* Wo_b = (const float*)d_in[8];
    const float* l1_w = (const float*)d_in[9];
    const float* l1_b = (const float*)d_in[10];
    const float* l2_w = (const float*)d_in[11];
    const float* l2_b = (const float*)d_in[12];
    const float* n1s  = (const float*)d_in[13];
    const float* n1b  = (const float*)d_in[14];
    const float* n2s  = (const float*)d_in[15];
    const float* n2b  = (const float*)d_in[16];
    float* out = (float*)d_out;

    float *x1, *rs, *rq, *var;
    cudaGetSymbolAddress((void**)&x1,  g_x1);
    cudaGetSymbolAddress((void**)&rs,  g_rowsum);
    cudaGetSymbolAddress((void**)&rq,  g_rowsq);
    cudaGetSymbolAddress((void**)&var, g_var);

    __half *h_hi, *h_lo, *ctx_hi, *ctx_lo, *ff_hi, *ff_lo;
    __half *qh, *ql, *kh, *vh;
    __half *wq, *wk, *wv, *wo, *l1, *l2;
    cudaGetSymbolAddress((void**)&h_hi, g_h_hi);
    cudaGetSymbolAddress((void**)&h_lo, g_h_lo);
    cudaGetSymbolAddress((void**)&qh, g_qh);
    cudaGetSymbolAddress((void**)&ql, g_ql);
    cudaGetSymbolAddress((void**)&kh, g_kh);
    cudaGetSymbolAddress((void**)&vh, g_vh);
    cudaGetSymbolAddress((void**)&ctx_hi, g_ctx_hi);
    cudaGetSymbolAddress((void**)&ctx_lo, g_ctx_lo);
    cudaGetSymbolAddress((void**)&ff_hi, g_ff_hi);
    cudaGetSymbolAddress((void**)&ff_lo, g_ff_lo);
    cudaGetSymbolAddress((void**)&wq, g_wq);
    cudaGetSymbolAddress((void**)&wk, g_wk);
    cudaGetSymbolAddress((void**)&wv, g_wv);
    cudaGetSymbolAddress((void**)&wo, g_wo);
    cudaGetSymbolAddress((void**)&l1, g_l1);
    cudaGetSymbolAddress((void**)&l2, g_l2);

    cudaFuncSetAttribute((const void*)attn_tc_kernel,
                         cudaFuncAttributeMaxDynamicSharedMemorySize, ATT_SMEM);
    cudaFuncSetAttribute((const void*)qkv_kernel,
                         cudaFuncAttributeMaxDynamicSharedMemorySize, MM_SMEM);
    cudaFuncSetAttribute((const void*)mmagemm_kernel<MODE_BIAS_RES>,
                         cudaFuncAttributeMaxDynamicSharedMemorySize, MM_SMEM);
    cudaFuncSetAttribute((const void*)mmagemm_kernel<MODE_GELU_SPLIT>,
                         cudaFuncAttributeMaxDynamicSharedMemorySize, MM_SMEM);

    const int LN_BLOCKS = (N_TOK * EMB / 4) / 256;
    dim3 blk(256);
    dim3 gP(EMB / 128, N_TOK / 128);
    dim3 gF(DFF / 128, N_TOK / 128);
    dim3 gQKV(3 * EMB / 128, N_TOK / 128);

    // fused weight split (hi only), one launch
    split_all_kernel<<<SPLIT_TOTAL4 / 256, 256>>>(Wq_w, Wk_w, Wv_w, Wo_w, l1_w, l2_w,
                                                  wq, wk, wv, wo, l1, l2);

    // LN1 -> h hi/lo
    rowstats_kernel<<<N_TOK, 256>>>(x, rs, rq);
    finalize_var_kernel<<<1, 256>>>(rs, rq, var);
    ln_apply_split_kernel<<<LN_BLOCKS, 256>>>(x, rs, var, n1s, n1b, h_hi, h_lo);

    // fused QKV projections (Q pre-scaled 1/8, hi+lo; K/V hi only)
    qkv_kernel<<<gQKV, blk, MM_SMEM>>>(h_hi, h_lo, wq, wk, wv,
                                       Wq_b, Wk_b, Wv_b, qh, ql, kh, vh);

    // attention -> ctx hi/lo
    attn_tc_kernel<<<dim3(TSEQ / 128, 64), 256, ATT_SMEM>>>(qh, ql, kh, vh,
                                                            ctx_hi, ctx_lo);

    // output projection + residual
    mmagemm_kernel<MODE_BIAS_RES><<<gP, blk, MM_SMEM>>>(
        ctx_hi, ctx_lo, wo, Wo_b, x, x1, nullptr, nullptr, EMB, EMB, 1.0f);

    // LN2 -> h hi/lo
    rowstats_kernel<<<N_TOK, 256>>>(x1, rs, rq);
    finalize_var_kernel<<<1, 256>>>(rs, rq, var);
    ln_apply_split_kernel<<<LN_BLOCKS, 256>>>(x1, rs, var, n2s, n2b, h_hi, h_lo);

    // FFN
    mmagemm_kernel<MODE_GELU_SPLIT><<<gF, blk, MM_SMEM>>>(
        h_hi, h_lo, l1, l1_b, nullptr, nullptr, ff_hi, ff_lo, DFF, EMB, 1.0f);
    mmagemm_kernel<MODE_BIAS_RES><<<gP, blk, MM_SMEM>>>(
        ff_hi, ff_lo, l2, l2_b, x1, out, nullptr, nullptr, EMB, DFF, 1.0f);
}

// round 14
// speedup vs baseline: 6.3718x; 1.2175x over previous
#include <cuda_runtime.h>
#include <cuda_fp16.h>
#include <math.h>
#include <stdint.h>

#define N_TOK 8192
#define EMB   1024
#define DFF   4096
#define TSEQ  2048

// ---------------- scratch (device globals; no allocations allowed) ----------
__device__ float g_x1 [N_TOK * EMB];
__device__ float g_rowsum[N_TOK];
__device__ float g_rowsq [N_TOK];
__device__ float g_var[2];

__device__ __half g_h_hi [N_TOK * EMB];
__device__ __half g_h_lo [N_TOK * EMB];
__device__ __half g_qh[N_TOK * EMB], g_ql[N_TOK * EMB];
__device__ __half g_kh[N_TOK * EMB];
__device__ __half g_vh[N_TOK * EMB];
__device__ __half g_ctx[N_TOK * EMB];
__device__ __half g_ff [N_TOK * DFF];
__device__ __half g_wq[EMB * EMB], g_wk[EMB * EMB], g_wv[EMB * EMB], g_wo[EMB * EMB];
__device__ __half g_l1[DFF * EMB], g_l2[EMB * DFF];

union HF2 { __half h[2]; uint32_t u; };
union HF4 { __half h[4]; uint2 u; };

__device__ __forceinline__ void split_f16(float v, __half& hi, __half& lo) {
    hi = __float2half_rn(v);
    lo = __float2half_rn(v - __half2float(hi));
}
__device__ __forceinline__ uint32_t smem_u32(const void* p) {
    uint32_t a;
    asm("{ .reg .u64 t; cvta.to.shared.u64 t, %1; cvt.u32.u64 %0, t; }" : "=r"(a) : "l"(p));
    return a;
}
__device__ __forceinline__ void cp16(uint32_t dst, const void* src) {
    asm volatile("cp.async.cg.shared.global [%0], [%1], 16;" :: "r"(dst), "l"(src) : "memory");
}
__device__ __forceinline__ void cp_commit() {
    asm volatile("cp.async.commit_group;" ::: "memory");
}
template <int N>
__device__ __forceinline__ void cp_wait() {
    asm volatile("cp.async.wait_group %0;" :: "n"(N) : "memory");
}
__device__ __forceinline__ void ldmx4(uint32_t* r, uint32_t addr) {
    asm volatile("ldmatrix.sync.aligned.m8n8.x4.shared.b16 {%0,%1,%2,%3}, [%4];"
                 : "=r"(r[0]), "=r"(r[1]), "=r"(r[2]), "=r"(r[3]) : "r"(addr));
}
__device__ __forceinline__ void ldmx4t(uint32_t* r, uint32_t addr) {
    asm volatile("ldmatrix.sync.aligned.m8n8.x4.trans.shared.b16 {%0,%1,%2,%3}, [%4];"
                 : "=r"(r[0]), "=r"(r[1]), "=r"(r[2]), "=r"(r[3]) : "r"(addr));
}
__device__ __forceinline__ void mma_f16(float* c, const uint32_t* a, const uint32_t* b) {
    asm volatile("mma.sync.aligned.m16n8k16.row.col.f32.f16.f16.f32 "
                 "{%0,%1,%2,%3}, {%4,%5,%6,%7}, {%8,%9}, {%0,%1,%2,%3};"
                 : "+f"(c[0]), "+f"(c[1]), "+f"(c[2]), "+f"(c[3])
                 : "r"(a[0]), "r"(a[1]), "r"(a[2]), "r"(a[3]), "r"(b[0]), "r"(b[1]));
}
__device__ __forceinline__ uint32_t sw128(uint32_t o) { return o ^ ((o >> 3) & 0x70); }
__device__ __forceinline__ uint32_t sw64(uint32_t o)  { return o ^ ((o >> 3) & 0x30); }

// ---------------- fused weight split (all 6 matrices, hi only) ---------------
#define SQ4 (EMB * EMB / 4)
#define SL4 (DFF * EMB / 4)
#define SPLIT_TOTAL4 (4 * SQ4 + 2 * SL4)

__global__ void split_all_kernel(const float* __restrict__ wq, const float* __restrict__ wk,
                                 const float* __restrict__ wv, const float* __restrict__ wo,
                                 const float* __restrict__ l1, const float* __restrict__ l2,
                                 __half* __restrict__ dq, __half* __restrict__ dk,
                                 __half* __restrict__ dv, __half* __restrict__ doo,
                                 __half* __restrict__ d1, __half* __restrict__ d2) {
    int i = blockIdx.x * blockDim.x + threadIdx.x;
    const float* src;
    __half* dst;
    int j;
    if (i < 4 * SQ4) {
        int m = i >> 18;
        j = i & (SQ4 - 1);
        src = (m == 0) ? wq : (m == 1) ? wk : (m == 2) ? wv : wo;
        dst = (m == 0) ? dq : (m == 1) ? dk : (m == 2) ? dv : doo;
    } else {
        int t = i - 4 * SQ4;
        if (t < SL4) { src = l1; dst = d1; j = t; }
        else         { src = l2; dst = d2; j = t - SL4; }
    }
    float4 v = ((const float4*)src)[j];
    HF4 H;
#pragma unroll
    for (int c = 0; c < 4; c++) H.h[c] = __float2half_rn((&v.x)[c]);
    ((uint2*)dst)[j] = H.u;
}

// ---------------- LN pieces ---------------------------------------------------
__global__ void rowstats_kernel(const float* __restrict__ x,
                                float* __restrict__ rowsum,
                                float* __restrict__ rowsq) {
    int row = blockIdx.x, tid = threadIdx.x;
    float4 v = *(const float4*)(x + (size_t)row * EMB + tid * 4);
    float s = v.x + v.y + v.z + v.w;
    float q = v.x * v.x + v.y * v.y + v.z * v.z + v.w * v.w;
#pragma unroll
    for (int o = 16; o > 0; o >>= 1) {
        s += __shfl_down_sync(0xffffffffu, s, o);
        q += __shfl_down_sync(0xffffffffu, q, o);
    }
    __shared__ float ss[8], qs[8];
    int w = tid >> 5, lane = tid & 31;
    if (lane == 0) { ss[w] = s; qs[w] = q; }
    __syncthreads();
    if (tid == 0) {
        float S = 0.f, Q = 0.f;
#pragma unroll
        for (int i = 0; i < 8; i++) { S += ss[i]; Q += qs[i]; }
        rowsum[row] = S; rowsq[row] = Q;
    }
}

__global__ void finalize_var_kernel(const float* __restrict__ rowsum,
                                    const float* __restrict__ rowsq,
                                    float* __restrict__ varout) {
    int tid = threadIdx.x;
    double s = 0.0, q = 0.0;
    for (int i = tid; i < N_TOK; i += 256) { s += (double)rowsum[i]; q += (double)rowsq[i]; }
#pragma unroll
    for (int o = 16; o > 0; o >>= 1) {
        s += __shfl_down_sync(0xffffffffu, s, o);
        q += __shfl_down_sync(0xffffffffu, q, o);
    }
    __shared__ double sd[8], qd[8];
    int w = tid >> 5, lane = tid & 31;
    if (lane == 0) { sd[w] = s; qd[w] = q; }
    __syncthreads();
    if (tid == 0) {
        double S = 0.0, Q = 0.0;
        for (int i = 0; i < 8; i++) { S += sd[i]; Q += qd[i]; }
        double M = (double)N_TOK * (double)EMB;
        double mean = S / M;
        varout[0] = (float)(Q / M - mean * mean);
    }
}

__global__ void ln_apply_split_kernel(const float* __restrict__ x,
                                      const float* __restrict__ rowsum,
                                      const float* __restrict__ varp,
                                      const float* __restrict__ scale,
                                      const float* __restrict__ shift,
                                      __half* __restrict__ hi,
                                      __half* __restrict__ lo) {
    size_t i4 = (size_t)blockIdx.x * blockDim.x + threadIdx.x;
    size_t off = i4 * 4;
    int row = (int)(off >> 10), col = (int)(off & 1023);
    float invv = 1.0f / varp[0];
    float mean = rowsum[row] * (1.0f / 1024.0f);
    float4 v  = *(const float4*)(x + off);
    float4 sc = *(const float4*)(scale + col);
    float4 sh = *(const float4*)(shift + col);
    float o[4];
    o[0] = ((v.x - mean) * invv + 1e-5f) * sc.x + sh.x;
    o[1] = ((v.y - mean) * invv + 1e-5f) * sc.y + sh.y;
    o[2] = ((v.z - mean) * invv + 1e-5f) * sc.z + sh.z;
    o[3] = ((v.w - mean) * invv + 1e-5f) * sc.w + sh.w;
    HF4 H, L;
#pragma unroll
    for (int j = 0; j < 4; j++) split_f16(o[j], H.h[j], L.h[j]);
    ((uint2*)hi)[i4] = H.u;
    ((uint2*)lo)[i4] = L.u;
}

// ---------------- fp16 GEMM: C[M,N] = A[M,K]*B[N,K]^T ------------------------
// TWOPASS: A = Ah + Al; else A = Ah only. B = Bh always.
enum { MODE_BIAS_RES = 1, MODE_GELU_HI = 2, MODE_BIAS_SPLIT = 3 };

#define MM_SMEM2 49152
#define MM_SMEM1 32768

template <int MODE, bool TWOPASS>
__device__ __forceinline__ void gemm_body(
    const __half* __restrict__ Ah, const __half* __restrict__ Al,
    const __half* __restrict__ Bh,
    const float* __restrict__ bias, const float* __restrict__ res,
    float* __restrict__ C, __half* __restrict__ Oh, __half* __restrict__ Ol,
    int N, int K, float oscale, int bxx, int byy, char* smg) {
    constexpr uint32_t BOFF  = TWOPASS ? 16384 : 8192;
    constexpr uint32_t STAGE = TWOPASS ? 24576 : 16384;
    const uint32_t sb = smem_u32(smg);
    const int tid = threadIdx.x, wid = tid >> 5, lane = tid & 31;
    const int warpM = wid >> 2;
    const int warpN = wid & 3;
    const size_t rowA0 = (size_t)byy * 128;
    const size_t rowB0 = (size_t)bxx * 128;

    const int gi = tid & 3;
    const int r0 = tid >> 2;
    uint32_t so[2];
#pragma unroll
    for (int i = 0; i < 2; i++)
        so[i] = sw64((uint32_t)((r0 + 64 * i) * 64 + gi * 16));

    auto cpchunk = [&](int k0, int st) {
        uint32_t base = sb + st * STAGE;
#pragma unroll
        for (int i = 0; i < 2; i++) {
            int r = r0 + 64 * i;
            size_t oa = (rowA0 + r) * (size_t)K + k0 + gi * 8;
            size_t ob = (rowB0 + r) * (size_t)K + k0 + gi * 8;
            cp16(base + so[i], Ah + oa);
            if (TWOPASS) cp16(base + 8192 + so[i], Al + oa);
            cp16(base + BOFF + so[i], Bh + ob);
        }
        cp_commit();
    };

    float acc[4][4][4];
#pragma unroll
    for (int mi = 0; mi < 4; mi++)
#pragma unroll
        for (int ni = 0; ni < 4; ni++)
#pragma unroll
            for (int j = 0; j < 4; j++) acc[mi][ni][j] = 0.0f;

    const int NC = K / 32;
    cpchunk(0, 0);
    for (int c = 0; c < NC; ++c) {
        if (c + 1 < NC) { cpchunk((c + 1) * 32, (c + 1) & 1); cp_wait<1>(); }
        else            { cp_wait<0>(); }
        __syncthreads();

        uint32_t base = sb + (c & 1) * STAGE;
#pragma unroll
        for (int ks = 0; ks < 2; ks++) {
            uint32_t bh[4][2];
#pragma unroll
            for (int np = 0; np < 2; np++) {
                int row = warpN * 32 + np * 16 + (lane & 15);
                uint32_t sw = sw64((uint32_t)(row * 64 + ks * 32 + (lane & 16)));
                uint32_t t[4];
                ldmx4(t, base + BOFF + sw);
                bh[np * 2][0] = t[0]; bh[np * 2][1] = t[2];
                bh[np * 2 + 1][0] = t[1]; bh[np * 2 + 1][1] = t[3];
            }
#pragma unroll
            for (int mi = 0; mi < 4; mi++) {
                int row = warpM * 64 + mi * 16 + (lane & 15);
                uint32_t sw = sw64((uint32_t)(row * 64 + ks * 32 + (lane & 16)));
                uint32_t ah[4];
                ldmx4(ah, base + sw);
#pragma unroll
                for (int ni = 0; ni < 4; ni++)
                    mma_f16(acc[mi][ni], ah, bh[ni]);
                if (TWOPASS) {
                    uint32_t al[4];
                    ldmx4(al, base + 8192 + sw);
#pragma unroll
                    for (int ni = 0; ni < 4; ni++)
                        mma_f16(acc[mi][ni], al, bh[ni]);
                }
            }
        }
        __syncthreads();
    }

    const int rbase = (int)rowA0 + warpM * 64 + (lane >> 2);
    const int cbase = (int)rowB0 + warpN * 32 + (lane & 3) * 2;
#pragma unroll
    for (int mi = 0; mi < 4; mi++) {
#pragma unroll
        for (int ni = 0; ni < 4; ni++) {
            int cg = cbase + ni * 8;
            float2 bv = *(const float2*)(bias + cg);
#pragma unroll
            for (int h = 0; h < 2; h++) {
                int rg = rbase + mi * 16 + h * 8;
                float o0 = acc[mi][ni][2 * h]     + bv.x;
                float o1 = acc[mi][ni][2 * h + 1] + bv.y;
                size_t off = (size_t)rg * N + cg;
                if (MODE == MODE_BIAS_RES) {
                    float2 r = *(const float2*)(res + off);
                    o0 += r.x; o1 += r.y;
                    float2 w; w.x = o0; w.y = o1;
                    *(float2*)(C + off) = w;
                } else if (MODE == MODE_GELU_HI) {
                    float g0 = 0.5f * o0 * (1.0f + erff(o0 * 0.70710678118654752f));
                    float g1 = 0.5f * o1 * (1.0f + erff(o1 * 0.70710678118654752f));
                    HF2 H;
                    H.h[0] = __float2half_rn(g0);
                    H.h[1] = __float2half_rn(g1);
                    *(uint32_t*)(Oh + off) = H.u;
                } else {  // MODE_BIAS_SPLIT
                    float s0 = o0 * oscale, s1 = o1 * oscale;
                    HF2 H;
                    H.h[0] = __float2half_rn(s0);
                    H.h[1] = __float2half_rn(s1);
                    *(uint32_t*)(Oh + off) = H.u;
                    if (Ol) {
                        HF2 L;
                        L.h[0] = __float2half_rn(s0 - __half2float(H.h[0]));
                        L.h[1] = __float2half_rn(s1 - __half2float(H.h[1]));
                        *(uint32_t*)(Ol + off) = L.u;
                    }
                }
            }
        }
    }
}

template <int MODE, bool TWOPASS>
__global__ __launch_bounds__(256, 2)
void mmagemm_kernel(const __half* __restrict__ Ah, const __half* __restrict__ Al,
                    const __half* __restrict__ Bh,
                    const float* __restrict__ bias, const float* __restrict__ res,
                    float* __restrict__ C,
                    __half* __restrict__ Oh, __half* __restrict__ Ol,
                    int N, int K, float oscale) {
    extern __shared__ char smg[];
    gemm_body<MODE, TWOPASS>(Ah, Al, Bh, bias, res, C, Oh, Ol, N, K, oscale,
                             blockIdx.x, blockIdx.y, smg);
}

__global__ __launch_bounds__(256, 2)
void qkv_kernel(const __half* __restrict__ Ah, const __half* __restrict__ Al,
                const __half* __restrict__ Bq, const __half* __restrict__ Bk,
                const __half* __restrict__ Bv,
                const float* __restrict__ b0, const float* __restrict__ b1,
                const float* __restrict__ b2,
                __half* __restrict__ Qh, __half* __restrict__ Ql,
                __half* __restrict__ Kh, __half* __restrict__ Vh) {
    extern __shared__ char smg[];
    const int sel = blockIdx.x >> 3;
    const int bxx = blockIdx.x & 7;
    const __half* Bh = (sel == 0) ? Bq : (sel == 1) ? Bk : Bv;
    const float* bias = (sel == 0) ? b0 : (sel == 1) ? b1 : b2;
    __half* Oh = (sel == 0) ? Qh : (sel == 1) ? Kh : Vh;
    __half* Ol = (sel == 0) ? Ql : nullptr;
    const float sc = (sel == 0) ? 0.125f : 1.0f;
    gemm_body<MODE_BIAS_SPLIT, true>(Ah, Al, Bh, bias, nullptr, nullptr, Oh, Ol,
                                     EMB, EMB, sc, bxx, blockIdx.y, smg);
}

// ---------------- fp16 tensor-core causal flash attention --------------------
// S = 2-pass (Qh+Ql)·Kh ; PV = 1-pass Ph·Vh ; output ctx hi only.
#define ATT_SMEM 65536

__global__ __launch_bounds__(256)
void attn_tc_kernel(const __half* __restrict__ Qh_, const __half* __restrict__ Ql_,
                    const __half* __restrict__ Kh_, const __half* __restrict__ Vh_,
                    __half* __restrict__ Oh) {
    extern __shared__ char smg[];
    const uint32_t sb = smem_u32(smg);
    const int qt   = (TSEQ / 128 - 1) - blockIdx.x;
    const int bh   = blockIdx.y;
    const int bb   = bh >> 4;
    const int head = bh & 15;
    const int tid  = threadIdx.x;
    const int wid  = tid >> 5;
    const int lane = tid & 31;
    const size_t hoff = (size_t)head * 64;
    const size_t seq0 = (size_t)bb * TSEQ;

    const int gi  = tid & 7;
    const int r32 = tid >> 3;

    {
#pragma unroll
        for (int i = 0; i < 4; i++) {
            int r = r32 + 32 * i;
            size_t g = (seq0 + qt * 128 + r) * EMB + hoff + gi * 8;
            uint32_t sw = sw128((uint32_t)(r * 128 + gi * 16));
            cp16(sb + sw, Qh_ + g);
            cp16(sb + 16384 + sw, Ql_ + g);
        }
        cp_commit();
    }
    auto cpKV = [&](int kt, int st) {
        uint32_t base = sb + 32768 + st * 16384;
#pragma unroll
        for (int i = 0; i < 2; i++) {
            int r = r32 + 32 * i;
            size_t g = (seq0 + kt * 64 + r) * EMB + hoff + gi * 8;
            uint32_t sw = sw128((uint32_t)(r * 128 + gi * 16));
            cp16(base + sw, Kh_ + g);
            cp16(base + 8192 + sw, Vh_ + g);
        }
        cp_commit();
    };
    cpKV(0, 0);
    cp_wait<0>();
    __syncthreads();

    uint32_t qh[4][4], ql[4][4];
#pragma unroll
    for (int ks = 0; ks < 4; ks++) {
        int row = wid * 16 + (lane & 15);
        uint32_t sw = sw128((uint32_t)(row * 128 + ks * 32 + (lane & 16)));
        ldmx4(qh[ks], sb + sw);
        ldmx4(ql[ks], sb + 16384 + sw);
    }

    float oacc[8][4];
#pragma unroll
    for (int i = 0; i < 8; i++)
#pragma unroll
        for (int j = 0; j < 4; j++) oacc[i][j] = 0.0f;
    float m0 = -3.0e38f, m1 = -3.0e38f, l0 = 0.0f, l1 = 0.0f;

    const int gr0 = qt * 128 + wid * 16 + (lane >> 2);
    const int cq  = (lane & 3) * 2;
    const int ktlast = 2 * qt + 1;

    for (int kt = 0; kt <= ktlast; ++kt) {
        if (kt > 0) { cp_wait<0>(); __syncthreads(); }
        if (kt < ktlast) cpKV(kt + 1, (kt + 1) & 1);
        uint32_t base = sb + 32768 + (kt & 1) * 16384;

        if (kt * 64 > qt * 128 + wid * 16 + 15) continue;

        float sacc[8][4];
#pragma unroll
        for (int i = 0; i < 8; i++)
#pragma unroll
            for (int j = 0; j < 4; j++) sacc[i][j] = 0.0f;
#pragma unroll
        for (int ks = 0; ks < 4; ks++) {
            uint32_t kh[8][2];
#pragma unroll
            for (int kp = 0; kp < 4; kp++) {
                int row = kp * 16 + (lane & 15);
                uint32_t sw = sw128((uint32_t)(row * 128 + ks * 32 + (lane & 16)));
                uint32_t t[4];
                ldmx4(t, base + sw);
                kh[kp * 2][0] = t[0]; kh[kp * 2][1] = t[2];
                kh[kp * 2 + 1][0] = t[1]; kh[kp * 2 + 1][1] = t[3];
            }
#pragma unroll
            for (int nt = 0; nt < 8; nt++) {
                mma_f16(sacc[nt], qh[ks], kh[nt]);
                mma_f16(sacc[nt], ql[ks], kh[nt]);
            }
        }

        if (kt * 64 + 63 > qt * 128 + wid * 16) {
#pragma unroll
            for (int nt = 0; nt < 8; nt++) {
                int c0 = kt * 64 + nt * 8 + cq;
                if (c0 > gr0)     sacc[nt][0] = -1e30f;
                if (c0 + 1 > gr0) sacc[nt][1] = -1e30f;
                if (c0 > gr0 + 8)     sacc[nt][2] = -1e30f;
                if (c0 + 1 > gr0 + 8) sacc[nt][3] = -1e30f;
            }
        }

        float t0 = -3.0e38f, t1 = -3.0e38f;
#pragma unroll
        for (int nt = 0; nt < 8; nt++) {
            t0 = fmaxf(t0, fmaxf(sacc[nt][0], sacc[nt][1]));
            t1 = fmaxf(t1, fmaxf(sacc[nt][2], sacc[nt][3]));
        }
        t0 = fmaxf(t0, __shfl_xor_sync(0xffffffffu, t0, 1));
        t0 = fmaxf(t0, __shfl_xor_sync(0xffffffffu, t0, 2));
        t1 = fmaxf(t1, __shfl_xor_sync(0xffffffffu, t1, 1));
        t1 = fmaxf(t1, __shfl_xor_sync(0xffffffffu, t1, 2));
        float mn0 = fmaxf(m0, t0), mn1 = fmaxf(m1, t1);
        float al0 = __expf(m0 - mn0), al1 = __expf(m1 - mn1);
        m0 = mn0; m1 = mn1;

        uint32_t pH[8][2];
        float ps0 = 0.0f, ps1 = 0.0f;
#pragma unroll
        for (int nt = 0; nt < 8; nt++) {
            float p0 = __expf(sacc[nt][0] - mn0);
            float p1 = __expf(sacc[nt][1] - mn0);
            float p2 = __expf(sacc[nt][2] - mn1);
            float p3 = __expf(sacc[nt][3] - mn1);
            ps0 += p0 + p1; ps1 += p2 + p3;
            HF2 H;
            H.h[0] = __float2half_rn(p0);
            H.h[1] = __float2half_rn(p1);
            pH[nt][0] = H.u;
            H.h[0] = __float2half_rn(p2);
            H.h[1] = __float2half_rn(p3);
            pH[nt][1] = H.u;
        }
        ps0 += __shfl_xor_sync(0xffffffffu, ps0, 1);
        ps0 += __shfl_xor_sync(0xffffffffu, ps0, 2);
        ps1 += __shfl_xor_sync(0xffffffffu, ps1, 1);
        ps1 += __shfl_xor_sync(0xffffffffu, ps1, 2);
        l0 = l0 * al0 + ps0;
        l1 = l1 * al1 + ps1;

#pragma unroll
        for (int dt = 0; dt < 8; dt++) {
            oacc[dt][0] *= al0; oacc[dt][1] *= al0;
            oacc[dt][2] *= al1; oacc[dt][3] *= al1;
        }

#pragma unroll
        for (int ks = 0; ks < 4; ks++) {
            uint32_t aH[4] = { pH[2 * ks][0], pH[2 * ks][1], pH[2 * ks + 1][0], pH[2 * ks + 1][1] };
#pragma unroll
            for (int dp = 0; dp < 4; dp++) {
                uint32_t sw = sw128((uint32_t)((ks * 16 + (lane & 15)) * 128 + dp * 32 + (lane & 16)));
                uint32_t th[4];
                ldmx4t(th, base + 8192 + sw);
                uint32_t b0h[2] = { th[0], th[1] }, b1h[2] = { th[2], th[3] };
                mma_f16(oacc[2 * dp],     aH, b0h);
                mma_f16(oacc[2 * dp + 1], aH, b1h);
            }
        }
    }

    float inv0 = 1.0f / l0, inv1 = 1.0f / l1;
#pragma unroll
    for (int dt = 0; dt < 8; dt++) {
        int cg = dt * 8 + cq;
        size_t off0 = (seq0 + gr0) * EMB + hoff + cg;
        size_t off1 = (seq0 + gr0 + 8) * EMB + hoff + cg;
        HF2 H;
        H.h[0] = __float2half_rn(oacc[dt][0] * inv0);
        H.h[1] = __float2half_rn(oacc[dt][1] * inv0);
        *(uint32_t*)(Oh + off0) = H.u;
        H.h[0] = __float2half_rn(oacc[dt][2] * inv1);
        H.h[1] = __float2half_rn(oacc[dt][3] * inv1);
        *(uint32_t*)(Oh + off1) = H.u;
    }
}

// ---------------- orchestration ----------------------------------------------
extern "C" void kernel_launch(void* const* d_in, const int* in_sizes, int n_in,
                              void* d_out, int out_size) {
    (void)in_sizes; (void)n_in; (void)out_size;
    const float* x    = (const float*)d_in[0];
    const float* Wq_w = (const float*)d_in[1];
    const float* Wq_b = (const float*)d_in[2];
    const float* Wk_w = (const float*)d_in[3];
    const float* Wk_b = (const float*)d_in[4];
    const float* Wv_w = (const float*)d_in[5];
    const float* Wv_b = (const float*)d_in[6];
    const float* Wo_w = (const float*)d_in[7];
    const float* Wo_b = (const float*)d_in[8];
    const float* l1_w = (const float*)d_in[9];
    const float* l1_b = (const float*)d_in[10];
    const float* l2_w = (const float*)d_in[11];
    const float* l2_b = (const float*)d_in[12];
    const float* n1s  = (const float*)d_in[13];
    const float* n1b  = (const float*)d_in[14];
    const float* n2s  = (const float*)d_in[15];
    const float* n2b  = (const float*)d_in[16];
    float* out = (float*)d_out;

    float *x1, *rs, *rq, *var;
    cudaGetSymbolAddress((void**)&x1,  g_x1);
    cudaGetSymbolAddress((void**)&rs,  g_rowsum);
    cudaGetSymbolAddress((void**)&rq,  g_rowsq);
    cudaGetSymbolAddress((void**)&var, g_var);

    __half *h_hi, *h_lo, *ctx, *ff;
    __half *qh, *ql, *kh, *vh;
    __half *wq, *wk, *wv, *wo, *l1, *l2;
    cudaGetSymbolAddress((void**)&h_hi, g_h_hi);
    cudaGetSymbolAddress((void**)&h_lo, g_h_lo);
    cudaGetSymbolAddress((void**)&qh, g_qh);
    cudaGetSymbolAddress((void**)&ql, g_ql);
    cudaGetSymbolAddress((void**)&kh, g_kh);
    cudaGetSymbolAddress((void**)&vh, g_vh);
    cudaGetSymbolAddress((void**)&ctx, g_ctx);
    cudaGetSymbolAddress((void**)&ff, g_ff);
    cudaGetSymbolAddress((void**)&wq, g_wq);
    cudaGetSymbolAddress((void**)&wk, g_wk);
    cudaGetSymbolAddress((void**)&wv, g_wv);
    cudaGetSymbolAddress((void**)&wo, g_wo);
    cudaGetSymbolAddress((void**)&l1, g_l1);
    cudaGetSymbolAddress((void**)&l2, g_l2);

    cudaFuncSetAttribute((const void*)attn_tc_kernel,
                         cudaFuncAttributeMaxDynamicSharedMemorySize, ATT_SMEM);
    cudaFuncSetAttribute((const void*)qkv_kernel,
                         cudaFuncAttributeMaxDynamicSharedMemorySize, MM_SMEM2);
    cudaFuncSetAttribute((const void*)mmagemm_kernel<MODE_BIAS_RES, false>,
                         cudaFuncAttributeMaxDynamicSharedMemorySize, MM_SMEM1);
    cudaFuncSetAttribute((const void*)mmagemm_kernel<MODE_GELU_HI, true>,
                         cudaFuncAttributeMaxDynamicSharedMemorySize, MM_SMEM2);

    const int LN_BLOCKS = (N_TOK * EMB / 4) / 256;
    dim3 blk(256);
    dim3 gP(EMB / 128, N_TOK / 128);
    dim3 gF(DFF / 128, N_TOK / 128);
    dim3 gQKV(3 * EMB / 128, N_TOK / 128);

    // fused weight split (hi only)
    split_all_kernel<<<SPLIT_TOTAL4 / 256, 256>>>(Wq_w, Wk_w, Wv_w, Wo_w, l1_w, l2_w,
                                                  wq, wk, wv, wo, l1, l2);

    // LN1 -> h hi/lo
    rowstats_kernel<<<N_TOK, 256>>>(x, rs, rq);
    finalize_var_kernel<<<1, 256>>>(rs, rq, var);
    ln_apply_split_kernel<<<LN_BLOCKS, 256>>>(x, rs, var, n1s, n1b, h_hi, h_lo);

    // fused QKV projections (2-pass A; Q pre-scaled 1/8 hi+lo; K/V hi only)
    qkv_kernel<<<gQKV, blk, MM_SMEM2>>>(h_hi, h_lo, wq, wk, wv,
                                        Wq_b, Wk_b, Wv_b, qh, ql, kh, vh);

    // attention -> ctx (hi only)
    attn_tc_kernel<<<dim3(TSEQ / 128, 64), 256, ATT_SMEM>>>(qh, ql, kh, vh, ctx);

    // output projection + residual (1-pass A)
    mmagemm_kernel<MODE_BIAS_RES, false><<<gP, blk, MM_SMEM1>>>(
        ctx, nullptr, wo, Wo_b, x, x1, nullptr, nullptr, EMB, EMB, 1.0f);

    // LN2 -> h hi/lo
    rowstats_kernel<<<N_TOK, 256>>>(x1, rs, rq);
    finalize_var_kernel<<<1, 256>>>(rs, rq, var);
    ln_apply_split_kernel<<<LN_BLOCKS, 256>>>(x1, rs, var, n2s, n2b, h_hi, h_lo);

    // FFN: FF1 2-pass A (h), gelu -> ff hi only; FF2 1-pass A (ff)
    mmagemm_kernel<MODE_GELU_HI, true><<<gF, blk, MM_SMEM2>>>(
        h_hi, h_lo, l1, l1_b, nullptr, nullptr, ff, nullptr, DFF, EMB, 1.0f);
    mmagemm_kernel<MODE_BIAS_RES, false><<<gP, blk, MM_SMEM1>>>(
        ff, nullptr, l2, l2_b, x1, out, nullptr, nullptr, EMB, DFF, 1.0f);
}

// round 15
// speedup vs baseline: 8.5798x; 1.3465x over previous
#include <cuda_runtime.h>
#include <cuda_fp16.h>
#include <math.h>
#include <stdint.h>

#define N_TOK 8192
#define EMB   1024
#define DFF   4096
#define TSEQ  2048

// ---------------- scratch (device globals; no allocations allowed) ----------
__device__ float g_x1 [N_TOK * EMB];
__device__ float g_rowsum[N_TOK];
__device__ float g_rowsq [N_TOK];
__device__ float g_var[2];

__device__ __half g_h  [N_TOK * EMB];
__device__ __half g_qh [N_TOK * EMB];
__device__ __half g_kh [N_TOK * EMB];
__device__ __half g_vh [N_TOK * EMB];
__device__ __half g_ctx[N_TOK * EMB];
__device__ __half g_ff [N_TOK * DFF];
__device__ __half g_wq[EMB * EMB], g_wk[EMB * EMB], g_wv[EMB * EMB], g_wo[EMB * EMB];
__device__ __half g_l1[DFF * EMB], g_l2[EMB * DFF];

union HF2 { __half h[2]; uint32_t u; };
union HF4 { __half h[4]; uint2 u; };

__device__ __forceinline__ uint32_t smem_u32(const void* p) {
    uint32_t a;
    asm("{ .reg .u64 t; cvta.to.shared.u64 t, %1; cvt.u32.u64 %0, t; }" : "=r"(a) : "l"(p));
    return a;
}
__device__ __forceinline__ void cp16(uint32_t dst, const void* src) {
    asm volatile("cp.async.cg.shared.global [%0], [%1], 16;" :: "r"(dst), "l"(src) : "memory");
}
__device__ __forceinline__ void cp_commit() {
    asm volatile("cp.async.commit_group;" ::: "memory");
}
template <int N>
__device__ __forceinline__ void cp_wait() {
    asm volatile("cp.async.wait_group %0;" :: "n"(N) : "memory");
}
__device__ __forceinline__ void ldmx4(uint32_t* r, uint32_t addr) {
    asm volatile("ldmatrix.sync.aligned.m8n8.x4.shared.b16 {%0,%1,%2,%3}, [%4];"
                 : "=r"(r[0]), "=r"(r[1]), "=r"(r[2]), "=r"(r[3]) : "r"(addr));
}
__device__ __forceinline__ void ldmx4t(uint32_t* r, uint32_t addr) {
    asm volatile("ldmatrix.sync.aligned.m8n8.x4.trans.shared.b16 {%0,%1,%2,%3}, [%4];"
                 : "=r"(r[0]), "=r"(r[1]), "=r"(r[2]), "=r"(r[3]) : "r"(addr));
}
__device__ __forceinline__ void mma_f16(float* c, const uint32_t* a, const uint32_t* b) {
    asm volatile("mma.sync.aligned.m16n8k16.row.col.f32.f16.f16.f32 "
                 "{%0,%1,%2,%3}, {%4,%5,%6,%7}, {%8,%9}, {%0,%1,%2,%3};"
                 : "+f"(c[0]), "+f"(c[1]), "+f"(c[2]), "+f"(c[3])
                 : "r"(a[0]), "r"(a[1]), "r"(a[2]), "r"(a[3]), "r"(b[0]), "r"(b[1]));
}
__device__ __forceinline__ uint32_t sw128(uint32_t o) { return o ^ ((o >> 3) & 0x70); }
__device__ __forceinline__ uint32_t sw64(uint32_t o)  { return o ^ ((o >> 3) & 0x30); }

// ---------------- fused weight split (all 6 matrices, hi only) ---------------
#define SQ4 (EMB * EMB / 4)
#define SL4 (DFF * EMB / 4)
#define SPLIT_TOTAL4 (4 * SQ4 + 2 * SL4)

__global__ void split_all_kernel(const float* __restrict__ wq, const float* __restrict__ wk,
                                 const float* __restrict__ wv, const float* __restrict__ wo,
                                 const float* __restrict__ l1, const float* __restrict__ l2,
                                 __half* __restrict__ dq, __half* __restrict__ dk,
                                 __half* __restrict__ dv, __half* __restrict__ doo,
                                 __half* __restrict__ d1, __half* __restrict__ d2) {
    int i = blockIdx.x * blockDim.x + threadIdx.x;
    const float* src;
    __half* dst;
    int j;
    if (i < 4 * SQ4) {
        int m = i >> 18;
        j = i & (SQ4 - 1);
        src = (m == 0) ? wq : (m == 1) ? wk : (m == 2) ? wv : wo;
        dst = (m == 0) ? dq : (m == 1) ? dk : (m == 2) ? dv : doo;
    } else {
        int t = i - 4 * SQ4;
        if (t < SL4) { src = l1; dst = d1; j = t; }
        else         { src = l2; dst = d2; j = t - SL4; }
    }
    float4 v = ((const float4*)src)[j];
    HF4 H;
#pragma unroll
    for (int c = 0; c < 4; c++) H.h[c] = __float2half_rn((&v.x)[c]);
    ((uint2*)dst)[j] = H.u;
}

// ---------------- LN pieces ---------------------------------------------------
__global__ void rowstats_kernel(const float* __restrict__ x,
                                float* __restrict__ rowsum,
                                float* __restrict__ rowsq) {
    int row = blockIdx.x, tid = threadIdx.x;
    float4 v = *(const float4*)(x + (size_t)row * EMB + tid * 4);
    float s = v.x + v.y + v.z + v.w;
    float q = v.x * v.x + v.y * v.y + v.z * v.z + v.w * v.w;
#pragma unroll
    for (int o = 16; o > 0; o >>= 1) {
        s += __shfl_down_sync(0xffffffffu, s, o);
        q += __shfl_down_sync(0xffffffffu, q, o);
    }
    __shared__ float ss[8], qs[8];
    int w = tid >> 5, lane = tid & 31;
    if (lane == 0) { ss[w] = s; qs[w] = q; }
    __syncthreads();
    if (tid == 0) {
        float S = 0.f, Q = 0.f;
#pragma unroll
        for (int i = 0; i < 8; i++) { S += ss[i]; Q += qs[i]; }
        rowsum[row] = S; rowsq[row] = Q;
    }
}

__global__ void finalize_var_kernel(const float* __restrict__ rowsum,
                                    const float* __restrict__ rowsq,
                                    float* __restrict__ varout) {
    int tid = threadIdx.x;
    double s = 0.0, q = 0.0;
    for (int i = tid; i < N_TOK; i += 256) { s += (double)rowsum[i]; q += (double)rowsq[i]; }
#pragma unroll
    for (int o = 16; o > 0; o >>= 1) {
        s += __shfl_down_sync(0xffffffffu, s, o);
        q += __shfl_down_sync(0xffffffffu, q, o);
    }
    __shared__ double sd[8], qd[8];
    int w = tid >> 5, lane = tid & 31;
    if (lane == 0) { sd[w] = s; qd[w] = q; }
    __syncthreads();
    if (tid == 0) {
        double S = 0.0, Q = 0.0;
        for (int i = 0; i < 8; i++) { S += sd[i]; Q += qd[i]; }
        double M = (double)N_TOK * (double)EMB;
        double mean = S / M;
        varout[0] = (float)(Q / M - mean * mean);
    }
}

__global__ void ln_apply_hi_kernel(const float* __restrict__ x,
                                   const float* __restrict__ rowsum,
                                   const float* __restrict__ varp,
                                   const float* __restrict__ scale,
                                   const float* __restrict__ shift,
                                   __half* __restrict__ hi) {
    size_t i4 = (size_t)blockIdx.x * blockDim.x + threadIdx.x;
    size_t off = i4 * 4;
    int row = (int)(off >> 10), col = (int)(off & 1023);
    float invv = 1.0f / varp[0];
    float mean = rowsum[row] * (1.0f / 1024.0f);
    float4 v  = *(const float4*)(x + off);
    float4 sc = *(const float4*)(scale + col);
    float4 sh = *(const float4*)(shift + col);
    float o[4];
    o[0] = ((v.x - mean) * invv + 1e-5f) * sc.x + sh.x;
    o[1] = ((v.y - mean) * invv + 1e-5f) * sc.y + sh.y;
    o[2] = ((v.z - mean) * invv + 1e-5f) * sc.z + sh.z;
    o[3] = ((v.w - mean) * invv + 1e-5f) * sc.w + sh.w;
    HF4 H;
#pragma unroll
    for (int j = 0; j < 4; j++) H.h[j] = __float2half_rn(o[j]);
    ((uint2*)hi)[i4] = H.u;
}

// ---------------- fp16 1-pass GEMM: C[M,N] = A[M,K]*B[N,K]^T -----------------
enum { MODE_BIAS_RES = 1, MODE_GELU_HI = 2, MODE_BIAS_HI = 3 };

#define STAGE_BYTES 16384
#define MM_SMEM (2 * STAGE_BYTES)

template <int MODE>
__device__ __forceinline__ void gemm_body(
    const __half* __restrict__ Ah, const __half* __restrict__ Bh,
    const float* __restrict__ bias, const float* __restrict__ res,
    float* __restrict__ C, __half* __restrict__ Oh,
    int N, int K, float oscale, int bxx, int byy, char* smg) {
    const uint32_t sb = smem_u32(smg);
    const int tid = threadIdx.x, wid = tid >> 5, lane = tid & 31;
    const int warpM = wid >> 2;
    const int warpN = wid & 3;
    const size_t rowA0 = (size_t)byy * 128;
    const size_t rowB0 = (size_t)bxx * 128;

    const int gi = tid & 3;
    const int r0 = tid >> 2;
    uint32_t so[2];
#pragma unroll
    for (int i = 0; i < 2; i++)
        so[i] = sw64((uint32_t)((r0 + 64 * i) * 64 + gi * 16));

    auto cpchunk = [&](int k0, int st) {
        uint32_t base = sb + st * STAGE_BYTES;
#pragma unroll
        for (int i = 0; i < 2; i++) {
            int r = r0 + 64 * i;
            size_t oa = (rowA0 + r) * (size_t)K + k0 + gi * 8;
            size_t ob = (rowB0 + r) * (size_t)K + k0 + gi * 8;
            cp16(base + so[i], Ah + oa);
            cp16(base + 8192 + so[i], Bh + ob);
        }
        cp_commit();
    };

    float acc[4][4][4];
#pragma unroll
    for (int mi = 0; mi < 4; mi++)
#pragma unroll
        for (int ni = 0; ni < 4; ni++)
#pragma unroll
            for (int j = 0; j < 4; j++) acc[mi][ni][j] = 0.0f;

    const int NC = K / 32;
    cpchunk(0, 0);
    for (int c = 0; c < NC; ++c) {
        if (c + 1 < NC) { cpchunk((c + 1) * 32, (c + 1) & 1); cp_wait<1>(); }
        else            { cp_wait<0>(); }
        __syncthreads();

        uint32_t base = sb + (c & 1) * STAGE_BYTES;
#pragma unroll
        for (int ks = 0; ks < 2; ks++) {
            uint32_t bh[4][2];
#pragma unroll
            for (int np = 0; np < 2; np++) {
                int row = warpN * 32 + np * 16 + (lane & 15);
                uint32_t sw = sw64((uint32_t)(row * 64 + ks * 32 + (lane & 16)));
                uint32_t t[4];
                ldmx4(t, base + 8192 + sw);
                bh[np * 2][0] = t[0]; bh[np * 2][1] = t[2];
                bh[np * 2 + 1][0] = t[1]; bh[np * 2 + 1][1] = t[3];
            }
#pragma unroll
            for (int mi = 0; mi < 4; mi++) {
                int row = warpM * 64 + mi * 16 + (lane & 15);
                uint32_t sw = sw64((uint32_t)(row * 64 + ks * 32 + (lane & 16)));
                uint32_t ah[4];
                ldmx4(ah, base + sw);
#pragma unroll
                for (int ni = 0; ni < 4; ni++)
                    mma_f16(acc[mi][ni], ah, bh[ni]);
            }
        }
        __syncthreads();
    }

    const int rbase = (int)rowA0 + warpM * 64 + (lane >> 2);
    const int cbase = (int)rowB0 + warpN * 32 + (lane & 3) * 2;
#pragma unroll
    for (int mi = 0; mi < 4; mi++) {
#pragma unroll
        for (int ni = 0; ni < 4; ni++) {
            int cg = cbase + ni * 8;
            float2 bv = *(const float2*)(bias + cg);
#pragma unroll
            for (int h = 0; h < 2; h++) {
                int rg = rbase + mi * 16 + h * 8;
                float o0 = acc[mi][ni][2 * h]     + bv.x;
                float o1 = acc[mi][ni][2 * h + 1] + bv.y;
                size_t off = (size_t)rg * N + cg;
                if (MODE == MODE_BIAS_RES) {
                    float2 r = *(const float2*)(res + off);
                    o0 += r.x; o1 += r.y;
                    float2 w; w.x = o0; w.y = o1;
                    *(float2*)(C + off) = w;
                } else if (MODE == MODE_GELU_HI) {
                    float g0 = 0.5f * o0 * (1.0f + erff(o0 * 0.70710678118654752f));
                    float g1 = 0.5f * o1 * (1.0f + erff(o1 * 0.70710678118654752f));
                    HF2 H;
                    H.h[0] = __float2half_rn(g0);
                    H.h[1] = __float2half_rn(g1);
                    *(uint32_t*)(Oh + off) = H.u;
                } else {  // MODE_BIAS_HI
                    HF2 H;
                    H.h[0] = __float2half_rn(o0 * oscale);
                    H.h[1] = __float2half_rn(o1 * oscale);
                    *(uint32_t*)(Oh + off) = H.u;
                }
            }
        }
    }
}

template <int MODE>
__global__ __launch_bounds__(256, 2)
void mmagemm_kernel(const __half* __restrict__ Ah, const __half* __restrict__ Bh,
                    const float* __restrict__ bias, const float* __restrict__ res,
                    float* __restrict__ C, __half* __restrict__ Oh,
                    int N, int K, float oscale) {
    extern __shared__ char smg[];
    gemm_body<MODE>(Ah, Bh, bias, res, C, Oh, N, K, oscale,
                    blockIdx.x, blockIdx.y, smg);
}

// fused QKV (1-pass): blockIdx.x in [0,24): sel = x>>3, col block = x&7
__global__ __launch_bounds__(256, 2)
void qkv_kernel(const __half* __restrict__ Ah,
                const __half* __restrict__ Bq, const __half* __restrict__ Bk,
                const __half* __restrict__ Bv,
                const float* __restrict__ b0, const float* __restrict__ b1,
                const float* __restrict__ b2,
                __half* __restrict__ Qh, __half* __restrict__ Kh,
                __half* __restrict__ Vh) {
    extern __shared__ char smg[];
    const int sel = blockIdx.x >> 3;
    const int bxx = blockIdx.x & 7;
    const __half* Bh = (sel == 0) ? Bq : (sel == 1) ? Bk : Bv;
    const float* bias = (sel == 0) ? b0 : (sel == 1) ? b1 : b2;
    __half* Oh = (sel == 0) ? Qh : (sel == 1) ? Kh : Vh;
    const float sc = (sel == 0) ? 0.125f : 1.0f;
    gemm_body<MODE_BIAS_HI>(Ah, Bh, bias, nullptr, nullptr, Oh,
                            EMB, EMB, sc, bxx, blockIdx.y, smg);
}

// ---------------- plain fp16 tensor-core causal flash attention --------------
// smem: Q 0 (16K); stages at 16384 + st*16384: Kh +0 (8K), Vh +8192. Total 48K.
#define ATT_SMEM 49152

__global__ __launch_bounds__(256)
void attn_tc_kernel(const __half* __restrict__ Qh_, const __half* __restrict__ Kh_,
                    const __half* __restrict__ Vh_, __half* __restrict__ Oh) {
    extern __shared__ char smg[];
    const uint32_t sb = smem_u32(smg);
    const int qt   = (TSEQ / 128 - 1) - blockIdx.x;
    const int bh   = blockIdx.y;
    const int bb   = bh >> 4;
    const int head = bh & 15;
    const int tid  = threadIdx.x;
    const int wid  = tid >> 5;
    const int lane = tid & 31;
    const size_t hoff = (size_t)head * 64;
    const size_t seq0 = (size_t)bb * TSEQ;

    const int gi  = tid & 7;
    const int r32 = tid >> 3;

    {
#pragma unroll
        for (int i = 0; i < 4; i++) {
            int r = r32 + 32 * i;
            size_t g = (seq0 + qt * 128 + r) * EMB + hoff + gi * 8;
            uint32_t sw = sw128((uint32_t)(r * 128 + gi * 16));
            cp16(sb + sw, Qh_ + g);
        }
        cp_commit();
    }
    auto cpKV = [&](int kt, int st) {
        uint32_t base = sb + 16384 + st * 16384;
#pragma unroll
        for (int i = 0; i < 2; i++) {
            int r = r32 + 32 * i;
            size_t g = (seq0 + kt * 64 + r) * EMB + hoff + gi * 8;
            uint32_t sw = sw128((uint32_t)(r * 128 + gi * 16));
            cp16(base + sw, Kh_ + g);
            cp16(base + 8192 + sw, Vh_ + g);
        }
        cp_commit();
    };
    cpKV(0, 0);
    cp_wait<0>();
    __syncthreads();

    uint32_t qh[4][4];
#pragma unroll
    for (int ks = 0; ks < 4; ks++) {
        int row = wid * 16 + (lane & 15);
        uint32_t sw = sw128((uint32_t)(row * 128 + ks * 32 + (lane & 16)));
        ldmx4(qh[ks], sb + sw);
    }

    float oacc[8][4];
#pragma unroll
    for (int i = 0; i < 8; i++)
#pragma unroll
        for (int j = 0; j < 4; j++) oacc[i][j] = 0.0f;
    float m0 = -3.0e38f, m1 = -3.0e38f, l0 = 0.0f, l1 = 0.0f;

    const int gr0 = qt * 128 + wid * 16 + (lane >> 2);
    const int cq  = (lane & 3) * 2;
    const int ktlast = 2 * qt + 1;

    for (int kt = 0; kt <= ktlast; ++kt) {
        if (kt > 0) { cp_wait<0>(); __syncthreads(); }
        if (kt < ktlast) cpKV(kt + 1, (kt + 1) & 1);
        uint32_t base = sb + 16384 + (kt & 1) * 16384;

        if (kt * 64 > qt * 128 + wid * 16 + 15) continue;

        // ---- S = Q K^T (1-pass) ----
        float sacc[8][4];
#pragma unroll
        for (int i = 0; i < 8; i++)
#pragma unroll
            for (int j = 0; j < 4; j++) sacc[i][j] = 0.0f;
#pragma unroll
        for (int ks = 0; ks < 4; ks++) {
            uint32_t kh[8][2];
#pragma unroll
            for (int kp = 0; kp < 4; kp++) {
                int row = kp * 16 + (lane & 15);
                uint32_t sw = sw128((uint32_t)(row * 128 + ks * 32 + (lane & 16)));
                uint32_t t[4];
                ldmx4(t, base + sw);
                kh[kp * 2][0] = t[0]; kh[kp * 2][1] = t[2];
                kh[kp * 2 + 1][0] = t[1]; kh[kp * 2 + 1][1] = t[3];
            }
#pragma unroll
            for (int nt = 0; nt < 8; nt++)
                mma_f16(sacc[nt], qh[ks], kh[nt]);
        }

        if (kt * 64 + 63 > qt * 128 + wid * 16) {
#pragma unroll
            for (int nt = 0; nt < 8; nt++) {
                int c0 = kt * 64 + nt * 8 + cq;
                if (c0 > gr0)     sacc[nt][0] = -1e30f;
                if (c0 + 1 > gr0) sacc[nt][1] = -1e30f;
                if (c0 > gr0 + 8)     sacc[nt][2] = -1e30f;
                if (c0 + 1 > gr0 + 8) sacc[nt][3] = -1e30f;
            }
        }

        // ---- online softmax ----
        float t0 = -3.0e38f, t1 = -3.0e38f;
#pragma unroll
        for (int nt = 0; nt < 8; nt++) {
            t0 = fmaxf(t0, fmaxf(sacc[nt][0], sacc[nt][1]));
            t1 = fmaxf(t1, fmaxf(sacc[nt][2], sacc[nt][3]));
        }
        t0 = fmaxf(t0, __shfl_xor_sync(0xffffffffu, t0, 1));
        t0 = fmaxf(t0, __shfl_xor_sync(0xffffffffu, t0, 2));
        t1 = fmaxf(t1, __shfl_xor_sync(0xffffffffu, t1, 1));
        t1 = fmaxf(t1, __shfl_xor_sync(0xffffffffu, t1, 2));
        float mn0 = fmaxf(m0, t0), mn1 = fmaxf(m1, t1);
        float al0 = __expf(m0 - mn0), al1 = __expf(m1 - mn1);
        m0 = mn0; m1 = mn1;

        uint32_t pH[8][2];
        float ps0 = 0.0f, ps1 = 0.0f;
#pragma unroll
        for (int nt = 0; nt < 8; nt++) {
            float p0 = __expf(sacc[nt][0] - mn0);
            float p1 = __expf(sacc[nt][1] - mn0);
            float p2 = __expf(sacc[nt][2] - mn1);
            float p3 = __expf(sacc[nt][3] - mn1);
            ps0 += p0 + p1; ps1 += p2 + p3;
            HF2 H;
            H.h[0] = __float2half_rn(p0);
            H.h[1] = __float2half_rn(p1);
            pH[nt][0] = H.u;
            H.h[0] = __float2half_rn(p2);
            H.h[1] = __float2half_rn(p3);
            pH[nt][1] = H.u;
        }
        ps0 += __shfl_xor_sync(0xffffffffu, ps0, 1);
        ps0 += __shfl_xor_sync(0xffffffffu, ps0, 2);
        ps1 += __shfl_xor_sync(0xffffffffu, ps1, 1);
        ps1 += __shfl_xor_sync(0xffffffffu, ps1, 2);
        l0 = l0 * al0 + ps0;
        l1 = l1 * al1 + ps1;

#pragma unroll
        for (int dt = 0; dt < 8; dt++) {
            oacc[dt][0] *= al0; oacc[dt][1] *= al0;
            oacc[dt][2] *= al1; oacc[dt][3] *= al1;
        }

        // ---- PV (1-pass) ----
#pragma unroll
        for (int ks = 0; ks < 4; ks++) {
            uint32_t aH[4] = { pH[2 * ks][0], pH[2 * ks][1], pH[2 * ks + 1][0], pH[2 * ks + 1][1] };
#pragma unroll
            for (int dp = 0; dp < 4; dp++) {
                uint32_t sw = sw128((uint32_t)((ks * 16 + (lane & 15)) * 128 + dp * 32 + (lane & 16)));
                uint32_t th[4];
                ldmx4t(th, base + 8192 + sw);
                uint32_t b0h[2] = { th[0], th[1] }, b1h[2] = { th[2], th[3] };
                mma_f16(oacc[2 * dp],     aH, b0h);
                mma_f16(oacc[2 * dp + 1], aH, b1h);
            }
        }
    }

    float inv0 = 1.0f / l0, inv1 = 1.0f / l1;
#pragma unroll
    for (int dt = 0; dt < 8; dt++) {
        int cg = dt * 8 + cq;
        size_t off0 = (seq0 + gr0) * EMB + hoff + cg;
        size_t off1 = (seq0 + gr0 + 8) * EMB + hoff + cg;
        HF2 H;
        H.h[0] = __float2half_rn(oacc[dt][0] * inv0);
        H.h[1] = __float2half_rn(oacc[dt][1] * inv0);
        *(uint32_t*)(Oh + off0) = H.u;
        H.h[0] = __float2half_rn(oacc[dt][2] * inv1);
        H.h[1] = __float2half_rn(oacc[dt][3] * inv1);
        *(uint32_t*)(Oh + off1) = H.u;
    }
}

// ---------------- orchestration ----------------------------------------------
extern "C" void kernel_launch(void* const* d_in, const int* in_sizes, int n_in,
                              void* d_out, int out_size) {
    (void)in_sizes; (void)n_in; (void)out_size;
    const float* x    = (const float*)d_in[0];
    const float* Wq_w = (const float*)d_in[1];
    const float* Wq_b = (const float*)d_in[2];
    const float* Wk_w = (const float*)d_in[3];
    const float* Wk_b = (const float*)d_in[4];
    const float* Wv_w = (const float*)d_in[5];
    const float* Wv_b = (const float*)d_in[6];
    const float* Wo_w = (const float*)d_in[7];
    const float* Wo_b = (const float*)d_in[8];
    const float* l1_w = (const float*)d_in[9];
    const float* l1_b = (const float*)d_in[10];
    const float* l2_w = (const float*)d_in[11];
    const float* l2_b = (const float*)d_in[12];
    const float* n1s  = (const float*)d_in[13];
    const float* n1b  = (const float*)d_in[14];
    const float* n2s  = (const float*)d_in[15];
    const float* n2b  = (const float*)d_in[16];
    float* out = (float*)d_out;

    float *x1, *rs, *rq, *var;
    cudaGetSymbolAddress((void**)&x1,  g_x1);
    cudaGetSymbolAddress((void**)&rs,  g_rowsum);
    cudaGetSymbolAddress((void**)&rq,  g_rowsq);
    cudaGetSymbolAddress((void**)&var, g_var);

    __half *h, *ctx, *ff, *qh, *kh, *vh;
    __half *wq, *wk, *wv, *wo, *l1, *l2;
    cudaGetSymbolAddress((void**)&h,  g_h);
    cudaGetSymbolAddress((void**)&qh, g_qh);
    cudaGetSymbolAddress((void**)&kh, g_kh);
    cudaGetSymbolAddress((void**)&vh, g_vh);
    cudaGetSymbolAddress((void**)&ctx, g_ctx);
    cudaGetSymbolAddress((void**)&ff, g_ff);
    cudaGetSymbolAddress((void**)&wq, g_wq);
    cudaGetSymbolAddress((void**)&wk, g_wk);
    cudaGetSymbolAddress((void**)&wv, g_wv);
    cudaGetSymbolAddress((void**)&wo, g_wo);
    cudaGetSymbolAddress((void**)&l1, g_l1);
    cudaGetSymbolAddress((void**)&l2, g_l2);

    cudaFuncSetAttribute((const void*)attn_tc_kernel,
                         cudaFuncAttributeMaxDynamicSharedMemorySize, ATT_SMEM);
    cudaFuncSetAttribute((const void*)qkv_kernel,
                         cudaFuncAttributeMaxDynamicSharedMemorySize, MM_SMEM);
    cudaFuncSetAttribute((const void*)mmagemm_kernel<MODE_BIAS_RES>,
                         cudaFuncAttributeMaxDynamicSharedMemorySize, MM_SMEM);
    cudaFuncSetAttribute((const void*)mmagemm_kernel<MODE_GELU_HI>,
                         cudaFuncAttributeMaxDynamicSharedMemorySize, MM_SMEM);

    const int LN_BLOCKS = (N_TOK * EMB / 4) / 256;
    dim3 blk(256);
    dim3 gP(EMB / 128, N_TOK / 128);
    dim3 gF(DFF / 128, N_TOK / 128);
    dim3 gQKV(3 * EMB / 128, N_TOK / 128);

    // fused weight split (hi only)
    split_all_kernel<<<SPLIT_TOTAL4 / 256, 256>>>(Wq_w, Wk_w, Wv_w, Wo_w, l1_w, l2_w,
                                                  wq, wk, wv, wo, l1, l2);

    // LN1 -> h (hi only)
    rowstats_kernel<<<N_TOK, 256>>>(x, rs, rq);
    finalize_var_kernel<<<1, 256>>>(rs, rq, var);
    ln_apply_hi_kernel<<<LN_BLOCKS, 256>>>(x, rs, var, n1s, n1b, h);

    // fused QKV projections (1-pass; Q pre-scaled 1/8)
    qkv_kernel<<<gQKV, blk, MM_SMEM>>>(h, wq, wk, wv, Wq_b, Wk_b, Wv_b, qh, kh, vh);

    // attention -> ctx
    attn_tc_kernel<<<dim3(TSEQ / 128, 64), 256, ATT_SMEM>>>(qh, kh, vh, ctx);

    // output projection + residual
    mmagemm_kernel<MODE_BIAS_RES><<<gP, blk, MM_SMEM>>>(
        ctx, wo, Wo_b, x, x1, nullptr, EMB, EMB, 1.0f);

    // LN2 -> h (hi only)
    rowstats_kernel<<<N_TOK, 256>>>(x1, rs, rq);
    finalize_var_kernel<<<1, 256>>>(rs, rq, var);
    ln_apply_hi_kernel<<<LN_BLOCKS, 256>>>(x1, rs, var, n2s, n2b, h);

    // FFN
    mmagemm_kernel<MODE_GELU_HI><<<gF, blk, MM_SMEM>>>(
        h, l1, l1_b, nullptr, nullptr, ff, DFF, EMB, 1.0f);
    mmagemm_kernel<MODE_BIAS_RES><<<gP, blk, MM_SMEM>>>(
        ff, l2, l2_b, x1, out, nullptr, EMB, DFF, 1.0f);
}

// round 16
// speedup vs baseline: 9.1524x; 1.0667x over previous
#include <cuda_runtime.h>
#include <cuda_fp16.h>
#include <math.h>
#include <stdint.h>

#define N_TOK 8192
#define EMB   1024
#define DFF   4096
#define TSEQ  2048

// ---------------- scratch (device globals; no allocations allowed) ----------
__device__ float g_x1 [N_TOK * EMB];
__device__ float g_rowsum[N_TOK];
__device__ float g_rowsq [N_TOK];
__device__ float g_var[2];

__device__ __half g_h  [N_TOK * EMB];
__device__ __half g_qh [N_TOK * EMB];
__device__ __half g_kh [N_TOK * EMB];
__device__ __half g_vh [N_TOK * EMB];
__device__ __half g_ctx[N_TOK * EMB];
__device__ __half g_ff [N_TOK * DFF];
__device__ __half g_wq[EMB * EMB], g_wk[EMB * EMB], g_wv[EMB * EMB], g_wo[EMB * EMB];
__device__ __half g_l1[DFF * EMB], g_l2[EMB * DFF];

union HF2 { __half h[2]; uint32_t u; };
union HF4 { __half h[4]; uint2 u; };

__device__ __forceinline__ uint32_t smem_u32(const void* p) {
    uint32_t a;
    asm("{ .reg .u64 t; cvta.to.shared.u64 t, %1; cvt.u32.u64 %0, t; }" : "=r"(a) : "l"(p));
    return a;
}
__device__ __forceinline__ void cp16(uint32_t dst, const void* src) {
    asm volatile("cp.async.cg.shared.global [%0], [%1], 16;" :: "r"(dst), "l"(src) : "memory");
}
__device__ __forceinline__ void cp_commit() {
    asm volatile("cp.async.commit_group;" ::: "memory");
}
template <int N>
__device__ __forceinline__ void cp_wait() {
    asm volatile("cp.async.wait_group %0;" :: "n"(N) : "memory");
}
__device__ __forceinline__ void ldmx4(uint32_t* r, uint32_t addr) {
    asm volatile("ldmatrix.sync.aligned.m8n8.x4.shared.b16 {%0,%1,%2,%3}, [%4];"
                 : "=r"(r[0]), "=r"(r[1]), "=r"(r[2]), "=r"(r[3]) : "r"(addr));
}
__device__ __forceinline__ void ldmx4t(uint32_t* r, uint32_t addr) {
    asm volatile("ldmatrix.sync.aligned.m8n8.x4.trans.shared.b16 {%0,%1,%2,%3}, [%4];"
                 : "=r"(r[0]), "=r"(r[1]), "=r"(r[2]), "=r"(r[3]) : "r"(addr));
}
__device__ __forceinline__ void mma_f16(float* c, const uint32_t* a, const uint32_t* b) {
    asm volatile("mma.sync.aligned.m16n8k16.row.col.f32.f16.f16.f32 "
                 "{%0,%1,%2,%3}, {%4,%5,%6,%7}, {%8,%9}, {%0,%1,%2,%3};"
                 : "+f"(c[0]), "+f"(c[1]), "+f"(c[2]), "+f"(c[3])
                 : "r"(a[0]), "r"(a[1]), "r"(a[2]), "r"(a[3]), "r"(b[0]), "r"(b[1]));
}
__device__ __forceinline__ uint32_t sw128(uint32_t o) { return o ^ ((o >> 3) & 0x70); }

// ---------------- fused weight split (all 6 matrices, hi only) ---------------
#define SQ4 (EMB * EMB / 4)
#define SL4 (DFF * EMB / 4)
#define SPLIT_TOTAL4 (4 * SQ4 + 2 * SL4)

__global__ void split_all_kernel(const float* __restrict__ wq, const float* __restrict__ wk,
                                 const float* __restrict__ wv, const float* __restrict__ wo,
                                 const float* __restrict__ l1, const float* __restrict__ l2,
                                 __half* __restrict__ dq, __half* __restrict__ dk,
                                 __half* __restrict__ dv, __half* __restrict__ doo,
                                 __half* __restrict__ d1, __half* __restrict__ d2) {
    int i = blockIdx.x * blockDim.x + threadIdx.x;
    const float* src;
    __half* dst;
    int j;
    if (i < 4 * SQ4) {
        int m = i >> 18;
        j = i & (SQ4 - 1);
        src = (m == 0) ? wq : (m == 1) ? wk : (m == 2) ? wv : wo;
        dst = (m == 0) ? dq : (m == 1) ? dk : (m == 2) ? dv : doo;
    } else {
        int t = i - 4 * SQ4;
        if (t < SL4) { src = l1; dst = d1; j = t; }
        else         { src = l2; dst = d2; j = t - SL4; }
    }
    float4 v = ((const float4*)src)[j];
    HF4 H;
#pragma unroll
    for (int c = 0; c < 4; c++) H.h[c] = __float2half_rn((&v.x)[c]);
    ((uint2*)dst)[j] = H.u;
}

// ---------------- LN pieces ---------------------------------------------------
__global__ void rowstats_kernel(const float* __restrict__ x,
                                float* __restrict__ rowsum,
                                float* __restrict__ rowsq) {
    int row = blockIdx.x, tid = threadIdx.x;
    float4 v = *(const float4*)(x + (size_t)row * EMB + tid * 4);
    float s = v.x + v.y + v.z + v.w;
    float q = v.x * v.x + v.y * v.y + v.z * v.z + v.w * v.w;
#pragma unroll
    for (int o = 16; o > 0; o >>= 1) {
        s += __shfl_down_sync(0xffffffffu, s, o);
        q += __shfl_down_sync(0xffffffffu, q, o);
    }
    __shared__ float ss[8], qs[8];
    int w = tid >> 5, lane = tid & 31;
    if (lane == 0) { ss[w] = s; qs[w] = q; }
    __syncthreads();
    if (tid == 0) {
        float S = 0.f, Q = 0.f;
#pragma unroll
        for (int i = 0; i < 8; i++) { S += ss[i]; Q += qs[i]; }
        rowsum[row] = S; rowsq[row] = Q;
    }
}

__global__ void finalize_var_kernel(const float* __restrict__ rowsum,
                                    const float* __restrict__ rowsq,
                                    float* __restrict__ varout) {
    int tid = threadIdx.x;
    double s = 0.0, q = 0.0;
    for (int i = tid; i < N_TOK; i += 256) { s += (double)rowsum[i]; q += (double)rowsq[i]; }
#pragma unroll
    for (int o = 16; o > 0; o >>= 1) {
        s += __shfl_down_sync(0xffffffffu, s, o);
        q += __shfl_down_sync(0xffffffffu, q, o);
    }
    __shared__ double sd[8], qd[8];
    int w = tid >> 5, lane = tid & 31;
    if (lane == 0) { sd[w] = s; qd[w] = q; }
    __syncthreads();
    if (tid == 0) {
        double S = 0.0, Q = 0.0;
        for (int i = 0; i < 8; i++) { S += sd[i]; Q += qd[i]; }
        double M = (double)N_TOK * (double)EMB;
        double mean = S / M;
        varout[0] = (float)(Q / M - mean * mean);
    }
}

__global__ void ln_apply_hi_kernel(const float* __restrict__ x,
                                   const float* __restrict__ rowsum,
                                   const float* __restrict__ varp,
                                   const float* __restrict__ scale,
                                   const float* __restrict__ shift,
                                   __half* __restrict__ hi) {
    size_t i4 = (size_t)blockIdx.x * blockDim.x + threadIdx.x;
    size_t off = i4 * 4;
    int row = (int)(off >> 10), col = (int)(off & 1023);
    float invv = 1.0f / varp[0];
    float mean = rowsum[row] * (1.0f / 1024.0f);
    float4 v  = *(const float4*)(x + off);
    float4 sc = *(const float4*)(scale + col);
    float4 sh = *(const float4*)(shift + col);
    float o[4];
    o[0] = ((v.x - mean) * invv + 1e-5f) * sc.x + sh.x;
    o[1] = ((v.y - mean) * invv + 1e-5f) * sc.y + sh.y;
    o[2] = ((v.z - mean) * invv + 1e-5f) * sc.z + sh.z;
    o[3] = ((v.w - mean) * invv + 1e-5f) * sc.w + sh.w;
    HF4 H;
#pragma unroll
    for (int j = 0; j < 4; j++) H.h[j] = __float2half_rn(o[j]);
    ((uint2*)hi)[i4] = H.u;
}

// ---------------- fp16 1-pass GEMM, BK=64: C[M,N] = A[M,K]*B[N,K]^T ----------
enum { MODE_BIAS_RES = 1, MODE_GELU_HI = 2, MODE_BIAS_HI = 3 };

#define STAGE_BYTES 32768
#define MM_SMEM (2 * STAGE_BYTES)

template <int MODE>
__device__ __forceinline__ void gemm_body(
    const __half* __restrict__ Ah, const __half* __restrict__ Bh,
    const float* __restrict__ bias, const float* __restrict__ res,
    float* __restrict__ C, __half* __restrict__ Oh,
    int N, int K, float oscale, int bxx, int byy, char* smg) {
    const uint32_t sb = smem_u32(smg);
    const int tid = threadIdx.x, wid = tid >> 5, lane = tid & 31;
    const int warpM = wid >> 2;
    const int warpN = wid & 3;
    const size_t rowA0 = (size_t)byy * 128;
    const size_t rowB0 = (size_t)bxx * 128;

    // staging: 128B rows (64 halfs); gi = tid&7 (16B group), r0 = tid>>3 (0..31)
    const int gi = tid & 7;
    const int r0 = tid >> 3;
    uint32_t so[4];
#pragma unroll
    for (int i = 0; i < 4; i++)
        so[i] = sw128((uint32_t)((r0 + 32 * i) * 128 + gi * 16));

    auto cpchunk = [&](int k0, int st) {
        uint32_t base = sb + st * STAGE_BYTES;
#pragma unroll
        for (int i = 0; i < 4; i++) {
            int r = r0 + 32 * i;
            size_t oa = (rowA0 + r) * (size_t)K + k0 + gi * 8;
            size_t ob = (rowB0 + r) * (size_t)K + k0 + gi * 8;
            cp16(base + so[i], Ah + oa);
            cp16(base + 16384 + so[i], Bh + ob);
        }
        cp_commit();
    };

    float acc[4][4][4];
#pragma unroll
    for (int mi = 0; mi < 4; mi++)
#pragma unroll
        for (int ni = 0; ni < 4; ni++)
#pragma unroll
            for (int j = 0; j < 4; j++) acc[mi][ni][j] = 0.0f;

    const int NC = K / 64;
    cpchunk(0, 0);
    for (int c = 0; c < NC; ++c) {
        if (c + 1 < NC) { cpchunk((c + 1) * 64, (c + 1) & 1); cp_wait<1>(); }
        else            { cp_wait<0>(); }
        __syncthreads();

        uint32_t base = sb + (c & 1) * STAGE_BYTES;
#pragma unroll
        for (int ks = 0; ks < 4; ks++) {
            uint32_t bh[4][2];
#pragma unroll
            for (int np = 0; np < 2; np++) {
                int row = warpN * 32 + np * 16 + (lane & 15);
                uint32_t sw = sw128((uint32_t)(row * 128 + ks * 32 + (lane & 16)));
                uint32_t t[4];
                ldmx4(t, base + 16384 + sw);
                bh[np * 2][0] = t[0]; bh[np * 2][1] = t[2];
                bh[np * 2 + 1][0] = t[1]; bh[np * 2 + 1][1] = t[3];
            }
#pragma unroll
            for (int mi = 0; mi < 4; mi++) {
                int row = warpM * 64 + mi * 16 + (lane & 15);
                uint32_t sw = sw128((uint32_t)(row * 128 + ks * 32 + (lane & 16)));
                uint32_t ah[4];
                ldmx4(ah, base + sw);
#pragma unroll
                for (int ni = 0; ni < 4; ni++)
                    mma_f16(acc[mi][ni], ah, bh[ni]);
            }
        }
        __syncthreads();
    }

    const int rbase = (int)rowA0 + warpM * 64 + (lane >> 2);
    const int cbase = (int)rowB0 + warpN * 32 + (lane & 3) * 2;
#pragma unroll
    for (int mi = 0; mi < 4; mi++) {
#pragma unroll
        for (int ni = 0; ni < 4; ni++) {
            int cg = cbase + ni * 8;
            float2 bv = *(const float2*)(bias + cg);
#pragma unroll
            for (int h = 0; h < 2; h++) {
                int rg = rbase + mi * 16 + h * 8;
                float o0 = acc[mi][ni][2 * h]     + bv.x;
                float o1 = acc[mi][ni][2 * h + 1] + bv.y;
                size_t off = (size_t)rg * N + cg;
                if (MODE == MODE_BIAS_RES) {
                    float2 r = *(const float2*)(res + off);
                    o0 += r.x; o1 += r.y;
                    float2 w; w.x = o0; w.y = o1;
                    *(float2*)(C + off) = w;
                } else if (MODE == MODE_GELU_HI) {
                    float g0 = 0.5f * o0 * (1.0f + erff(o0 * 0.70710678118654752f));
                    float g1 = 0.5f * o1 * (1.0f + erff(o1 * 0.70710678118654752f));
                    HF2 H;
                    H.h[0] = __float2half_rn(g0);
                    H.h[1] = __float2half_rn(g1);
                    *(uint32_t*)(Oh + off) = H.u;
                } else {  // MODE_BIAS_HI
                    HF2 H;
                    H.h[0] = __float2half_rn(o0 * oscale);
                    H.h[1] = __float2half_rn(o1 * oscale);
                    *(uint32_t*)(Oh + off) = H.u;
                }
            }
        }
    }
}

template <int MODE>
__global__ __launch_bounds__(256, 2)
void mmagemm_kernel(const __half* __restrict__ Ah, const __half* __restrict__ Bh,
                    const float* __restrict__ bias, const float* __restrict__ res,
                    float* __restrict__ C, __half* __restrict__ Oh,
                    int N, int K, float oscale) {
    extern __shared__ char smg[];
    gemm_body<MODE>(Ah, Bh, bias, res, C, Oh, N, K, oscale,
                    blockIdx.x, blockIdx.y, smg);
}

// fused QKV (1-pass): blockIdx.x in [0,24): sel = x>>3, col block = x&7
__global__ __launch_bounds__(256, 2)
void qkv_kernel(const __half* __restrict__ Ah,
                const __half* __restrict__ Bq, const __half* __restrict__ Bk,
                const __half* __restrict__ Bv,
                const float* __restrict__ b0, const float* __restrict__ b1,
                const float* __restrict__ b2,
                __half* __restrict__ Qh, __half* __restrict__ Kh,
                __half* __restrict__ Vh) {
    extern __shared__ char smg[];
    const int sel = blockIdx.x >> 3;
    const int bxx = blockIdx.x & 7;
    const __half* Bh = (sel == 0) ? Bq : (sel == 1) ? Bk : Bv;
    const float* bias = (sel == 0) ? b0 : (sel == 1) ? b1 : b2;
    __half* Oh = (sel == 0) ? Qh : (sel == 1) ? Kh : Vh;
    const float sc = (sel == 0) ? 0.125f : 1.0f;
    gemm_body<MODE_BIAS_HI>(Ah, Bh, bias, nullptr, nullptr, Oh,
                            EMB, EMB, sc, bxx, blockIdx.y, smg);
}

// ---------------- plain fp16 tensor-core causal flash attention --------------
#define ATT_SMEM 49152

__global__ __launch_bounds__(256)
void attn_tc_kernel(const __half* __restrict__ Qh_, const __half* __restrict__ Kh_,
                    const __half* __restrict__ Vh_, __half* __restrict__ Oh) {
    extern __shared__ char smg[];
    const uint32_t sb = smem_u32(smg);
    const int qt   = (TSEQ / 128 - 1) - blockIdx.x;
    const int bh   = blockIdx.y;
    const int bb   = bh >> 4;
    const int head = bh & 15;
    const int tid  = threadIdx.x;
    const int wid  = tid >> 5;
    const int lane = tid & 31;
    const size_t hoff = (size_t)head * 64;
    const size_t seq0 = (size_t)bb * TSEQ;

    const int gi  = tid & 7;
    const int r32 = tid >> 3;

    {
#pragma unroll
        for (int i = 0; i < 4; i++) {
            int r = r32 + 32 * i;
            size_t g = (seq0 + qt * 128 + r) * EMB + hoff + gi * 8;
            uint32_t sw = sw128((uint32_t)(r * 128 + gi * 16));
            cp16(sb + sw, Qh_ + g);
        }
        cp_commit();
    }
    auto cpKV = [&](int kt, int st) {
        uint32_t base = sb + 16384 + st * 16384;
#pragma unroll
        for (int i = 0; i < 2; i++) {
            int r = r32 + 32 * i;
            size_t g = (seq0 + kt * 64 + r) * EMB + hoff + gi * 8;
            uint32_t sw = sw128((uint32_t)(r * 128 + gi * 16));
            cp16(base + sw, Kh_ + g);
            cp16(base + 8192 + sw, Vh_ + g);
        }
        cp_commit();
    };
    cpKV(0, 0);
    cp_wait<0>();
    __syncthreads();

    uint32_t qh[4][4];
#pragma unroll
    for (int ks = 0; ks < 4; ks++) {
        int row = wid * 16 + (lane & 15);
        uint32_t sw = sw128((uint32_t)(row * 128 + ks * 32 + (lane & 16)));
        ldmx4(qh[ks], sb + sw);
    }

    float oacc[8][4];
#pragma unroll
    for (int i = 0; i < 8; i++)
#pragma unroll
        for (int j = 0; j < 4; j++) oacc[i][j] = 0.0f;
    float m0 = -3.0e38f, m1 = -3.0e38f, l0 = 0.0f, l1 = 0.0f;

    const int gr0 = qt * 128 + wid * 16 + (lane >> 2);
    const int cq  = (lane & 3) * 2;
    const int ktlast = 2 * qt + 1;

    for (int kt = 0; kt <= ktlast; ++kt) {
        if (kt > 0) { cp_wait<0>(); __syncthreads(); }
        if (kt < ktlast) cpKV(kt + 1, (kt + 1) & 1);
        uint32_t base = sb + 16384 + (kt & 1) * 16384;

        if (kt * 64 > qt * 128 + wid * 16 + 15) continue;

        float sacc[8][4];
#pragma unroll
        for (int i = 0; i < 8; i++)
#pragma unroll
            for (int j = 0; j < 4; j++) sacc[i][j] = 0.0f;
#pragma unroll
        for (int ks = 0; ks < 4; ks++) {
            uint32_t kh[8][2];
#pragma unroll
            for (int kp = 0; kp < 4; kp++) {
                int row = kp * 16 + (lane & 15);
                uint32_t sw = sw128((uint32_t)(row * 128 + ks * 32 + (lane & 16)));
                uint32_t t[4];
                ldmx4(t, base + sw);
                kh[kp * 2][0] = t[0]; kh[kp * 2][1] = t[2];
                kh[kp * 2 + 1][0] = t[1]; kh[kp * 2 + 1][1] = t[3];
            }
#pragma unroll
            for (int nt = 0; nt < 8; nt++)
                mma_f16(sacc[nt], qh[ks], kh[nt]);
        }

        if (kt * 64 + 63 > qt * 128 + wid * 16) {
#pragma unroll
            for (int nt = 0; nt < 8; nt++) {
                int c0 = kt * 64 + nt * 8 + cq;
                if (c0 > gr0)     sacc[nt][0] = -1e30f;
                if (c0 + 1 > gr0) sacc[nt][1] = -1e30f;
                if (c0 > gr0 + 8)     sacc[nt][2] = -1e30f;
                if (c0 + 1 > gr0 + 8) sacc[nt][3] = -1e30f;
            }
        }

        float t0 = -3.0e38f, t1 = -3.0e38f;
#pragma unroll
        for (int nt = 0; nt < 8; nt++) {
            t0 = fmaxf(t0, fmaxf(sacc[nt][0], sacc[nt][1]));
            t1 = fmaxf(t1, fmaxf(sacc[nt][2], sacc[nt][3]));
        }
        t0 = fmaxf(t0, __shfl_xor_sync(0xffffffffu, t0, 1));
        t0 = fmaxf(t0, __shfl_xor_sync(0xffffffffu, t0, 2));
        t1 = fmaxf(t1, __shfl_xor_sync(0xffffffffu, t1, 1));
        t1 = fmaxf(t1, __shfl_xor_sync(0xffffffffu, t1, 2));
        float mn0 = fmaxf(m0, t0), mn1 = fmaxf(m1, t1);
        float al0 = __expf(m0 - mn0), al1 = __expf(m1 - mn1);
        m0 = mn0; m1 = mn1;

        uint32_t pH[8][2];
        float ps0 = 0.0f, ps1 = 0.0f;
#pragma unroll
        for (int nt = 0; nt < 8; nt++) {
            float p0 = __expf(sacc[nt][0] - mn0);
            float p1 = __expf(sacc[nt][1] - mn0);
            float p2 = __expf(sacc[nt][2] - mn1);
            float p3 = __expf(sacc[nt][3] - mn1);
            ps0 += p0 + p1; ps1 += p2 + p3;
            HF2 H;
            H.h[0] = __float2half_rn(p0);
            H.h[1] = __float2half_rn(p1);
            pH[nt][0] = H.u;
            H.h[0] = __float2half_rn(p2);
            H.h[1] = __float2half_rn(p3);
            pH[nt][1] = H.u;
        }
        ps0 += __shfl_xor_sync(0xffffffffu, ps0, 1);
        ps0 += __shfl_xor_sync(0xffffffffu, ps0, 2);
        ps1 += __shfl_xor_sync(0xffffffffu, ps1, 1);
        ps1 += __shfl_xor_sync(0xffffffffu, ps1, 2);
        l0 = l0 * al0 + ps0;
        l1 = l1 * al1 + ps1;

#pragma unroll
        for (int dt = 0; dt < 8; dt++) {
            oacc[dt][0] *= al0; oacc[dt][1] *= al0;
            oacc[dt][2] *= al1; oacc[dt][3] *= al1;
        }

#pragma unroll
        for (int ks = 0; ks < 4; ks++) {
            uint32_t aH[4] = { pH[2 * ks][0], pH[2 * ks][1], pH[2 * ks + 1][0], pH[2 * ks + 1][1] };
#pragma unroll
            for (int dp = 0; dp < 4; dp++) {
                uint32_t sw = sw128((uint32_t)((ks * 16 + (lane & 15)) * 128 + dp * 32 + (lane & 16)));
                uint32_t th[4];
                ldmx4t(th, base + 8192 + sw);
                uint32_t b0h[2] = { th[0], th[1] }, b1h[2] = { th[2], th[3] };
                mma_f16(oacc[2 * dp],     aH, b0h);
                mma_f16(oacc[2 * dp + 1], aH, b1h);
            }
        }
    }

    float inv0 = 1.0f / l0, inv1 = 1.0f / l1;
#pragma unroll
    for (int dt = 0; dt < 8; dt++) {
        int cg = dt * 8 + cq;
        size_t off0 = (seq0 + gr0) * EMB + hoff + cg;
        size_t off1 = (seq0 + gr0 + 8) * EMB + hoff + cg;
        HF2 H;
        H.h[0] = __float2half_rn(oacc[dt][0] * inv0);
        H.h[1] = __float2half_rn(oacc[dt][1] * inv0);
        *(uint32_t*)(Oh + off0) = H.u;
        H.h[0] = __float2half_rn(oacc[dt][2] * inv1);
        H.h[1] = __float2half_rn(oacc[dt][3] * inv1);
        *(uint32_t*)(Oh + off1) = H.u;
    }
}

// ---------------- orchestration ----------------------------------------------
extern "C" void kernel_launch(void* const* d_in, const int* in_sizes, int n_in,
                              void* d_out, int out_size) {
    (void)in_sizes; (void)n_in; (void)out_size;
    const float* x    = (const float*)d_in[0];
    const float* Wq_w = (const float*)d_in[1];
    const float* Wq_b = (const float*)d_in[2];
    const float* Wk_w = (const float*)d_in[3];
    const float* Wk_b = (const float*)d_in[4];
    const float* Wv_w = (const float*)d_in[5];
    const float* Wv_b = (const float*)d_in[6];
    const float* Wo_w = (const float*)d_in[7];
    const float* Wo_b = (const float*)d_in[8];
    const float* l1_w = (const float*)d_in[9];
    const float* l1_b = (const float*)d_in[10];
    const float* l2_w = (const float*)d_in[11];
    const float* l2_b = (const float*)d_in[12];
    const float* n1s  = (const float*)d_in[13];
    const float* n1b  = (const float*)d_in[14];
    const float* n2s  = (const float*)d_in[15];
    const float* n2b  = (const float*)d_in[16];
    float* out = (float*)d_out;

    float *x1, *rs, *rq, *var;
    cudaGetSymbolAddress((void**)&x1,  g_x1);
    cudaGetSymbolAddress((void**)&rs,  g_rowsum);
    cudaGetSymbolAddress((void**)&rq,  g_rowsq);
    cudaGetSymbolAddress((void**)&var, g_var);

    __half *h, *ctx, *ff, *qh, *kh, *vh;
    __half *wq, *wk, *wv, *wo, *l1, *l2;
    cudaGetSymbolAddress((void**)&h,  g_h);
    cudaGetSymbolAddress((void**)&qh, g_qh);
    cudaGetSymbolAddress((void**)&kh, g_kh);
    cudaGetSymbolAddress((void**)&vh, g_vh);
    cudaGetSymbolAddress((void**)&ctx, g_ctx);
    cudaGetSymbolAddress((void**)&ff, g_ff);
    cudaGetSymbolAddress((void**)&wq, g_wq);
    cudaGetSymbolAddress((void**)&wk, g_wk);
    cudaGetSymbolAddress((void**)&wv, g_wv);
    cudaGetSymbolAddress((void**)&wo, g_wo);
    cudaGetSymbolAddress((void**)&l1, g_l1);
    cudaGetSymbolAddress((void**)&l2, g_l2);

    cudaFuncSetAttribute((const void*)attn_tc_kernel,
                         cudaFuncAttributeMaxDynamicSharedMemorySize, ATT_SMEM);
    cudaFuncSetAttribute((const void*)qkv_kernel,
                         cudaFuncAttributeMaxDynamicSharedMemorySize, MM_SMEM);
    cudaFuncSetAttribute((const void*)mmagemm_kernel<MODE_BIAS_RES>,
                         cudaFuncAttributeMaxDynamicSharedMemorySize, MM_SMEM);
    cudaFuncSetAttribute((const void*)mmagemm_kernel<MODE_GELU_HI>,
                         cudaFuncAttributeMaxDynamicSharedMemorySize, MM_SMEM);

    const int LN_BLOCKS = (N_TOK * EMB / 4) / 256;
    dim3 blk(256);
    dim3 gP(EMB / 128, N_TOK / 128);
    dim3 gF(DFF / 128, N_TOK / 128);
    dim3 gQKV(3 * EMB / 128, N_TOK / 128);

    // fused weight split (hi only)
    split_all_kernel<<<SPLIT_TOTAL4 / 256, 256>>>(Wq_w, Wk_w, Wv_w, Wo_w, l1_w, l2_w,
                                                  wq, wk, wv, wo, l1, l2);

    // LN1 -> h (hi only)
    rowstats_kernel<<<N_TOK, 256>>>(x, rs, rq);
    finalize_var_kernel<<<1, 256>>>(rs, rq, var);
    ln_apply_hi_kernel<<<LN_BLOCKS, 256>>>(x, rs, var, n1s, n1b, h);

    // fused QKV projections (1-pass; Q pre-scaled 1/8)
    qkv_kernel<<<gQKV, blk, MM_SMEM>>>(h, wq, wk, wv, Wq_b, Wk_b, Wv_b, qh, kh, vh);

    // attention -> ctx
    attn_tc_kernel<<<dim3(TSEQ / 128, 64), 256, ATT_SMEM>>>(qh, kh, vh, ctx);

    // output projection + residual
    mmagemm_kernel<MODE_BIAS_RES><<<gP, blk, MM_SMEM>>>(
        ctx, wo, Wo_b, x, x1, nullptr, EMB, EMB, 1.0f);

    // LN2 -> h (hi only)
    rowstats_kernel<<<N_TOK, 256>>>(x1, rs, rq);
    finalize_var_kernel<<<1, 256>>>(rs, rq, var);
    ln_apply_hi_kernel<<<LN_BLOCKS, 256>>>(x1, rs, var, n2s, n2b, h);

    // FFN
    mmagemm_kernel<MODE_GELU_HI><<<gF, blk, MM_SMEM>>>(
        h, l1, l1_b, nullptr, nullptr, ff, DFF, EMB, 1.0f);
    mmagemm_kernel<MODE_BIAS_RES><<<gP, blk, MM_SMEM>>>(
        ff, l2, l2_b, x1, out, nullptr, EMB, DFF, 1.0f);
}